// round 1
// baseline (speedup 1.0000x reference)
#include <cuda_runtime.h>
#include <cuda_bf16.h>
#include <math.h>

// Problem constants
#define BATCH 2
#define SEQ 2048
#define DMODEL 4096
#define NHEAD 32
#define NKVHEAD 8
#define DHEAD 128
#define MROWS (BATCH * SEQ)            // 4096
#define QCOLS (NHEAD * DHEAD)          // 4096
#define KVCOLS (NKVHEAD * DHEAD)       // 1024

// Scratch buffers (allocation-free rule: __device__ globals)
__device__ float QBUF[(size_t)MROWS * QCOLS];
__device__ float KBUF[(size_t)MROWS * KVCOLS];
__device__ float VBUF[(size_t)MROWS * KVCOLS];
__device__ float ZBUF[(size_t)MROWS * QCOLS];

// ----------------------------------------------------------------------------
// Generic fp32 GEMM: C[M,N] = A[M,K] @ W[K,N], all row-major.
// 64x64 tile, BK=16, 256 threads, each thread 4x4.
// ----------------------------------------------------------------------------
__global__ __launch_bounds__(256) void gemm64(const float* __restrict__ A,
                                              const float* __restrict__ W,
                                              float* __restrict__ C,
                                              int M, int N, int K) {
    __shared__ float As[16][64];   // transposed A tile: As[k][m]
    __shared__ float Ws[16][64];   // Ws[k][n]

    const int tid = threadIdx.x;
    const int ty = tid >> 4;       // 0..15
    const int tx = tid & 15;       // 0..15
    const int m0 = blockIdx.y * 64;
    const int n0 = blockIdx.x * 64;

    const int arow = tid >> 2;     // 0..63
    const int akg  = tid & 3;      // 0..3 (k-group of 4)

    float acc[4][4];
    #pragma unroll
    for (int i = 0; i < 4; i++)
        #pragma unroll
        for (int j = 0; j < 4; j++) acc[i][j] = 0.0f;

    for (int k0 = 0; k0 < K; k0 += 16) {
        // Load A tile (64 rows x 16 k) -> transposed store
        float4 av = *(const float4*)(A + (size_t)(m0 + arow) * K + k0 + akg * 4);
        As[akg * 4 + 0][arow] = av.x;
        As[akg * 4 + 1][arow] = av.y;
        As[akg * 4 + 2][arow] = av.z;
        As[akg * 4 + 3][arow] = av.w;
        // Load W tile (16 k x 64 n)
        *(float4*)&Ws[ty][tx * 4] =
            *(const float4*)(W + (size_t)(k0 + ty) * N + n0 + tx * 4);
        __syncthreads();

        #pragma unroll
        for (int kk = 0; kk < 16; kk++) {
            float4 a = *(const float4*)&As[kk][ty * 4];
            float4 w = *(const float4*)&Ws[kk][tx * 4];
            acc[0][0] += a.x * w.x; acc[0][1] += a.x * w.y; acc[0][2] += a.x * w.z; acc[0][3] += a.x * w.w;
            acc[1][0] += a.y * w.x; acc[1][1] += a.y * w.y; acc[1][2] += a.y * w.z; acc[1][3] += a.y * w.w;
            acc[2][0] += a.z * w.x; acc[2][1] += a.z * w.y; acc[2][2] += a.z * w.z; acc[2][3] += a.z * w.w;
            acc[3][0] += a.w * w.x; acc[3][1] += a.w * w.y; acc[3][2] += a.w * w.z; acc[3][3] += a.w * w.w;
        }
        __syncthreads();
    }

    #pragma unroll
    for (int i = 0; i < 4; i++) {
        float4 o = make_float4(acc[i][0], acc[i][1], acc[i][2], acc[i][3]);
        *(float4*)(C + (size_t)(m0 + ty * 4 + i) * N + n0 + tx * 4) = o;
    }
}

// ----------------------------------------------------------------------------
// RoPE (interleaved pairs), applied in-place to Q or K buffer.
// buf layout: [B*T, nheads*128]; cos/sin: [T, 64]
// ----------------------------------------------------------------------------
__global__ __launch_bounds__(256) void rope_kernel(float* __restrict__ buf,
                                                   const float* __restrict__ cosb,
                                                   const float* __restrict__ sinb,
                                                   int nheads) {
    int idx = blockIdx.x * blockDim.x + threadIdx.x;
    int total = MROWS * nheads * (DHEAD / 2);
    if (idx >= total) return;
    int d2 = idx & 63;
    int h = (idx >> 6) % nheads;
    int r = idx / (64 * nheads);
    int t = r & (SEQ - 1);
    size_t base = (size_t)r * nheads * DHEAD + h * DHEAD + d2 * 2;
    float xr = buf[base];
    float xi = buf[base + 1];
    float c = cosb[t * 64 + d2];
    float s = sinb[t * 64 + d2];
    buf[base]     = xr * c - xi * s;
    buf[base + 1] = xr * s + xi * c;
}

// ----------------------------------------------------------------------------
// Fused causal flash attention, fp32, GQA (4 q-heads per kv-head).
// grid: (T/64, B*H). 256 threads. BM=BN=64, D=128.
// Shared: Qs/Ks/Vs as float4[64][32] XOR-swizzled; Ps float[64][65].
// ----------------------------------------------------------------------------
#define FLASH_SMEM (3 * 64 * 32 * 16 + 64 * 65 * 4)

__global__ __launch_bounds__(256) void flash_kernel(const float* __restrict__ Q,
                                                    const float* __restrict__ Kb,
                                                    const float* __restrict__ Vb,
                                                    float* __restrict__ Z) {
    extern __shared__ float4 sm4[];
    float4* Qs = sm4;              // [64][32] swizzled
    float4* Ks = Qs + 64 * 32;
    float4* Vs = Ks + 64 * 32;
    float*  Ps = (float*)(Vs + 64 * 32);   // [64][65]

    const int tid = threadIdx.x;
    const int ty = tid >> 4;   // 0..15
    const int tx = tid & 15;   // 0..15
    const int q0 = blockIdx.x * 64;
    const int bh = blockIdx.y;
    const int b = bh >> 5;
    const int h = bh & 31;
    const int kvh = h >> 2;

    // Load Q tile with XOR swizzle on the float4 column index
    for (int idx = tid; idx < 64 * 32; idx += 256) {
        int row = idx >> 5, c = idx & 31;
        float4 v = *(const float4*)(Q + (size_t)(b * SEQ + q0 + row) * QCOLS + h * DHEAD + c * 4);
        Qs[row * 32 + (c ^ (row & 31))] = v;
    }

    float m_[4], l_[4], acc[4][8];
    #pragma unroll
    for (int i = 0; i < 4; i++) {
        m_[i] = -1e30f;
        l_[i] = 0.0f;
        #pragma unroll
        for (int c = 0; c < 8; c++) acc[i][c] = 0.0f;
    }

    const float scale = 0.08838834764831845f;  // 1/sqrt(128)
    const int nkb = (q0 >> 6) + 1;

    for (int kb = 0; kb < nkb; kb++) {
        const int j0 = kb * 64;
        __syncthreads();  // protect Ks/Vs/Ps (and Qs on first iter)

        for (int idx = tid; idx < 64 * 32; idx += 256) {
            int row = idx >> 5, c = idx & 31;
            size_t g = (size_t)(b * SEQ + j0 + row) * KVCOLS + kvh * DHEAD + c * 4;
            int sw = row * 32 + (c ^ (row & 31));
            Ks[sw] = *(const float4*)(Kb + g);
            Vs[sw] = *(const float4*)(Vb + g);
        }
        __syncthreads();

        // S = Q @ K^T (4x4 per thread)
        float s[4][4];
        #pragma unroll
        for (int i = 0; i < 4; i++)
            #pragma unroll
            for (int j = 0; j < 4; j++) s[i][j] = 0.0f;

        #pragma unroll 4
        for (int d4 = 0; d4 < 32; d4++) {
            float4 qv[4], kv[4];
            #pragma unroll
            for (int i = 0; i < 4; i++) {
                int row = ty * 4 + i;
                qv[i] = Qs[row * 32 + (d4 ^ (row & 31))];
            }
            #pragma unroll
            for (int j = 0; j < 4; j++) {
                int row = tx * 4 + j;
                kv[j] = Ks[row * 32 + (d4 ^ (row & 31))];
            }
            #pragma unroll
            for (int i = 0; i < 4; i++)
                #pragma unroll
                for (int j = 0; j < 4; j++)
                    s[i][j] += qv[i].x * kv[j].x + qv[i].y * kv[j].y +
                               qv[i].z * kv[j].z + qv[i].w * kv[j].w;
        }

        // mask + scale
        #pragma unroll
        for (int i = 0; i < 4; i++) {
            int qg = q0 + ty * 4 + i;
            #pragma unroll
            for (int j = 0; j < 4; j++) {
                int kg = j0 + tx * 4 + j;
                s[i][j] = (kg <= qg) ? s[i][j] * scale : -1e30f;
            }
        }

        // online softmax per row (rows owned by constant ty across 16 tx lanes)
        #pragma unroll
        for (int i = 0; i < 4; i++) {
            float rm = fmaxf(fmaxf(s[i][0], s[i][1]), fmaxf(s[i][2], s[i][3]));
            #pragma unroll
            for (int off = 1; off < 16; off <<= 1)
                rm = fmaxf(rm, __shfl_xor_sync(0xffffffffu, rm, off));
            float mn = fmaxf(m_[i], rm);
            float f = __expf(m_[i] - mn);
            float rs = 0.0f;
            #pragma unroll
            for (int j = 0; j < 4; j++) {
                float p = __expf(s[i][j] - mn);
                s[i][j] = p;
                rs += p;
            }
            #pragma unroll
            for (int off = 1; off < 16; off <<= 1)
                rs += __shfl_xor_sync(0xffffffffu, rs, off);
            l_[i] = l_[i] * f + rs;
            m_[i] = mn;
            #pragma unroll
            for (int c = 0; c < 8; c++) acc[i][c] *= f;
            #pragma unroll
            for (int j = 0; j < 4; j++)
                Ps[(ty * 4 + i) * 65 + tx * 4 + j] = s[i][j];
        }
        __syncthreads();

        // O += P @ V  (thread owns rows ty*4..+3, cols tx*8..+7)
        #pragma unroll 4
        for (int j = 0; j < 64; j++) {
            float p[4];
            #pragma unroll
            for (int i = 0; i < 4; i++) p[i] = Ps[(ty * 4 + i) * 65 + j];
            float4 v0 = Vs[j * 32 + ((tx * 2) ^ (j & 31))];
            float4 v1 = Vs[j * 32 + ((tx * 2 + 1) ^ (j & 31))];
            #pragma unroll
            for (int i = 0; i < 4; i++) {
                acc[i][0] += p[i] * v0.x; acc[i][1] += p[i] * v0.y;
                acc[i][2] += p[i] * v0.z; acc[i][3] += p[i] * v0.w;
                acc[i][4] += p[i] * v1.x; acc[i][5] += p[i] * v1.y;
                acc[i][6] += p[i] * v1.z; acc[i][7] += p[i] * v1.w;
            }
        }
    }

    // epilogue: normalize and write Z[b, q, h, :]
    #pragma unroll
    for (int i = 0; i < 4; i++) {
        int q = q0 + ty * 4 + i;
        float inv = 1.0f / l_[i];
        float4 o0 = make_float4(acc[i][0] * inv, acc[i][1] * inv, acc[i][2] * inv, acc[i][3] * inv);
        float4 o1 = make_float4(acc[i][4] * inv, acc[i][5] * inv, acc[i][6] * inv, acc[i][7] * inv);
        size_t base = (size_t)(b * SEQ + q) * QCOLS + h * DHEAD + tx * 8;
        *(float4*)(Z + base)     = o0;
        *(float4*)(Z + base + 4) = o1;
    }
}

// ----------------------------------------------------------------------------
// Host launcher
// ----------------------------------------------------------------------------
extern "C" void kernel_launch(void* const* d_in, const int* in_sizes, int n_in,
                              void* d_out, int out_size) {
    const float* x    = (const float*)d_in[0];
    const float* fcos = (const float*)d_in[1];
    const float* fsin = (const float*)d_in[2];
    const float* wq   = (const float*)d_in[3];
    const float* wk   = (const float*)d_in[4];
    const float* wv   = (const float*)d_in[5];
    const float* wo   = (const float*)d_in[6];
    float* out = (float*)d_out;

    float *q, *k, *v, *z;
    cudaGetSymbolAddress((void**)&q, QBUF);
    cudaGetSymbolAddress((void**)&k, KBUF);
    cudaGetSymbolAddress((void**)&v, VBUF);
    cudaGetSymbolAddress((void**)&z, ZBUF);

    // QKV projections
    gemm64<<<dim3(QCOLS / 64, MROWS / 64), 256>>>(x, wq, q, MROWS, QCOLS, DMODEL);
    gemm64<<<dim3(KVCOLS / 64, MROWS / 64), 256>>>(x, wk, k, MROWS, KVCOLS, DMODEL);
    gemm64<<<dim3(KVCOLS / 64, MROWS / 64), 256>>>(x, wv, v, MROWS, KVCOLS, DMODEL);

    // RoPE on Q and K
    {
        int totq = MROWS * NHEAD * (DHEAD / 2);
        rope_kernel<<<(totq + 255) / 256, 256>>>(q, fcos, fsin, NHEAD);
        int totk = MROWS * NKVHEAD * (DHEAD / 2);
        rope_kernel<<<(totk + 255) / 256, 256>>>(k, fcos, fsin, NKVHEAD);
    }

    // Flash attention
    cudaFuncSetAttribute(flash_kernel, cudaFuncAttributeMaxDynamicSharedMemorySize, FLASH_SMEM);
    flash_kernel<<<dim3(SEQ / 64, BATCH * NHEAD), 256, FLASH_SMEM>>>(q, k, v, z);

    // Output projection
    gemm64<<<dim3(DMODEL / 64, MROWS / 64), 256>>>(z, wo, out, MROWS, DMODEL, DMODEL);
}

// round 3
// speedup vs baseline: 1.6730x; 1.6730x over previous
#include <cuda_runtime.h>
#include <cuda_bf16.h>
#include <cstdint>
#include <math.h>

// Problem constants
#define BATCH 2
#define SEQ 2048
#define DMODEL 4096
#define NHEAD 32
#define NKVHEAD 8
#define DHEAD 128
#define MROWS (BATCH * SEQ)            // 4096
#define QCOLS (NHEAD * DHEAD)          // 4096
#define KVCOLS (NKVHEAD * DHEAD)       // 1024

// ---------------------------------------------------------------------------
// Scratch buffers (__device__ globals; allocation-free rule)
// ---------------------------------------------------------------------------
__device__ __nv_bfloat16 XHI[(size_t)MROWS * DMODEL];
__device__ __nv_bfloat16 XLO[(size_t)MROWS * DMODEL];
__device__ __nv_bfloat16 WQT_HI[(size_t)QCOLS * DMODEL];
__device__ __nv_bfloat16 WQT_LO[(size_t)QCOLS * DMODEL];
__device__ __nv_bfloat16 WKT_HI[(size_t)KVCOLS * DMODEL];
__device__ __nv_bfloat16 WKT_LO[(size_t)KVCOLS * DMODEL];
__device__ __nv_bfloat16 WVT_HI[(size_t)KVCOLS * DMODEL];
__device__ __nv_bfloat16 WVT_LO[(size_t)KVCOLS * DMODEL];
__device__ __nv_bfloat16 WOT_HI[(size_t)DMODEL * DMODEL];
__device__ __nv_bfloat16 WOT_LO[(size_t)DMODEL * DMODEL];
__device__ __nv_bfloat16 ZHI[(size_t)MROWS * DMODEL];
__device__ __nv_bfloat16 ZLO[(size_t)MROWS * DMODEL];
__device__ float QBUF[(size_t)MROWS * QCOLS];
__device__ float KBUF[(size_t)MROWS * KVCOLS];
__device__ float VBUF[(size_t)MROWS * KVCOLS];
__device__ float ZBUF[(size_t)MROWS * QCOLS];

// ---------------------------------------------------------------------------
// Helpers
// ---------------------------------------------------------------------------
__device__ __forceinline__ uint32_t smem_u32(const void* p) {
    uint32_t a;
    asm("{ .reg .u64 t; cvta.to.shared.u64 t, %1; cvt.u32.u64 %0, t; }" : "=r"(a) : "l"(p));
    return a;
}

__device__ __forceinline__ void cp16(uint32_t dst, const void* src) {
    asm volatile("cp.async.cg.shared.global [%0], [%1], 16;" :: "r"(dst), "l"(src));
}
#define CP_COMMIT() asm volatile("cp.async.commit_group;" ::: "memory")
template <int N>
__device__ __forceinline__ void cp_wait() {
    asm volatile("cp.async.wait_group %0;" :: "n"(N) : "memory");
}

#define LDSM4(r, addr)                                                        \
    asm volatile("ldmatrix.sync.aligned.m8n8.x4.shared.b16 {%0,%1,%2,%3}, [%4];" \
        : "=r"((r)[0]), "=r"((r)[1]), "=r"((r)[2]), "=r"((r)[3]) : "r"(addr))

#define MMA16816(c, a, b0, b1)                                                \
    asm volatile("mma.sync.aligned.m16n8k16.row.col.f32.bf16.bf16.f32 "       \
        "{%0,%1,%2,%3}, {%4,%5,%6,%7}, {%8,%9}, {%0,%1,%2,%3};"               \
        : "+f"((c)[0]), "+f"((c)[1]), "+f"((c)[2]), "+f"((c)[3])              \
        : "r"((a)[0]), "r"((a)[1]), "r"((a)[2]), "r"((a)[3]),                 \
          "r"(b0), "r"(b1))

// ---------------------------------------------------------------------------
// fp32 -> bf16 hi/lo split (elementwise)
// ---------------------------------------------------------------------------
__global__ __launch_bounds__(256) void split_kernel(const float* __restrict__ src,
                                                    __nv_bfloat16* __restrict__ hi,
                                                    __nv_bfloat16* __restrict__ lo,
                                                    int n) {
    int i = blockIdx.x * blockDim.x + threadIdx.x;
    if (i >= n) return;
    float a = src[i];
    __nv_bfloat16 h = __float2bfloat16(a);
    hi[i] = h;
    lo[i] = __float2bfloat16(a - __bfloat162float(h));
}

// ---------------------------------------------------------------------------
// Transpose + split: W[K,N] fp32 -> T_hi/T_lo [N,K] bf16
// ---------------------------------------------------------------------------
__global__ __launch_bounds__(256) void transpose_split(const float* __restrict__ W,
                                                       __nv_bfloat16* __restrict__ Thi,
                                                       __nv_bfloat16* __restrict__ Tlo,
                                                       int K, int N) {
    __shared__ float t[32][33];
    int n0 = blockIdx.x * 32;
    int k0 = blockIdx.y * 32;
    int tx = threadIdx.x, ty = threadIdx.y;   // (32, 8)
    #pragma unroll
    for (int r = ty; r < 32; r += 8)
        t[r][tx] = W[(size_t)(k0 + r) * N + n0 + tx];
    __syncthreads();
    #pragma unroll
    for (int r = ty; r < 32; r += 8) {
        float a = t[tx][r];
        __nv_bfloat16 h = __float2bfloat16(a);
        size_t o = (size_t)(n0 + r) * K + k0 + tx;
        Thi[o] = h;
        Tlo[o] = __float2bfloat16(a - __bfloat162float(h));
    }
}

// ---------------------------------------------------------------------------
// HMMA bf16x3 GEMM: C[M,N] fp32 = sum over 3 passes A_p[M,K] * B_p[N,K]^T
//   passes: (Ahi,Bhi), (Ahi,Blo), (Alo,Bhi); fp32 accum in registers.
// CTA tile 128x256, BK=32, 8 warps (2x4), warp tile 64x64, 3-stage cp.async.
// grid: (N/256, M/128)
// ---------------------------------------------------------------------------
#define BM 128
#define BN 256
#define BK 32
#define A_SM_BYTES (BM * BK * 2)              // 8192
#define B_SM_BYTES (BN * BK * 2)              // 16384
#define STAGE_B (A_SM_BYTES + B_SM_BYTES)     // 24576
#define NST 3
#define GEMM_SMEM (NST * STAGE_B)             // 73728

// swizzled byte offset within an A/B buffer for (row, kseg[0..3])
__device__ __forceinline__ uint32_t swz_off(int row, int ks) {
    return (uint32_t)(row * 64 + (((ks ^ (row >> 1)) & 3) << 4));
}

__global__ __launch_bounds__(256, 1)
void hmma_gemm(const __nv_bfloat16* __restrict__ Ahi, const __nv_bfloat16* __restrict__ Alo,
               const __nv_bfloat16* __restrict__ Bhi, const __nv_bfloat16* __restrict__ Blo,
               float* __restrict__ C, int N, int K) {
    extern __shared__ char smem[];
    const uint32_t sb = smem_u32(smem);
    const int tid = threadIdx.x;
    const int wid = tid >> 5;
    const int lane = tid & 31;
    const int wm = wid >> 2;        // 0..1
    const int wn = wid & 3;         // 0..3
    const int m0 = blockIdx.y * BM;
    const int n0 = blockIdx.x * BN;

    const int kchunks = K / BK;     // 128
    const int TOT = 3 * kchunks;    // 384

    float acc[4][8][4];
    #pragma unroll
    for (int i = 0; i < 4; i++)
        #pragma unroll
        for (int j = 0; j < 8; j++)
            #pragma unroll
            for (int r = 0; r < 4; r++) acc[i][j][r] = 0.0f;

    auto load_chunk = [&](int c, int s) {
        int p = c / kchunks;
        int kc = c - p * kchunks;
        const __nv_bfloat16* pa = (p == 2) ? Alo : Ahi;
        const __nv_bfloat16* pb = (p == 1) ? Blo : Bhi;
        const __nv_bfloat16* asrc = pa + (size_t)m0 * K + kc * BK;
        const __nv_bfloat16* bsrc = pb + (size_t)n0 * K + kc * BK;
        uint32_t base = sb + s * STAGE_B;
        #pragma unroll
        for (int t = 0; t < 6; t++) {
            int idx = tid + t * 256;          // 0..1535  (512 A segs + 1024 B segs)
            bool isB = idx >= 512;
            int j = isB ? idx - 512 : idx;
            int row = j >> 2, ks = j & 3;
            uint32_t dst = base + (isB ? A_SM_BYTES : 0) + swz_off(row, ks);
            const __nv_bfloat16* src = (isB ? bsrc : asrc) + (size_t)row * K + ks * 8;
            cp16(dst, src);
        }
    };

    load_chunk(0, 0); CP_COMMIT();
    load_chunk(1, 1); CP_COMMIT();

    const int r15 = lane & 15;
    const int hi = lane >> 4;

    for (int c = 0; c < TOT; c++) {
        const int s = c % NST;
        cp_wait<1>();
        __syncthreads();

        const uint32_t abase = sb + s * STAGE_B;
        const uint32_t bbase = abase + A_SM_BYTES;

        #pragma unroll
        for (int ks2 = 0; ks2 < 2; ks2++) {
            const int kseg = ks2 * 2 + hi;
            uint32_t aF[4][4], bF[4][4];
            #pragma unroll
            for (int i = 0; i < 4; i++) {
                int row = wm * 64 + i * 16 + r15;
                LDSM4(aF[i], abase + swz_off(row, kseg));
            }
            #pragma unroll
            for (int j = 0; j < 4; j++) {
                int row = wn * 64 + j * 16 + r15;
                LDSM4(bF[j], bbase + swz_off(row, kseg));
            }
            #pragma unroll
            for (int i = 0; i < 4; i++) {
                #pragma unroll
                for (int j = 0; j < 4; j++) {
                    MMA16816(acc[i][2 * j],     aF[i], bF[j][0], bF[j][2]);
                    MMA16816(acc[i][2 * j + 1], aF[i], bF[j][1], bF[j][3]);
                }
            }
        }
        __syncthreads();
        if (c + 2 < TOT) load_chunk(c + 2, (c + 2) % NST);
        CP_COMMIT();
    }

    // Epilogue: direct stores (thread holds rows l/4 and l/4+8, col pairs)
    const int quad = lane >> 2;       // 0..7
    const int tq = lane & 3;          // 0..3
    #pragma unroll
    for (int i = 0; i < 4; i++) {
        int row0 = m0 + wm * 64 + i * 16 + quad;
        #pragma unroll
        for (int j = 0; j < 8; j++) {
            int col = n0 + wn * 64 + j * 8 + tq * 2;
            *(float2*)(C + (size_t)row0 * N + col) =
                make_float2(acc[i][j][0], acc[i][j][1]);
            *(float2*)(C + (size_t)(row0 + 8) * N + col) =
                make_float2(acc[i][j][2], acc[i][j][3]);
        }
    }
}

// ----------------------------------------------------------------------------
// RoPE (interleaved pairs), in-place on Q or K buffer.
// ----------------------------------------------------------------------------
__global__ __launch_bounds__(256) void rope_kernel(float* __restrict__ buf,
                                                   const float* __restrict__ cosb,
                                                   const float* __restrict__ sinb,
                                                   int nheads) {
    int idx = blockIdx.x * blockDim.x + threadIdx.x;
    int total = MROWS * nheads * (DHEAD / 2);
    if (idx >= total) return;
    int d2 = idx & 63;
    int h = (idx >> 6) % nheads;
    int r = idx / (64 * nheads);
    int t = r & (SEQ - 1);
    size_t base = (size_t)r * nheads * DHEAD + h * DHEAD + d2 * 2;
    float xr = buf[base];
    float xi = buf[base + 1];
    float c = cosb[t * 64 + d2];
    float s = sinb[t * 64 + d2];
    buf[base]     = xr * c - xi * s;
    buf[base + 1] = xr * s + xi * c;
}

// ----------------------------------------------------------------------------
// Fused causal flash attention, fp32, GQA (4 q-heads per kv-head).
// ----------------------------------------------------------------------------
#define FLASH_SMEM (3 * 64 * 32 * 16 + 64 * 65 * 4)

__global__ __launch_bounds__(256) void flash_kernel(const float* __restrict__ Q,
                                                    const float* __restrict__ Kb,
                                                    const float* __restrict__ Vb,
                                                    float* __restrict__ Z) {
    extern __shared__ float4 sm4[];
    float4* Qs = sm4;
    float4* Ks = Qs + 64 * 32;
    float4* Vs = Ks + 64 * 32;
    float*  Ps = (float*)(Vs + 64 * 32);

    const int tid = threadIdx.x;
    const int ty = tid >> 4;
    const int tx = tid & 15;
    const int q0 = blockIdx.x * 64;
    const int bh = blockIdx.y;
    const int b = bh >> 5;
    const int h = bh & 31;
    const int kvh = h >> 2;

    for (int idx = tid; idx < 64 * 32; idx += 256) {
        int row = idx >> 5, c = idx & 31;
        float4 v = *(const float4*)(Q + (size_t)(b * SEQ + q0 + row) * QCOLS + h * DHEAD + c * 4);
        Qs[row * 32 + (c ^ (row & 31))] = v;
    }

    float m_[4], l_[4], acc[4][8];
    #pragma unroll
    for (int i = 0; i < 4; i++) {
        m_[i] = -1e30f;
        l_[i] = 0.0f;
        #pragma unroll
        for (int c = 0; c < 8; c++) acc[i][c] = 0.0f;
    }

    const float scale = 0.08838834764831845f;
    const int nkb = (q0 >> 6) + 1;

    for (int kb = 0; kb < nkb; kb++) {
        const int j0 = kb * 64;
        __syncthreads();

        for (int idx = tid; idx < 64 * 32; idx += 256) {
            int row = idx >> 5, c = idx & 31;
            size_t g = (size_t)(b * SEQ + j0 + row) * KVCOLS + kvh * DHEAD + c * 4;
            int swi = row * 32 + (c ^ (row & 31));
            Ks[swi] = *(const float4*)(Kb + g);
            Vs[swi] = *(const float4*)(Vb + g);
        }
        __syncthreads();

        float s[4][4];
        #pragma unroll
        for (int i = 0; i < 4; i++)
            #pragma unroll
            for (int j = 0; j < 4; j++) s[i][j] = 0.0f;

        #pragma unroll 4
        for (int d4 = 0; d4 < 32; d4++) {
            float4 qv[4], kv[4];
            #pragma unroll
            for (int i = 0; i < 4; i++) {
                int row = ty * 4 + i;
                qv[i] = Qs[row * 32 + (d4 ^ (row & 31))];
            }
            #pragma unroll
            for (int j = 0; j < 4; j++) {
                int row = tx * 4 + j;
                kv[j] = Ks[row * 32 + (d4 ^ (row & 31))];
            }
            #pragma unroll
            for (int i = 0; i < 4; i++)
                #pragma unroll
                for (int j = 0; j < 4; j++)
                    s[i][j] += qv[i].x * kv[j].x + qv[i].y * kv[j].y +
                               qv[i].z * kv[j].z + qv[i].w * kv[j].w;
        }

        #pragma unroll
        for (int i = 0; i < 4; i++) {
            int qg = q0 + ty * 4 + i;
            #pragma unroll
            for (int j = 0; j < 4; j++) {
                int kg = j0 + tx * 4 + j;
                s[i][j] = (kg <= qg) ? s[i][j] * scale : -1e30f;
            }
        }

        #pragma unroll
        for (int i = 0; i < 4; i++) {
            float rm = fmaxf(fmaxf(s[i][0], s[i][1]), fmaxf(s[i][2], s[i][3]));
            #pragma unroll
            for (int off = 1; off < 16; off <<= 1)
                rm = fmaxf(rm, __shfl_xor_sync(0xffffffffu, rm, off));
            float mn = fmaxf(m_[i], rm);
            float f = __expf(m_[i] - mn);
            float rs = 0.0f;
            #pragma unroll
            for (int j = 0; j < 4; j++) {
                float p = __expf(s[i][j] - mn);
                s[i][j] = p;
                rs += p;
            }
            #pragma unroll
            for (int off = 1; off < 16; off <<= 1)
                rs += __shfl_xor_sync(0xffffffffu, rs, off);
            l_[i] = l_[i] * f + rs;
            m_[i] = mn;
            #pragma unroll
            for (int c = 0; c < 8; c++) acc[i][c] *= f;
            #pragma unroll
            for (int j = 0; j < 4; j++)
                Ps[(ty * 4 + i) * 65 + tx * 4 + j] = s[i][j];
        }
        __syncthreads();

        #pragma unroll 4
        for (int j = 0; j < 64; j++) {
            float p[4];
            #pragma unroll
            for (int i = 0; i < 4; i++) p[i] = Ps[(ty * 4 + i) * 65 + j];
            float4 v0 = Vs[j * 32 + ((tx * 2) ^ (j & 31))];
            float4 v1 = Vs[j * 32 + ((tx * 2 + 1) ^ (j & 31))];
            #pragma unroll
            for (int i = 0; i < 4; i++) {
                acc[i][0] += p[i] * v0.x; acc[i][1] += p[i] * v0.y;
                acc[i][2] += p[i] * v0.z; acc[i][3] += p[i] * v0.w;
                acc[i][4] += p[i] * v1.x; acc[i][5] += p[i] * v1.y;
                acc[i][6] += p[i] * v1.z; acc[i][7] += p[i] * v1.w;
            }
        }
    }

    #pragma unroll
    for (int i = 0; i < 4; i++) {
        int q = q0 + ty * 4 + i;
        float inv = 1.0f / l_[i];
        float4 o0 = make_float4(acc[i][0] * inv, acc[i][1] * inv, acc[i][2] * inv, acc[i][3] * inv);
        float4 o1 = make_float4(acc[i][4] * inv, acc[i][5] * inv, acc[i][6] * inv, acc[i][7] * inv);
        size_t base = (size_t)(b * SEQ + q) * QCOLS + h * DHEAD + tx * 8;
        *(float4*)(Z + base)     = o0;
        *(float4*)(Z + base + 4) = o1;
    }
}

// ----------------------------------------------------------------------------
// Host launcher
// ----------------------------------------------------------------------------
extern "C" void kernel_launch(void* const* d_in, const int* in_sizes, int n_in,
                              void* d_out, int out_size) {
    const float* x    = (const float*)d_in[0];
    const float* fcos = (const float*)d_in[1];
    const float* fsin = (const float*)d_in[2];
    const float* wq   = (const float*)d_in[3];
    const float* wk   = (const float*)d_in[4];
    const float* wv   = (const float*)d_in[5];
    const float* wo   = (const float*)d_in[6];
    float* out = (float*)d_out;

    __nv_bfloat16 *xhi, *xlo, *wqh, *wql, *wkh, *wkl, *wvh, *wvl, *woh, *wol, *zhi, *zlo;
    float *q, *k, *v, *z;
    cudaGetSymbolAddress((void**)&xhi, XHI);   cudaGetSymbolAddress((void**)&xlo, XLO);
    cudaGetSymbolAddress((void**)&wqh, WQT_HI); cudaGetSymbolAddress((void**)&wql, WQT_LO);
    cudaGetSymbolAddress((void**)&wkh, WKT_HI); cudaGetSymbolAddress((void**)&wkl, WKT_LO);
    cudaGetSymbolAddress((void**)&wvh, WVT_HI); cudaGetSymbolAddress((void**)&wvl, WVT_LO);
    cudaGetSymbolAddress((void**)&woh, WOT_HI); cudaGetSymbolAddress((void**)&wol, WOT_LO);
    cudaGetSymbolAddress((void**)&zhi, ZHI);   cudaGetSymbolAddress((void**)&zlo, ZLO);
    cudaGetSymbolAddress((void**)&q, QBUF);
    cudaGetSymbolAddress((void**)&k, KBUF);
    cudaGetSymbolAddress((void**)&v, VBUF);
    cudaGetSymbolAddress((void**)&z, ZBUF);

    cudaFuncSetAttribute(hmma_gemm, cudaFuncAttributeMaxDynamicSharedMemorySize, GEMM_SMEM);
    cudaFuncSetAttribute(flash_kernel, cudaFuncAttributeMaxDynamicSharedMemorySize, FLASH_SMEM);

    // Convert inputs
    {
        int n = MROWS * DMODEL;
        split_kernel<<<(n + 255) / 256, 256>>>(x, xhi, xlo, n);
    }
    transpose_split<<<dim3(QCOLS / 32, DMODEL / 32), dim3(32, 8)>>>(wq, wqh, wql, DMODEL, QCOLS);
    transpose_split<<<dim3(KVCOLS / 32, DMODEL / 32), dim3(32, 8)>>>(wk, wkh, wkl, DMODEL, KVCOLS);
    transpose_split<<<dim3(KVCOLS / 32, DMODEL / 32), dim3(32, 8)>>>(wv, wvh, wvl, DMODEL, KVCOLS);
    transpose_split<<<dim3(DMODEL / 32, DMODEL / 32), dim3(32, 8)>>>(wo, woh, wol, DMODEL, DMODEL);

    // QKV projections (HMMA bf16x3)
    hmma_gemm<<<dim3(QCOLS / BN, MROWS / BM), 256, GEMM_SMEM>>>(xhi, xlo, wqh, wql, q, QCOLS, DMODEL);
    hmma_gemm<<<dim3(KVCOLS / BN, MROWS / BM), 256, GEMM_SMEM>>>(xhi, xlo, wkh, wkl, k, KVCOLS, DMODEL);
    hmma_gemm<<<dim3(KVCOLS / BN, MROWS / BM), 256, GEMM_SMEM>>>(xhi, xlo, wvh, wvl, v, KVCOLS, DMODEL);

    // RoPE
    {
        int totq = MROWS * NHEAD * (DHEAD / 2);
        rope_kernel<<<(totq + 255) / 256, 256>>>(q, fcos, fsin, NHEAD);
        int totk = MROWS * NKVHEAD * (DHEAD / 2);
        rope_kernel<<<(totk + 255) / 256, 256>>>(k, fcos, fsin, NKVHEAD);
    }

    // Flash attention (fp32)
    flash_kernel<<<dim3(SEQ / 64, BATCH * NHEAD), 256, FLASH_SMEM>>>(q, k, v, z);

    // Output projection
    {
        int n = MROWS * DMODEL;
        split_kernel<<<(n + 255) / 256, 256>>>(z, zhi, zlo, n);
    }
    hmma_gemm<<<dim3(DMODEL / BN, MROWS / BM), 256, GEMM_SMEM>>>(zhi, zlo, woh, wol, out, DMODEL, DMODEL);
}

// round 4
// speedup vs baseline: 1.8233x; 1.0898x over previous
#include <cuda_runtime.h>
#include <cuda_bf16.h>
#include <cstdint>
#include <math.h>

// Problem constants
#define BATCH 2
#define SEQ 2048
#define DMODEL 4096
#define NHEAD 32
#define NKVHEAD 8
#define DHEAD 128
#define MROWS (BATCH * SEQ)            // 4096
#define QCOLS (NHEAD * DHEAD)          // 4096
#define KVCOLS (NKVHEAD * DHEAD)       // 1024

// ---------------------------------------------------------------------------
// Scratch buffers (__device__ globals; allocation-free rule)
// ---------------------------------------------------------------------------
__device__ __nv_bfloat16 XHI[(size_t)MROWS * DMODEL];
__device__ __nv_bfloat16 XLO[(size_t)MROWS * DMODEL];
__device__ __nv_bfloat16 WQT_HI[(size_t)QCOLS * DMODEL];
__device__ __nv_bfloat16 WQT_LO[(size_t)QCOLS * DMODEL];
__device__ __nv_bfloat16 WKT_HI[(size_t)KVCOLS * DMODEL];
__device__ __nv_bfloat16 WKT_LO[(size_t)KVCOLS * DMODEL];
__device__ __nv_bfloat16 WVT_HI[(size_t)KVCOLS * DMODEL];
__device__ __nv_bfloat16 WVT_LO[(size_t)KVCOLS * DMODEL];
__device__ __nv_bfloat16 WOT_HI[(size_t)DMODEL * DMODEL];
__device__ __nv_bfloat16 WOT_LO[(size_t)DMODEL * DMODEL];
__device__ __nv_bfloat16 ZHI[(size_t)MROWS * DMODEL];
__device__ __nv_bfloat16 ZLO[(size_t)MROWS * DMODEL];
__device__ float QBUF[(size_t)MROWS * QCOLS];
__device__ float KBUF[(size_t)MROWS * KVCOLS];
__device__ float VBUF[(size_t)MROWS * KVCOLS];
__device__ float ZBUF[(size_t)MROWS * QCOLS];

// ---------------------------------------------------------------------------
// Helpers
// ---------------------------------------------------------------------------
__device__ __forceinline__ uint32_t smem_u32(const void* p) {
    uint32_t a;
    asm("{ .reg .u64 t; cvta.to.shared.u64 t, %1; cvt.u32.u64 %0, t; }" : "=r"(a) : "l"(p));
    return a;
}

__device__ __forceinline__ void cp16(uint32_t dst, const void* src) {
    asm volatile("cp.async.cg.shared.global [%0], [%1], 16;" :: "r"(dst), "l"(src));
}
#define CP_COMMIT() asm volatile("cp.async.commit_group;" ::: "memory")
template <int N>
__device__ __forceinline__ void cp_wait() {
    asm volatile("cp.async.wait_group %0;" :: "n"(N) : "memory");
}

#define LDSM4(r, addr)                                                        \
    asm volatile("ldmatrix.sync.aligned.m8n8.x4.shared.b16 {%0,%1,%2,%3}, [%4];" \
        : "=r"((r)[0]), "=r"((r)[1]), "=r"((r)[2]), "=r"((r)[3]) : "r"(addr))

#define MMA16816(c, a, b0, b1)                                                \
    asm volatile("mma.sync.aligned.m16n8k16.row.col.f32.bf16.bf16.f32 "       \
        "{%0,%1,%2,%3}, {%4,%5,%6,%7}, {%8,%9}, {%0,%1,%2,%3};"               \
        : "+f"((c)[0]), "+f"((c)[1]), "+f"((c)[2]), "+f"((c)[3])              \
        : "r"((a)[0]), "r"((a)[1]), "r"((a)[2]), "r"((a)[3]),                 \
          "r"(b0), "r"(b1))

// ---------------------------------------------------------------------------
// fp32 -> bf16 hi/lo split (elementwise)
// ---------------------------------------------------------------------------
__global__ __launch_bounds__(256) void split_kernel(const float* __restrict__ src,
                                                    __nv_bfloat16* __restrict__ hi,
                                                    __nv_bfloat16* __restrict__ lo,
                                                    int n) {
    int i = blockIdx.x * blockDim.x + threadIdx.x;
    if (i >= n) return;
    float a = src[i];
    __nv_bfloat16 h = __float2bfloat16(a);
    hi[i] = h;
    lo[i] = __float2bfloat16(a - __bfloat162float(h));
}

// ---------------------------------------------------------------------------
// Transpose + split: W[K,N] fp32 -> T_hi/T_lo [N,K] bf16
// ---------------------------------------------------------------------------
__global__ __launch_bounds__(256) void transpose_split(const float* __restrict__ W,
                                                       __nv_bfloat16* __restrict__ Thi,
                                                       __nv_bfloat16* __restrict__ Tlo,
                                                       int K, int N) {
    __shared__ float t[32][33];
    int n0 = blockIdx.x * 32;
    int k0 = blockIdx.y * 32;
    int tx = threadIdx.x, ty = threadIdx.y;   // (32, 8)
    #pragma unroll
    for (int r = ty; r < 32; r += 8)
        t[r][tx] = W[(size_t)(k0 + r) * N + n0 + tx];
    __syncthreads();
    #pragma unroll
    for (int r = ty; r < 32; r += 8) {
        float a = t[tx][r];
        __nv_bfloat16 h = __float2bfloat16(a);
        size_t o = (size_t)(n0 + r) * K + k0 + tx;
        Thi[o] = h;
        Tlo[o] = __float2bfloat16(a - __bfloat162float(h));
    }
}

// ---------------------------------------------------------------------------
// HMMA bf16x3 GEMM, fused passes: C = Ahi*Bhi^T + Ahi*Blo^T + Alo*Bhi^T
// CTA tile 128x256, BK=32, 8 warps (2x4), warp tile 64x64.
// Each k-chunk loads AHi/ALo/BHi/BLo tiles once (48KB/stage); NST=4 stages,
// cp_wait<2>, single __syncthreads per iteration.
// grid: (N/256, M/128)
// ---------------------------------------------------------------------------
#define BM 128
#define BN 256
#define BK 32
#define AT_B (BM * BK * 2)            // 8192 per A tile
#define BT_B (BN * BK * 2)            // 16384 per B tile
#define STAGE_B (2 * AT_B + 2 * BT_B) // 49152
#define NST 4
#define GEMM_SMEM (NST * STAGE_B)     // 196608

// swizzled byte offset within a tile for (row, kseg[0..3]) — 64B rows
__device__ __forceinline__ uint32_t swz_off(int row, int ks) {
    return (uint32_t)(row * 64 + (((ks ^ (row >> 1)) & 3) << 4));
}

__global__ __launch_bounds__(256, 1)
void hmma_gemm(const __nv_bfloat16* __restrict__ Ahi, const __nv_bfloat16* __restrict__ Alo,
               const __nv_bfloat16* __restrict__ Bhi, const __nv_bfloat16* __restrict__ Blo,
               float* __restrict__ C, int N, int K) {
    extern __shared__ char smem[];
    const uint32_t sb = smem_u32(smem);
    const int tid = threadIdx.x;
    const int wid = tid >> 5;
    const int lane = tid & 31;
    const int wm = wid >> 2;        // 0..1
    const int wn = wid & 3;         // 0..3
    const int m0 = blockIdx.y * BM;
    const int n0 = blockIdx.x * BN;

    const int TOT = K / BK;         // 128

    float acc[4][8][4];
    #pragma unroll
    for (int i = 0; i < 4; i++)
        #pragma unroll
        for (int j = 0; j < 8; j++)
            #pragma unroll
            for (int r = 0; r < 4; r++) acc[i][j][r] = 0.0f;

    // chunk c -> stage s: AHi | ALo | BHi | BLo tiles
    auto load_chunk = [&](int c, int s) {
        const __nv_bfloat16* aH = Ahi + (size_t)m0 * K + c * BK;
        const __nv_bfloat16* aL = Alo + (size_t)m0 * K + c * BK;
        const __nv_bfloat16* bH = Bhi + (size_t)n0 * K + c * BK;
        const __nv_bfloat16* bL = Blo + (size_t)n0 * K + c * BK;
        uint32_t base = sb + s * STAGE_B;
        #pragma unroll
        for (int t = 0; t < 12; t++) {
            int idx = tid + t * 256;      // 0..3071
            const __nv_bfloat16* src;
            uint32_t dst;
            if (idx < 1024) {             // A tiles: 512 segs each
                int half = idx >> 9;      // 0=AHi 1=ALo
                int j = idx & 511;
                int row = j >> 2, ks = j & 3;
                src = (half ? aL : aH) + (size_t)row * K + ks * 8;
                dst = base + half * AT_B + swz_off(row, ks);
            } else {                      // B tiles: 1024 segs each
                int j = idx - 1024;
                int half = j >> 10;       // 0=BHi 1=BLo
                int jj = j & 1023;
                int row = jj >> 2, ks = jj & 3;
                src = (half ? bL : bH) + (size_t)row * K + ks * 8;
                dst = base + 2 * AT_B + half * BT_B + swz_off(row, ks);
            }
            cp16(dst, src);
        }
    };

    // prologue: NST-1 chunks in flight
    #pragma unroll
    for (int s = 0; s < NST - 1; s++) {
        if (s < TOT) load_chunk(s, s);
        CP_COMMIT();
    }

    const int r15 = lane & 15;
    const int hi = lane >> 4;

    for (int c = 0; c < TOT; c++) {
        const int s = c & (NST - 1);
        cp_wait<NST - 2>();
        __syncthreads();

        // issue next loads (into stage consumed at iter c-1)
        {
            int nc = c + NST - 1;
            if (nc < TOT) load_chunk(nc, nc & (NST - 1));
            CP_COMMIT();
        }

        const uint32_t aHb = sb + s * STAGE_B;
        const uint32_t aLb = aHb + AT_B;
        const uint32_t bHb = aHb + 2 * AT_B;
        const uint32_t bLb = bHb + BT_B;

        #pragma unroll
        for (int ks2 = 0; ks2 < 2; ks2++) {
            const int kseg = ks2 * 2 + hi;
            uint32_t aH[4][4], aL[4][4], bH[4][4], bL[4][4];
            #pragma unroll
            for (int i = 0; i < 4; i++) {
                int row = wm * 64 + i * 16 + r15;
                uint32_t so = swz_off(row, kseg);
                LDSM4(aH[i], aHb + so);
                LDSM4(aL[i], aLb + so);
            }
            #pragma unroll
            for (int j = 0; j < 4; j++) {
                int row = wn * 64 + j * 16 + r15;
                uint32_t so = swz_off(row, kseg);
                LDSM4(bH[j], bHb + so);
                LDSM4(bL[j], bLb + so);
            }
            // pass 1: AHi * BHi
            #pragma unroll
            for (int i = 0; i < 4; i++)
                #pragma unroll
                for (int j = 0; j < 4; j++) {
                    MMA16816(acc[i][2 * j],     aH[i], bH[j][0], bH[j][2]);
                    MMA16816(acc[i][2 * j + 1], aH[i], bH[j][1], bH[j][3]);
                }
            // pass 2: AHi * BLo
            #pragma unroll
            for (int i = 0; i < 4; i++)
                #pragma unroll
                for (int j = 0; j < 4; j++) {
                    MMA16816(acc[i][2 * j],     aH[i], bL[j][0], bL[j][2]);
                    MMA16816(acc[i][2 * j + 1], aH[i], bL[j][1], bL[j][3]);
                }
            // pass 3: ALo * BHi
            #pragma unroll
            for (int i = 0; i < 4; i++)
                #pragma unroll
                for (int j = 0; j < 4; j++) {
                    MMA16816(acc[i][2 * j],     aL[i], bH[j][0], bH[j][2]);
                    MMA16816(acc[i][2 * j + 1], aL[i], bH[j][1], bH[j][3]);
                }
        }
    }

    // Epilogue: direct stores
    const int quad = lane >> 2;       // 0..7
    const int tq = lane & 3;          // 0..3
    #pragma unroll
    for (int i = 0; i < 4; i++) {
        int row0 = m0 + wm * 64 + i * 16 + quad;
        #pragma unroll
        for (int j = 0; j < 8; j++) {
            int col = n0 + wn * 64 + j * 8 + tq * 2;
            *(float2*)(C + (size_t)row0 * N + col) =
                make_float2(acc[i][j][0], acc[i][j][1]);
            *(float2*)(C + (size_t)(row0 + 8) * N + col) =
                make_float2(acc[i][j][2], acc[i][j][3]);
        }
    }
}

// ----------------------------------------------------------------------------
// RoPE (interleaved pairs), in-place on Q or K buffer.
// ----------------------------------------------------------------------------
__global__ __launch_bounds__(256) void rope_kernel(float* __restrict__ buf,
                                                   const float* __restrict__ cosb,
                                                   const float* __restrict__ sinb,
                                                   int nheads) {
    int idx = blockIdx.x * blockDim.x + threadIdx.x;
    int total = MROWS * nheads * (DHEAD / 2);
    if (idx >= total) return;
    int d2 = idx & 63;
    int h = (idx >> 6) % nheads;
    int r = idx / (64 * nheads);
    int t = r & (SEQ - 1);
    size_t base = (size_t)r * nheads * DHEAD + h * DHEAD + d2 * 2;
    float xr = buf[base];
    float xi = buf[base + 1];
    float c = cosb[t * 64 + d2];
    float s = sinb[t * 64 + d2];
    buf[base]     = xr * c - xi * s;
    buf[base + 1] = xr * s + xi * c;
}

// ----------------------------------------------------------------------------
// Fused causal flash attention, fp32, GQA (4 q-heads per kv-head).
// ----------------------------------------------------------------------------
#define FLASH_SMEM (3 * 64 * 32 * 16 + 64 * 65 * 4)

__global__ __launch_bounds__(256) void flash_kernel(const float* __restrict__ Q,
                                                    const float* __restrict__ Kb,
                                                    const float* __restrict__ Vb,
                                                    float* __restrict__ Z) {
    extern __shared__ float4 sm4[];
    float4* Qs = sm4;
    float4* Ks = Qs + 64 * 32;
    float4* Vs = Ks + 64 * 32;
    float*  Ps = (float*)(Vs + 64 * 32);

    const int tid = threadIdx.x;
    const int ty = tid >> 4;
    const int tx = tid & 15;
    const int q0 = blockIdx.x * 64;
    const int bh = blockIdx.y;
    const int b = bh >> 5;
    const int h = bh & 31;
    const int kvh = h >> 2;

    for (int idx = tid; idx < 64 * 32; idx += 256) {
        int row = idx >> 5, c = idx & 31;
        float4 v = *(const float4*)(Q + (size_t)(b * SEQ + q0 + row) * QCOLS + h * DHEAD + c * 4);
        Qs[row * 32 + (c ^ (row & 31))] = v;
    }

    float m_[4], l_[4], acc[4][8];
    #pragma unroll
    for (int i = 0; i < 4; i++) {
        m_[i] = -1e30f;
        l_[i] = 0.0f;
        #pragma unroll
        for (int c = 0; c < 8; c++) acc[i][c] = 0.0f;
    }

    const float scale = 0.08838834764831845f;
    const int nkb = (q0 >> 6) + 1;

    for (int kb = 0; kb < nkb; kb++) {
        const int j0 = kb * 64;
        __syncthreads();

        for (int idx = tid; idx < 64 * 32; idx += 256) {
            int row = idx >> 5, c = idx & 31;
            size_t g = (size_t)(b * SEQ + j0 + row) * KVCOLS + kvh * DHEAD + c * 4;
            int swi = row * 32 + (c ^ (row & 31));
            Ks[swi] = *(const float4*)(Kb + g);
            Vs[swi] = *(const float4*)(Vb + g);
        }
        __syncthreads();

        float s[4][4];
        #pragma unroll
        for (int i = 0; i < 4; i++)
            #pragma unroll
            for (int j = 0; j < 4; j++) s[i][j] = 0.0f;

        #pragma unroll 4
        for (int d4 = 0; d4 < 32; d4++) {
            float4 qv[4], kv[4];
            #pragma unroll
            for (int i = 0; i < 4; i++) {
                int row = ty * 4 + i;
                qv[i] = Qs[row * 32 + (d4 ^ (row & 31))];
            }
            #pragma unroll
            for (int j = 0; j < 4; j++) {
                int row = tx * 4 + j;
                kv[j] = Ks[row * 32 + (d4 ^ (row & 31))];
            }
            #pragma unroll
            for (int i = 0; i < 4; i++)
                #pragma unroll
                for (int j = 0; j < 4; j++)
                    s[i][j] += qv[i].x * kv[j].x + qv[i].y * kv[j].y +
                               qv[i].z * kv[j].z + qv[i].w * kv[j].w;
        }

        #pragma unroll
        for (int i = 0; i < 4; i++) {
            int qg = q0 + ty * 4 + i;
            #pragma unroll
            for (int j = 0; j < 4; j++) {
                int kg = j0 + tx * 4 + j;
                s[i][j] = (kg <= qg) ? s[i][j] * scale : -1e30f;
            }
        }

        #pragma unroll
        for (int i = 0; i < 4; i++) {
            float rm = fmaxf(fmaxf(s[i][0], s[i][1]), fmaxf(s[i][2], s[i][3]));
            #pragma unroll
            for (int off = 1; off < 16; off <<= 1)
                rm = fmaxf(rm, __shfl_xor_sync(0xffffffffu, rm, off));
            float mn = fmaxf(m_[i], rm);
            float f = __expf(m_[i] - mn);
            float rs = 0.0f;
            #pragma unroll
            for (int j = 0; j < 4; j++) {
                float p = __expf(s[i][j] - mn);
                s[i][j] = p;
                rs += p;
            }
            #pragma unroll
            for (int off = 1; off < 16; off <<= 1)
                rs += __shfl_xor_sync(0xffffffffu, rs, off);
            l_[i] = l_[i] * f + rs;
            m_[i] = mn;
            #pragma unroll
            for (int c = 0; c < 8; c++) acc[i][c] *= f;
            #pragma unroll
            for (int j = 0; j < 4; j++)
                Ps[(ty * 4 + i) * 65 + tx * 4 + j] = s[i][j];
        }
        __syncthreads();

        #pragma unroll 4
        for (int j = 0; j < 64; j++) {
            float p[4];
            #pragma unroll
            for (int i = 0; i < 4; i++) p[i] = Ps[(ty * 4 + i) * 65 + j];
            float4 v0 = Vs[j * 32 + ((tx * 2) ^ (j & 31))];
            float4 v1 = Vs[j * 32 + ((tx * 2 + 1) ^ (j & 31))];
            #pragma unroll
            for (int i = 0; i < 4; i++) {
                acc[i][0] += p[i] * v0.x; acc[i][1] += p[i] * v0.y;
                acc[i][2] += p[i] * v0.z; acc[i][3] += p[i] * v0.w;
                acc[i][4] += p[i] * v1.x; acc[i][5] += p[i] * v1.y;
                acc[i][6] += p[i] * v1.z; acc[i][7] += p[i] * v1.w;
            }
        }
    }

    #pragma unroll
    for (int i = 0; i < 4; i++) {
        int q = q0 + ty * 4 + i;
        float inv = 1.0f / l_[i];
        float4 o0 = make_float4(acc[i][0] * inv, acc[i][1] * inv, acc[i][2] * inv, acc[i][3] * inv);
        float4 o1 = make_float4(acc[i][4] * inv, acc[i][5] * inv, acc[i][6] * inv, acc[i][7] * inv);
        size_t base = (size_t)(b * SEQ + q) * QCOLS + h * DHEAD + tx * 8;
        *(float4*)(Z + base)     = o0;
        *(float4*)(Z + base + 4) = o1;
    }
}

// ----------------------------------------------------------------------------
// Host launcher
// ----------------------------------------------------------------------------
extern "C" void kernel_launch(void* const* d_in, const int* in_sizes, int n_in,
                              void* d_out, int out_size) {
    const float* x    = (const float*)d_in[0];
    const float* fcos = (const float*)d_in[1];
    const float* fsin = (const float*)d_in[2];
    const float* wq   = (const float*)d_in[3];
    const float* wk   = (const float*)d_in[4];
    const float* wv   = (const float*)d_in[5];
    const float* wo   = (const float*)d_in[6];
    float* out = (float*)d_out;

    __nv_bfloat16 *xhi, *xlo, *wqh, *wql, *wkh, *wkl, *wvh, *wvl, *woh, *wol, *zhi, *zlo;
    float *q, *k, *v, *z;
    cudaGetSymbolAddress((void**)&xhi, XHI);   cudaGetSymbolAddress((void**)&xlo, XLO);
    cudaGetSymbolAddress((void**)&wqh, WQT_HI); cudaGetSymbolAddress((void**)&wql, WQT_LO);
    cudaGetSymbolAddress((void**)&wkh, WKT_HI); cudaGetSymbolAddress((void**)&wkl, WKT_LO);
    cudaGetSymbolAddress((void**)&wvh, WVT_HI); cudaGetSymbolAddress((void**)&wvl, WVT_LO);
    cudaGetSymbolAddress((void**)&woh, WOT_HI); cudaGetSymbolAddress((void**)&wol, WOT_LO);
    cudaGetSymbolAddress((void**)&zhi, ZHI);   cudaGetSymbolAddress((void**)&zlo, ZLO);
    cudaGetSymbolAddress((void**)&q, QBUF);
    cudaGetSymbolAddress((void**)&k, KBUF);
    cudaGetSymbolAddress((void**)&v, VBUF);
    cudaGetSymbolAddress((void**)&z, ZBUF);

    cudaFuncSetAttribute(hmma_gemm, cudaFuncAttributeMaxDynamicSharedMemorySize, GEMM_SMEM);
    cudaFuncSetAttribute(flash_kernel, cudaFuncAttributeMaxDynamicSharedMemorySize, FLASH_SMEM);

    // Convert inputs
    {
        int n = MROWS * DMODEL;
        split_kernel<<<(n + 255) / 256, 256>>>(x, xhi, xlo, n);
    }
    transpose_split<<<dim3(QCOLS / 32, DMODEL / 32), dim3(32, 8)>>>(wq, wqh, wql, DMODEL, QCOLS);
    transpose_split<<<dim3(KVCOLS / 32, DMODEL / 32), dim3(32, 8)>>>(wk, wkh, wkl, DMODEL, KVCOLS);
    transpose_split<<<dim3(KVCOLS / 32, DMODEL / 32), dim3(32, 8)>>>(wv, wvh, wvl, DMODEL, KVCOLS);
    transpose_split<<<dim3(DMODEL / 32, DMODEL / 32), dim3(32, 8)>>>(wo, woh, wol, DMODEL, DMODEL);

    // QKV projections (HMMA bf16x3, fused passes)
    hmma_gemm<<<dim3(QCOLS / BN, MROWS / BM), 256, GEMM_SMEM>>>(xhi, xlo, wqh, wql, q, QCOLS, DMODEL);
    hmma_gemm<<<dim3(KVCOLS / BN, MROWS / BM), 256, GEMM_SMEM>>>(xhi, xlo, wkh, wkl, k, KVCOLS, DMODEL);
    hmma_gemm<<<dim3(KVCOLS / BN, MROWS / BM), 256, GEMM_SMEM>>>(xhi, xlo, wvh, wvl, v, KVCOLS, DMODEL);

    // RoPE
    {
        int totq = MROWS * NHEAD * (DHEAD / 2);
        rope_kernel<<<(totq + 255) / 256, 256>>>(q, fcos, fsin, NHEAD);
        int totk = MROWS * NKVHEAD * (DHEAD / 2);
        rope_kernel<<<(totk + 255) / 256, 256>>>(k, fcos, fsin, NKVHEAD);
    }

    // Flash attention (fp32)
    flash_kernel<<<dim3(SEQ / 64, BATCH * NHEAD), 256, FLASH_SMEM>>>(q, k, v, z);

    // Output projection
    {
        int n = MROWS * DMODEL;
        split_kernel<<<(n + 255) / 256, 256>>>(z, zhi, zlo, n);
    }
    hmma_gemm<<<dim3(DMODEL / BN, MROWS / BM), 256, GEMM_SMEM>>>(zhi, zlo, woh, wol, out, DMODEL, DMODEL);
}

// round 5
// speedup vs baseline: 3.5452x; 1.9444x over previous
#include <cuda_runtime.h>
#include <cuda_bf16.h>
#include <cuda_fp16.h>
#include <cstdint>
#include <math.h>

// Problem constants
#define BATCH 2
#define SEQ 2048
#define DMODEL 4096
#define NHEAD 32
#define NKVHEAD 8
#define DHEAD 128
#define MROWS (BATCH * SEQ)            // 4096
#define QCOLS (NHEAD * DHEAD)          // 4096
#define KVCOLS (NKVHEAD * DHEAD)       // 1024

// ---------------------------------------------------------------------------
// Scratch buffers (__device__ globals; allocation-free rule)
// ---------------------------------------------------------------------------
__device__ __nv_bfloat16 XHI[(size_t)MROWS * DMODEL];
__device__ __nv_bfloat16 XLO[(size_t)MROWS * DMODEL];
__device__ __nv_bfloat16 WQT_HI[(size_t)QCOLS * DMODEL];
__device__ __nv_bfloat16 WQT_LO[(size_t)QCOLS * DMODEL];
__device__ __nv_bfloat16 WKT_HI[(size_t)KVCOLS * DMODEL];
__device__ __nv_bfloat16 WKT_LO[(size_t)KVCOLS * DMODEL];
__device__ __nv_bfloat16 WVT_HI[(size_t)KVCOLS * DMODEL];
__device__ __nv_bfloat16 WVT_LO[(size_t)KVCOLS * DMODEL];
__device__ __nv_bfloat16 WOT_HI[(size_t)DMODEL * DMODEL];
__device__ __nv_bfloat16 WOT_LO[(size_t)DMODEL * DMODEL];
__device__ __nv_bfloat16 ZHI[(size_t)MROWS * DMODEL];
__device__ __nv_bfloat16 ZLO[(size_t)MROWS * DMODEL];
__device__ float QBUF[(size_t)MROWS * QCOLS];
__device__ float KBUF[(size_t)MROWS * KVCOLS];
__device__ float VBUF[(size_t)MROWS * KVCOLS];
// fp16 head-major tensors for flash
__device__ __half Q16[(size_t)MROWS * QCOLS];
__device__ __half K16[(size_t)MROWS * KVCOLS];
__device__ __half V16[(size_t)MROWS * KVCOLS];

// ---------------------------------------------------------------------------
// Helpers
// ---------------------------------------------------------------------------
__device__ __forceinline__ uint32_t smem_u32(const void* p) {
    uint32_t a;
    asm("{ .reg .u64 t; cvta.to.shared.u64 t, %1; cvt.u32.u64 %0, t; }" : "=r"(a) : "l"(p));
    return a;
}

__device__ __forceinline__ void cp16(uint32_t dst, const void* src) {
    asm volatile("cp.async.cg.shared.global [%0], [%1], 16;" :: "r"(dst), "l"(src));
}
#define CP_COMMIT() asm volatile("cp.async.commit_group;" ::: "memory")
template <int N>
__device__ __forceinline__ void cp_wait() {
    asm volatile("cp.async.wait_group %0;" :: "n"(N) : "memory");
}

#define LDSM4(r, addr)                                                        \
    asm volatile("ldmatrix.sync.aligned.m8n8.x4.shared.b16 {%0,%1,%2,%3}, [%4];" \
        : "=r"((r)[0]), "=r"((r)[1]), "=r"((r)[2]), "=r"((r)[3]) : "r"(addr))

#define LDSM4T(r, addr)                                                       \
    asm volatile("ldmatrix.sync.aligned.m8n8.x4.trans.shared.b16 {%0,%1,%2,%3}, [%4];" \
        : "=r"((r)[0]), "=r"((r)[1]), "=r"((r)[2]), "=r"((r)[3]) : "r"(addr))

#define MMA16816(c, a, b0, b1)                                                \
    asm volatile("mma.sync.aligned.m16n8k16.row.col.f32.bf16.bf16.f32 "       \
        "{%0,%1,%2,%3}, {%4,%5,%6,%7}, {%8,%9}, {%0,%1,%2,%3};"               \
        : "+f"((c)[0]), "+f"((c)[1]), "+f"((c)[2]), "+f"((c)[3])              \
        : "r"((a)[0]), "r"((a)[1]), "r"((a)[2]), "r"((a)[3]),                 \
          "r"(b0), "r"(b1))

#define MMAH(c, a, b0, b1)                                                    \
    asm volatile("mma.sync.aligned.m16n8k16.row.col.f32.f16.f16.f32 "         \
        "{%0,%1,%2,%3}, {%4,%5,%6,%7}, {%8,%9}, {%0,%1,%2,%3};"               \
        : "+f"((c)[0]), "+f"((c)[1]), "+f"((c)[2]), "+f"((c)[3])              \
        : "r"((a)[0]), "r"((a)[1]), "r"((a)[2]), "r"((a)[3]),                 \
          "r"(b0), "r"(b1))

__device__ __forceinline__ uint32_t packh2(float x, float y) {
    __half2 h = __floats2half2_rn(x, y);
    return *(uint32_t*)&h;
}

// swizzled byte offset within a 64B-row tile for (row, kseg[0..3])
__device__ __forceinline__ uint32_t swz_off(int row, int ks) {
    return (uint32_t)(row * 64 + (((ks ^ (row >> 1)) & 3) << 4));
}

// ---------------------------------------------------------------------------
// fp32 -> bf16 hi/lo split (elementwise)
// ---------------------------------------------------------------------------
__global__ __launch_bounds__(256) void split_kernel(const float* __restrict__ src,
                                                    __nv_bfloat16* __restrict__ hi,
                                                    __nv_bfloat16* __restrict__ lo,
                                                    int n) {
    int i = blockIdx.x * blockDim.x + threadIdx.x;
    if (i >= n) return;
    float a = src[i];
    __nv_bfloat16 h = __float2bfloat16(a);
    hi[i] = h;
    lo[i] = __float2bfloat16(a - __bfloat162float(h));
}

// ---------------------------------------------------------------------------
// Transpose + split: W[K,N] fp32 -> T_hi/T_lo [N,K] bf16
// ---------------------------------------------------------------------------
__global__ __launch_bounds__(256) void transpose_split(const float* __restrict__ W,
                                                       __nv_bfloat16* __restrict__ Thi,
                                                       __nv_bfloat16* __restrict__ Tlo,
                                                       int K, int N) {
    __shared__ float t[32][33];
    int n0 = blockIdx.x * 32;
    int k0 = blockIdx.y * 32;
    int tx = threadIdx.x, ty = threadIdx.y;   // (32, 8)
    #pragma unroll
    for (int r = ty; r < 32; r += 8)
        t[r][tx] = W[(size_t)(k0 + r) * N + n0 + tx];
    __syncthreads();
    #pragma unroll
    for (int r = ty; r < 32; r += 8) {
        float a = t[tx][r];
        __nv_bfloat16 h = __float2bfloat16(a);
        size_t o = (size_t)(n0 + r) * K + k0 + tx;
        Thi[o] = h;
        Tlo[o] = __float2bfloat16(a - __bfloat162float(h));
    }
}

// ---------------------------------------------------------------------------
// HMMA bf16x3 GEMM (unchanged from R4 — at mma.sync roofline)
// ---------------------------------------------------------------------------
#define BM 128
#define BN 256
#define BK 32
#define AT_B (BM * BK * 2)
#define BT_B (BN * BK * 2)
#define STAGE_B (2 * AT_B + 2 * BT_B)
#define NST 4
#define GEMM_SMEM (NST * STAGE_B)

__global__ __launch_bounds__(256, 1)
void hmma_gemm(const __nv_bfloat16* __restrict__ Ahi, const __nv_bfloat16* __restrict__ Alo,
               const __nv_bfloat16* __restrict__ Bhi, const __nv_bfloat16* __restrict__ Blo,
               float* __restrict__ C, int N, int K) {
    extern __shared__ char smem[];
    const uint32_t sb = smem_u32(smem);
    const int tid = threadIdx.x;
    const int wid = tid >> 5;
    const int lane = tid & 31;
    const int wm = wid >> 2;
    const int wn = wid & 3;
    const int m0 = blockIdx.y * BM;
    const int n0 = blockIdx.x * BN;

    const int TOT = K / BK;

    float acc[4][8][4];
    #pragma unroll
    for (int i = 0; i < 4; i++)
        #pragma unroll
        for (int j = 0; j < 8; j++)
            #pragma unroll
            for (int r = 0; r < 4; r++) acc[i][j][r] = 0.0f;

    auto load_chunk = [&](int c, int s) {
        const __nv_bfloat16* aH = Ahi + (size_t)m0 * K + c * BK;
        const __nv_bfloat16* aL = Alo + (size_t)m0 * K + c * BK;
        const __nv_bfloat16* bH = Bhi + (size_t)n0 * K + c * BK;
        const __nv_bfloat16* bL = Blo + (size_t)n0 * K + c * BK;
        uint32_t base = sb + s * STAGE_B;
        #pragma unroll
        for (int t = 0; t < 12; t++) {
            int idx = tid + t * 256;
            const __nv_bfloat16* src;
            uint32_t dst;
            if (idx < 1024) {
                int half = idx >> 9;
                int j = idx & 511;
                int row = j >> 2, ks = j & 3;
                src = (half ? aL : aH) + (size_t)row * K + ks * 8;
                dst = base + half * AT_B + swz_off(row, ks);
            } else {
                int j = idx - 1024;
                int half = j >> 10;
                int jj = j & 1023;
                int row = jj >> 2, ks = jj & 3;
                src = (half ? bL : bH) + (size_t)row * K + ks * 8;
                dst = base + 2 * AT_B + half * BT_B + swz_off(row, ks);
            }
            cp16(dst, src);
        }
    };

    #pragma unroll
    for (int s = 0; s < NST - 1; s++) {
        if (s < TOT) load_chunk(s, s);
        CP_COMMIT();
    }

    const int r15 = lane & 15;
    const int hi = lane >> 4;

    for (int c = 0; c < TOT; c++) {
        const int s = c & (NST - 1);
        cp_wait<NST - 2>();
        __syncthreads();

        {
            int nc = c + NST - 1;
            if (nc < TOT) load_chunk(nc, nc & (NST - 1));
            CP_COMMIT();
        }

        const uint32_t aHb = sb + s * STAGE_B;
        const uint32_t aLb = aHb + AT_B;
        const uint32_t bHb = aHb + 2 * AT_B;
        const uint32_t bLb = bHb + BT_B;

        #pragma unroll
        for (int ks2 = 0; ks2 < 2; ks2++) {
            const int kseg = ks2 * 2 + hi;
            uint32_t aH[4][4], aL[4][4], bH[4][4], bL[4][4];
            #pragma unroll
            for (int i = 0; i < 4; i++) {
                int row = wm * 64 + i * 16 + r15;
                uint32_t so = swz_off(row, kseg);
                LDSM4(aH[i], aHb + so);
                LDSM4(aL[i], aLb + so);
            }
            #pragma unroll
            for (int j = 0; j < 4; j++) {
                int row = wn * 64 + j * 16 + r15;
                uint32_t so = swz_off(row, kseg);
                LDSM4(bH[j], bHb + so);
                LDSM4(bL[j], bLb + so);
            }
            #pragma unroll
            for (int i = 0; i < 4; i++)
                #pragma unroll
                for (int j = 0; j < 4; j++) {
                    MMA16816(acc[i][2 * j],     aH[i], bH[j][0], bH[j][2]);
                    MMA16816(acc[i][2 * j + 1], aH[i], bH[j][1], bH[j][3]);
                }
            #pragma unroll
            for (int i = 0; i < 4; i++)
                #pragma unroll
                for (int j = 0; j < 4; j++) {
                    MMA16816(acc[i][2 * j],     aH[i], bL[j][0], bL[j][2]);
                    MMA16816(acc[i][2 * j + 1], aH[i], bL[j][1], bL[j][3]);
                }
            #pragma unroll
            for (int i = 0; i < 4; i++)
                #pragma unroll
                for (int j = 0; j < 4; j++) {
                    MMA16816(acc[i][2 * j],     aL[i], bH[j][0], bH[j][2]);
                    MMA16816(acc[i][2 * j + 1], aL[i], bH[j][1], bH[j][3]);
                }
        }
    }

    const int quad = lane >> 2;
    const int tq = lane & 3;
    #pragma unroll
    for (int i = 0; i < 4; i++) {
        int row0 = m0 + wm * 64 + i * 16 + quad;
        #pragma unroll
        for (int j = 0; j < 8; j++) {
            int col = n0 + wn * 64 + j * 8 + tq * 2;
            *(float2*)(C + (size_t)row0 * N + col) =
                make_float2(acc[i][j][0], acc[i][j][1]);
            *(float2*)(C + (size_t)(row0 + 8) * N + col) =
                make_float2(acc[i][j][2], acc[i][j][3]);
        }
    }
}

// ----------------------------------------------------------------------------
// RoPE + fp16 convert: fp32 [b,t,nh,128] -> fp16 [b,nh,t,128], scaled by sc.
// ----------------------------------------------------------------------------
__global__ __launch_bounds__(256) void rope_convert(const float* __restrict__ buf,
                                                    const float* __restrict__ cosb,
                                                    const float* __restrict__ sinb,
                                                    __half* __restrict__ out,
                                                    int nheads, float sc) {
    int idx = blockIdx.x * blockDim.x + threadIdx.x;
    int total = MROWS * nheads * (DHEAD / 2);
    if (idx >= total) return;
    int d2 = idx & 63;
    int h = (idx >> 6) % nheads;
    int r = idx / (64 * nheads);
    int t = r & (SEQ - 1);
    int b = r >> 11;
    size_t in = (size_t)r * nheads * DHEAD + h * DHEAD + d2 * 2;
    float xr = buf[in];
    float xi = buf[in + 1];
    float c = cosb[t * 64 + d2];
    float s = sinb[t * 64 + d2];
    float orr = (xr * c - xi * s) * sc;
    float oii = (xr * s + xi * c) * sc;
    size_t o = (((size_t)b * nheads + h) * SEQ + t) * DHEAD + d2 * 2;
    out[o]     = __float2half(orr);
    out[o + 1] = __float2half(oii);
}

// V convert: fp32 [b,t,kvh,128] -> fp16 [b,kvh,t,128]
__global__ __launch_bounds__(256) void vconvert(const float* __restrict__ src,
                                                __half* __restrict__ out) {
    int idx = blockIdx.x * blockDim.x + threadIdx.x;
    if (idx >= MROWS * KVCOLS) return;
    int d = idx & 127;
    int kvh = (idx >> 7) & 7;
    int r = idx >> 10;
    int t = r & (SEQ - 1);
    int b = r >> 11;
    out[(((size_t)b * NKVHEAD + kvh) * SEQ + t) * DHEAD + d] =
        __float2half(src[(size_t)r * KVCOLS + kvh * DHEAD + d]);
}

// ----------------------------------------------------------------------------
// HMMA fp16 flash attention. grid (SEQ/128, B*NHEAD), 256 threads, 8 warps.
// Q tile 128x128 in regs (scale*log2e folded into Q16); KV tiles 64x128,
// double-buffered cp.async. P kept in registers as fp16 A-frags.
// Writes ZHI/ZLO bf16 hi/lo directly.
// ----------------------------------------------------------------------------
#define QS_BYTES (128 * 128 * 2)      // 32768
#define KV_BYTES (64 * 128 * 2)       // 16384
#define FLASH_SMEM (QS_BYTES + 2 * (2 * KV_BYTES))   // 98304

__global__ __launch_bounds__(256, 1)
void flash_hmma(const __half* __restrict__ Qg, const __half* __restrict__ Kg,
                const __half* __restrict__ Vg,
                __nv_bfloat16* __restrict__ Zhi, __nv_bfloat16* __restrict__ Zlo) {
    extern __shared__ char smem[];
    const uint32_t sb = smem_u32(smem);
    const int tid = threadIdx.x;
    const int wid = tid >> 5;
    const int lane = tid & 31;
    const int quad = lane >> 2, tq = lane & 3;
    const int r15 = lane & 15, hsel = lane >> 4;
    const int qt = blockIdx.x;
    const int q0 = qt * 128;
    const int bh = blockIdx.y;
    const int b = bh >> 5, h = bh & 31, kvh = h >> 2;
    const __half* qsrc = Qg + ((size_t)bh * SEQ + q0) * DHEAD;
    const __half* ksrc0 = Kg + ((size_t)(b * NKVHEAD + kvh)) * SEQ * DHEAD;
    const __half* vsrc0 = Vg + ((size_t)(b * NKVHEAD + kvh)) * SEQ * DHEAD;
    const int nkt = 2 * (qt + 1);

    // load Q tile: 2048 x 16B segs
    #pragma unroll
    for (int t = 0; t < 8; t++) {
        int j = tid + t * 256;
        int row = j >> 4, dc = (j >> 2) & 3, ks = j & 3;
        cp16(sb + dc * 8192 + swz_off(row, ks), qsrc + (size_t)row * DHEAD + dc * 32 + ks * 8);
    }
    CP_COMMIT();

    auto load_kv = [&](int t, int s) {
        uint32_t kb = sb + QS_BYTES + s * (2 * KV_BYTES);
        uint32_t vb = kb + KV_BYTES;
        const __half* ks_ = ksrc0 + (size_t)t * 64 * DHEAD;
        const __half* vs_ = vsrc0 + (size_t)t * 64 * DHEAD;
        #pragma unroll
        for (int u = 0; u < 8; u++) {
            int j = tid + u * 256;
            bool isv = j >= 1024;
            int jj = j & 1023;
            int row = jj >> 4, dc = (jj >> 2) & 3, ks = jj & 3;
            cp16((isv ? vb : kb) + dc * 4096 + swz_off(row, ks),
                 (isv ? vs_ : ks_) + (size_t)row * DHEAD + dc * 32 + ks * 8);
        }
    };

    load_kv(0, 0); CP_COMMIT();
    cp_wait<1>();          // Q resident
    __syncthreads();

    // Q fragments: m16 rows wid*16, k = D 128 -> 8 k16 chunks
    uint32_t qF[8][4];
    #pragma unroll
    for (int kc = 0; kc < 8; kc++) {
        int dc = kc >> 1;
        LDSM4(qF[kc], sb + dc * 8192 + swz_off(wid * 16 + r15, (kc & 1) * 2 + hsel));
    }

    if (nkt > 1) load_kv(1, 1);
    CP_COMMIT();

    float o[16][4];
    #pragma unroll
    for (int i = 0; i < 16; i++)
        #pragma unroll
        for (int r = 0; r < 4; r++) o[i][r] = 0.0f;
    float m0v = -1e30f, m1v = -1e30f, l0v = 0.0f, l1v = 0.0f;

    const int row_g0 = q0 + wid * 16 + quad;

    for (int t = 0; t < nkt; t++) {
        cp_wait<1>();
        __syncthreads();
        const uint32_t kb = sb + QS_BYTES + (t & 1) * (2 * KV_BYTES);
        const uint32_t vb = kb + KV_BYTES;

        // S = Q @ K^T
        float s[8][4];
        #pragma unroll
        for (int j = 0; j < 8; j++)
            #pragma unroll
            for (int r = 0; r < 4; r++) s[j][r] = 0.0f;

        #pragma unroll
        for (int kc = 0; kc < 8; kc++) {
            int dc = kc >> 1;
            #pragma unroll
            for (int j = 0; j < 4; j++) {
                uint32_t kf[4];
                LDSM4(kf, kb + dc * 4096 + swz_off(j * 16 + r15, (kc & 1) * 2 + hsel));
                MMAH(s[2 * j],     qF[kc], kf[0], kf[2]);
                MMAH(s[2 * j + 1], qF[kc], kf[1], kf[3]);
            }
        }

        // causal mask (only diagonal-adjacent tiles)
        if (t >= nkt - 2) {
            #pragma unroll
            for (int j = 0; j < 8; j++) {
                int col = t * 64 + j * 8 + tq * 2;
                if (col     > row_g0)     s[j][0] = -1e30f;
                if (col + 1 > row_g0)     s[j][1] = -1e30f;
                if (col     > row_g0 + 8) s[j][2] = -1e30f;
                if (col + 1 > row_g0 + 8) s[j][3] = -1e30f;
            }
        }

        // row max (rows quad, quad+8)
        float rm0 = -1e30f, rm1 = -1e30f;
        #pragma unroll
        for (int j = 0; j < 8; j++) {
            rm0 = fmaxf(rm0, fmaxf(s[j][0], s[j][1]));
            rm1 = fmaxf(rm1, fmaxf(s[j][2], s[j][3]));
        }
        rm0 = fmaxf(rm0, __shfl_xor_sync(0xffffffffu, rm0, 1));
        rm0 = fmaxf(rm0, __shfl_xor_sync(0xffffffffu, rm0, 2));
        rm1 = fmaxf(rm1, __shfl_xor_sync(0xffffffffu, rm1, 1));
        rm1 = fmaxf(rm1, __shfl_xor_sync(0xffffffffu, rm1, 2));

        float mn0 = fmaxf(m0v, rm0), mn1 = fmaxf(m1v, rm1);
        float f0 = exp2f(m0v - mn0), f1 = exp2f(m1v - mn1);

        float rs0 = 0.0f, rs1 = 0.0f;
        uint32_t aP[4][4];
        #pragma unroll
        for (int kk = 0; kk < 4; kk++) {
            float p00 = exp2f(s[2 * kk][0] - mn0);
            float p01 = exp2f(s[2 * kk][1] - mn0);
            float p02 = exp2f(s[2 * kk][2] - mn1);
            float p03 = exp2f(s[2 * kk][3] - mn1);
            float p10 = exp2f(s[2 * kk + 1][0] - mn0);
            float p11 = exp2f(s[2 * kk + 1][1] - mn0);
            float p12 = exp2f(s[2 * kk + 1][2] - mn1);
            float p13 = exp2f(s[2 * kk + 1][3] - mn1);
            rs0 += p00 + p01 + p10 + p11;
            rs1 += p02 + p03 + p12 + p13;
            aP[kk][0] = packh2(p00, p01);
            aP[kk][1] = packh2(p02, p03);
            aP[kk][2] = packh2(p10, p11);
            aP[kk][3] = packh2(p12, p13);
        }
        rs0 += __shfl_xor_sync(0xffffffffu, rs0, 1);
        rs0 += __shfl_xor_sync(0xffffffffu, rs0, 2);
        rs1 += __shfl_xor_sync(0xffffffffu, rs1, 1);
        rs1 += __shfl_xor_sync(0xffffffffu, rs1, 2);

        l0v = l0v * f0 + rs0;
        l1v = l1v * f1 + rs1;
        m0v = mn0; m1v = mn1;

        #pragma unroll
        for (int i = 0; i < 16; i++) {
            o[i][0] *= f0; o[i][1] *= f0;
            o[i][2] *= f1; o[i][3] *= f1;
        }

        // O += P @ V  (V via ldmatrix.x4.trans: two n8 tiles per load)
        #pragma unroll
        for (int djp = 0; djp < 8; djp++) {
            int dj = djp * 2 + hsel;          // lane-dependent dj for address
            int dc = dj >> 2, ks = dj & 3;
            #pragma unroll
            for (int kk = 0; kk < 4; kk++) {
                uint32_t vr[4];
                LDSM4T(vr, vb + dc * 4096 + swz_off(kk * 16 + r15, ks));
                MMAH(o[djp * 2],     aP[kk], vr[0], vr[1]);
                MMAH(o[djp * 2 + 1], aP[kk], vr[2], vr[3]);
            }
        }

        __syncthreads();
        if (t + 2 < nkt) load_kv(t + 2, t & 1);
        CP_COMMIT();
    }

    // epilogue
    float inv0 = 1.0f / l0v, inv1 = 1.0f / l1v;
    size_t base0 = (size_t)(b * SEQ + row_g0) * DMODEL + h * DHEAD;
    size_t base1 = base0 + (size_t)8 * DMODEL;
    #pragma unroll
    for (int djt = 0; djt < 16; djt++) {
        int col = djt * 8 + tq * 2;
        float v0 = o[djt][0] * inv0, v1 = o[djt][1] * inv0;
        float v2 = o[djt][2] * inv1, v3 = o[djt][3] * inv1;
        __nv_bfloat16 h0 = __float2bfloat16(v0), h1 = __float2bfloat16(v1);
        __nv_bfloat16 h2 = __float2bfloat16(v2), h3 = __float2bfloat16(v3);
        *(__nv_bfloat162*)(Zhi + base0 + col) = __nv_bfloat162(h0, h1);
        *(__nv_bfloat162*)(Zhi + base1 + col) = __nv_bfloat162(h2, h3);
        *(__nv_bfloat162*)(Zlo + base0 + col) = __nv_bfloat162(
            __float2bfloat16(v0 - __bfloat162float(h0)),
            __float2bfloat16(v1 - __bfloat162float(h1)));
        *(__nv_bfloat162*)(Zlo + base1 + col) = __nv_bfloat162(
            __float2bfloat16(v2 - __bfloat162float(h2)),
            __float2bfloat16(v3 - __bfloat162float(h3)));
    }
}

// ----------------------------------------------------------------------------
// Host launcher
// ----------------------------------------------------------------------------
extern "C" void kernel_launch(void* const* d_in, const int* in_sizes, int n_in,
                              void* d_out, int out_size) {
    const float* x    = (const float*)d_in[0];
    const float* fcos = (const float*)d_in[1];
    const float* fsin = (const float*)d_in[2];
    const float* wq   = (const float*)d_in[3];
    const float* wk   = (const float*)d_in[4];
    const float* wv   = (const float*)d_in[5];
    const float* wo   = (const float*)d_in[6];
    float* out = (float*)d_out;

    __nv_bfloat16 *xhi, *xlo, *wqh, *wql, *wkh, *wkl, *wvh, *wvl, *woh, *wol, *zhi, *zlo;
    float *q, *k, *v;
    __half *q16, *k16, *v16;
    cudaGetSymbolAddress((void**)&xhi, XHI);   cudaGetSymbolAddress((void**)&xlo, XLO);
    cudaGetSymbolAddress((void**)&wqh, WQT_HI); cudaGetSymbolAddress((void**)&wql, WQT_LO);
    cudaGetSymbolAddress((void**)&wkh, WKT_HI); cudaGetSymbolAddress((void**)&wkl, WKT_LO);
    cudaGetSymbolAddress((void**)&wvh, WVT_HI); cudaGetSymbolAddress((void**)&wvl, WVT_LO);
    cudaGetSymbolAddress((void**)&woh, WOT_HI); cudaGetSymbolAddress((void**)&wol, WOT_LO);
    cudaGetSymbolAddress((void**)&zhi, ZHI);   cudaGetSymbolAddress((void**)&zlo, ZLO);
    cudaGetSymbolAddress((void**)&q, QBUF);
    cudaGetSymbolAddress((void**)&k, KBUF);
    cudaGetSymbolAddress((void**)&v, VBUF);
    cudaGetSymbolAddress((void**)&q16, Q16);
    cudaGetSymbolAddress((void**)&k16, K16);
    cudaGetSymbolAddress((void**)&v16, V16);

    cudaFuncSetAttribute(hmma_gemm, cudaFuncAttributeMaxDynamicSharedMemorySize, GEMM_SMEM);
    cudaFuncSetAttribute(flash_hmma, cudaFuncAttributeMaxDynamicSharedMemorySize, FLASH_SMEM);

    // Convert inputs
    {
        int n = MROWS * DMODEL;
        split_kernel<<<(n + 255) / 256, 256>>>(x, xhi, xlo, n);
    }
    transpose_split<<<dim3(QCOLS / 32, DMODEL / 32), dim3(32, 8)>>>(wq, wqh, wql, DMODEL, QCOLS);
    transpose_split<<<dim3(KVCOLS / 32, DMODEL / 32), dim3(32, 8)>>>(wk, wkh, wkl, DMODEL, KVCOLS);
    transpose_split<<<dim3(KVCOLS / 32, DMODEL / 32), dim3(32, 8)>>>(wv, wvh, wvl, DMODEL, KVCOLS);
    transpose_split<<<dim3(DMODEL / 32, DMODEL / 32), dim3(32, 8)>>>(wo, woh, wol, DMODEL, DMODEL);

    // QKV projections (HMMA bf16x3)
    hmma_gemm<<<dim3(QCOLS / BN, MROWS / BM), 256, GEMM_SMEM>>>(xhi, xlo, wqh, wql, q, QCOLS, DMODEL);
    hmma_gemm<<<dim3(KVCOLS / BN, MROWS / BM), 256, GEMM_SMEM>>>(xhi, xlo, wkh, wkl, k, KVCOLS, DMODEL);
    hmma_gemm<<<dim3(KVCOLS / BN, MROWS / BM), 256, GEMM_SMEM>>>(xhi, xlo, wvh, wvl, v, KVCOLS, DMODEL);

    // RoPE + fp16 convert (scale*log2e folded into Q), V convert
    const float qs = 0.08838834764831845f * 1.4426950408889634f;
    {
        int totq = MROWS * NHEAD * (DHEAD / 2);
        rope_convert<<<(totq + 255) / 256, 256>>>(q, fcos, fsin, q16, NHEAD, qs);
        int totk = MROWS * NKVHEAD * (DHEAD / 2);
        rope_convert<<<(totk + 255) / 256, 256>>>(k, fcos, fsin, k16, NKVHEAD, 1.0f);
        int totv = MROWS * KVCOLS;
        vconvert<<<(totv + 255) / 256, 256>>>(v, v16);
    }

    // Flash attention (fp16 HMMA) -> writes zhi/zlo directly
    flash_hmma<<<dim3(SEQ / 128, BATCH * NHEAD), 256, FLASH_SMEM>>>(q16, k16, v16, zhi, zlo);

    // Output projection
    hmma_gemm<<<dim3(DMODEL / BN, MROWS / BM), 256, GEMM_SMEM>>>(zhi, zlo, woh, wol, out, DMODEL, DMODEL);
}

// round 6
// speedup vs baseline: 5.3096x; 1.4977x over previous
#include <cuda_runtime.h>
#include <cuda_bf16.h>
#include <cuda_fp16.h>
#include <cstdint>
#include <math.h>

// Problem constants
#define BATCH 2
#define SEQ 2048
#define DMODEL 4096
#define NHEAD 32
#define NKVHEAD 8
#define DHEAD 128
#define MROWS (BATCH * SEQ)            // 4096
#define QCOLS (NHEAD * DHEAD)          // 4096
#define KVCOLS (NKVHEAD * DHEAD)       // 1024

// ---------------------------------------------------------------------------
// Scratch buffers (__device__ globals; allocation-free rule)
// ---------------------------------------------------------------------------
__device__ __half X16[(size_t)MROWS * DMODEL];
__device__ __half WQT16[(size_t)QCOLS * DMODEL];
__device__ __half WKVT16[(size_t)2 * KVCOLS * DMODEL];   // rows 0-1023 K, 1024-2047 V
__device__ __nv_bfloat16 WOT_HI[(size_t)DMODEL * DMODEL];
__device__ __nv_bfloat16 WOT_LO[(size_t)DMODEL * DMODEL];
__device__ __nv_bfloat16 ZHI[(size_t)MROWS * DMODEL];
__device__ __nv_bfloat16 ZLO[(size_t)MROWS * DMODEL];
__device__ __half Q16[(size_t)MROWS * QCOLS];
__device__ __half K16[(size_t)MROWS * KVCOLS];
__device__ __half V16[(size_t)MROWS * KVCOLS];

// ---------------------------------------------------------------------------
// Helpers
// ---------------------------------------------------------------------------
__device__ __forceinline__ uint32_t smem_u32(const void* p) {
    uint32_t a;
    asm("{ .reg .u64 t; cvta.to.shared.u64 t, %1; cvt.u32.u64 %0, t; }" : "=r"(a) : "l"(p));
    return a;
}

__device__ __forceinline__ void cp16(uint32_t dst, const void* src) {
    asm volatile("cp.async.cg.shared.global [%0], [%1], 16;" :: "r"(dst), "l"(src));
}
#define CP_COMMIT() asm volatile("cp.async.commit_group;" ::: "memory")
template <int N>
__device__ __forceinline__ void cp_wait() {
    asm volatile("cp.async.wait_group %0;" :: "n"(N) : "memory");
}

#define LDSM4(r, addr)                                                        \
    asm volatile("ldmatrix.sync.aligned.m8n8.x4.shared.b16 {%0,%1,%2,%3}, [%4];" \
        : "=r"((r)[0]), "=r"((r)[1]), "=r"((r)[2]), "=r"((r)[3]) : "r"(addr))

#define LDSM4T(r, addr)                                                       \
    asm volatile("ldmatrix.sync.aligned.m8n8.x4.trans.shared.b16 {%0,%1,%2,%3}, [%4];" \
        : "=r"((r)[0]), "=r"((r)[1]), "=r"((r)[2]), "=r"((r)[3]) : "r"(addr))

#define MMA16816(c, a, b0, b1)                                                \
    asm volatile("mma.sync.aligned.m16n8k16.row.col.f32.bf16.bf16.f32 "       \
        "{%0,%1,%2,%3}, {%4,%5,%6,%7}, {%8,%9}, {%0,%1,%2,%3};"               \
        : "+f"((c)[0]), "+f"((c)[1]), "+f"((c)[2]), "+f"((c)[3])              \
        : "r"((a)[0]), "r"((a)[1]), "r"((a)[2]), "r"((a)[3]),                 \
          "r"(b0), "r"(b1))

#define MMAH(c, a, b0, b1)                                                    \
    asm volatile("mma.sync.aligned.m16n8k16.row.col.f32.f16.f16.f32 "         \
        "{%0,%1,%2,%3}, {%4,%5,%6,%7}, {%8,%9}, {%0,%1,%2,%3};"               \
        : "+f"((c)[0]), "+f"((c)[1]), "+f"((c)[2]), "+f"((c)[3])              \
        : "r"((a)[0]), "r"((a)[1]), "r"((a)[2]), "r"((a)[3]),                 \
          "r"(b0), "r"(b1))

__device__ __forceinline__ uint32_t packh2(float x, float y) {
    __half2 h = __floats2half2_rn(x, y);
    return *(uint32_t*)&h;
}

// swizzled byte offset within a 64B-row tile for (row, kseg[0..3])
__device__ __forceinline__ uint32_t swz_off(int row, int ks) {
    return (uint32_t)(row * 64 + (((ks ^ (row >> 1)) & 3) << 4));
}

// ---------------------------------------------------------------------------
// fp32 -> fp16 convert (elementwise)
// ---------------------------------------------------------------------------
__global__ __launch_bounds__(256) void xconvert(const float* __restrict__ src,
                                                __half* __restrict__ dst, int n) {
    int i = blockIdx.x * blockDim.x + threadIdx.x;
    if (i < n) dst[i] = __float2half(src[i]);
}

// Transpose + fp16 convert: W[K,N] fp32 -> T [N,K] fp16
__global__ __launch_bounds__(256) void transpose_convert(const float* __restrict__ W,
                                                         __half* __restrict__ T,
                                                         int K, int N) {
    __shared__ float t[32][33];
    int n0 = blockIdx.x * 32;
    int k0 = blockIdx.y * 32;
    int tx = threadIdx.x, ty = threadIdx.y;
    #pragma unroll
    for (int r = ty; r < 32; r += 8)
        t[r][tx] = W[(size_t)(k0 + r) * N + n0 + tx];
    __syncthreads();
    #pragma unroll
    for (int r = ty; r < 32; r += 8)
        T[(size_t)(n0 + r) * K + k0 + tx] = __float2half(t[tx][r]);
}

// Transpose + bf16 hi/lo split: W[K,N] fp32 -> T_hi/T_lo [N,K] bf16
__global__ __launch_bounds__(256) void transpose_split(const float* __restrict__ W,
                                                       __nv_bfloat16* __restrict__ Thi,
                                                       __nv_bfloat16* __restrict__ Tlo,
                                                       int K, int N) {
    __shared__ float t[32][33];
    int n0 = blockIdx.x * 32;
    int k0 = blockIdx.y * 32;
    int tx = threadIdx.x, ty = threadIdx.y;
    #pragma unroll
    for (int r = ty; r < 32; r += 8)
        t[r][tx] = W[(size_t)(k0 + r) * N + n0 + tx];
    __syncthreads();
    #pragma unroll
    for (int r = ty; r < 32; r += 8) {
        float a = t[tx][r];
        __nv_bfloat16 h = __float2bfloat16(a);
        size_t o = (size_t)(n0 + r) * K + k0 + tx;
        Thi[o] = h;
        Tlo[o] = __float2bfloat16(a - __bfloat162float(h));
    }
}

// ---------------------------------------------------------------------------
// Single-pass fp16 GEMM with fused RoPE/scale/head-major fp16 epilogue.
// C[M,N] = A[M,K] @ B[N,K]^T ; mode 0: all cols Q (rope, scale sc, out0[b,32,t,d])
//                              mode 1: cols<1024 K (rope, sc) -> out0; else V -> out1
// CTA 128x256, BK=32, NST=6 stages (24KB each), 8 warps.
// ---------------------------------------------------------------------------
#define BM 128
#define BN 256
#define BK 32
#define F_AT_B (BM * BK * 2)              // 8192
#define F_BT_B (BN * BK * 2)              // 16384
#define F_STAGE (F_AT_B + F_BT_B)         // 24576
#define F_NST 6
#define GEMM_F16_SMEM (F_NST * F_STAGE)   // 147456

__global__ __launch_bounds__(256, 1)
void gemm_f16_fused(const __half* __restrict__ A, const __half* __restrict__ B,
                    const float* __restrict__ cosb, const float* __restrict__ sinb,
                    __half* __restrict__ out0, __half* __restrict__ out1,
                    int N, int K, int mode, float sc) {
    extern __shared__ char smem[];
    const uint32_t sb = smem_u32(smem);
    const int tid = threadIdx.x;
    const int wid = tid >> 5;
    const int lane = tid & 31;
    const int wm = wid >> 2;
    const int wn = wid & 3;
    const int m0 = blockIdx.y * BM;
    const int n0 = blockIdx.x * BN;
    const int TOT = K / BK;

    float acc[4][8][4];
    #pragma unroll
    for (int i = 0; i < 4; i++)
        #pragma unroll
        for (int j = 0; j < 8; j++)
            #pragma unroll
            for (int r = 0; r < 4; r++) acc[i][j][r] = 0.0f;

    auto load_chunk = [&](int c, int s) {
        const __half* as = A + (size_t)m0 * K + c * BK;
        const __half* bs = B + (size_t)n0 * K + c * BK;
        uint32_t base = sb + s * F_STAGE;
        #pragma unroll
        for (int t = 0; t < 6; t++) {
            int idx = tid + t * 256;      // 512 A segs + 1024 B segs
            if (idx < 512) {
                int row = idx >> 2, ks = idx & 3;
                cp16(base + swz_off(row, ks), as + (size_t)row * K + ks * 8);
            } else {
                int j = idx - 512;
                int row = j >> 2, ks = j & 3;
                cp16(base + F_AT_B + swz_off(row, ks), bs + (size_t)row * K + ks * 8);
            }
        }
    };

    #pragma unroll
    for (int s = 0; s < F_NST - 1; s++) {
        if (s < TOT) load_chunk(s, s);
        CP_COMMIT();
    }

    const int r15 = lane & 15;
    const int hsel = lane >> 4;

    for (int c = 0; c < TOT; c++) {
        const int s = c % F_NST;
        cp_wait<F_NST - 2>();
        __syncthreads();

        {
            int nc = c + F_NST - 1;
            if (nc < TOT) load_chunk(nc, nc % F_NST);
            CP_COMMIT();
        }

        const uint32_t ab = sb + s * F_STAGE;
        const uint32_t bb = ab + F_AT_B;

        #pragma unroll
        for (int ks2 = 0; ks2 < 2; ks2++) {
            const int kseg = ks2 * 2 + hsel;
            uint32_t aF[4][4], bF[4][4];
            #pragma unroll
            for (int i = 0; i < 4; i++)
                LDSM4(aF[i], ab + swz_off(wm * 64 + i * 16 + r15, kseg));
            #pragma unroll
            for (int j = 0; j < 4; j++)
                LDSM4(bF[j], bb + swz_off(wn * 64 + j * 16 + r15, kseg));
            #pragma unroll
            for (int i = 0; i < 4; i++)
                #pragma unroll
                for (int j = 0; j < 4; j++) {
                    MMAH(acc[i][2 * j],     aF[i], bF[j][0], bF[j][2]);
                    MMAH(acc[i][2 * j + 1], aF[i], bF[j][1], bF[j][3]);
                }
        }
    }

    // Fused epilogue: RoPE (+scale) and head-major fp16 store
    const int quad = lane >> 2;
    const int tq = lane & 3;
    #pragma unroll
    for (int i = 0; i < 4; i++) {
        int r0 = m0 + wm * 64 + i * 16 + quad;
        int b0 = r0 >> 11;
        int t0 = r0 & (SEQ - 1);
        #pragma unroll
        for (int j = 0; j < 8; j++) {
            int c = n0 + wn * 64 + j * 8 + tq * 2;
            __half* dst;
            int H, cc = c;
            bool dorope;
            if (mode == 0) { dst = out0; H = NHEAD; dorope = true; }
            else if (c < 1024) { dst = out0; H = NKVHEAD; dorope = true; }
            else { dst = out1; H = NKVHEAD; cc = c - 1024; dorope = false; }
            int h = cc >> 7, d = cc & 127, d2 = d >> 1;
            float f0 = acc[i][j][0], f1 = acc[i][j][1];
            float f2 = acc[i][j][2], f3 = acc[i][j][3];
            if (dorope) {
                float c0 = cosb[t0 * 64 + d2], s0 = sinb[t0 * 64 + d2];
                float c1 = cosb[(t0 + 8) * 64 + d2], s1 = sinb[(t0 + 8) * 64 + d2];
                float a0 = (f0 * c0 - f1 * s0) * sc, a1 = (f0 * s0 + f1 * c0) * sc;
                float a2 = (f2 * c1 - f3 * s1) * sc, a3 = (f2 * s1 + f3 * c1) * sc;
                f0 = a0; f1 = a1; f2 = a2; f3 = a3;
            }
            size_t o0 = (((size_t)b0 * H + h) * SEQ + t0) * DHEAD + d;
            *(__half2*)(dst + o0) = __floats2half2_rn(f0, f1);
            *(__half2*)(dst + o0 + (size_t)8 * DHEAD) = __floats2half2_rn(f2, f3);
        }
    }
}

// ---------------------------------------------------------------------------
// HMMA bf16x3 GEMM (output projection only)
// ---------------------------------------------------------------------------
#define AT_B (BM * BK * 2)
#define BT_B (BN * BK * 2)
#define STAGE_B (2 * AT_B + 2 * BT_B)
#define NST 4
#define GEMM_SMEM (NST * STAGE_B)

__global__ __launch_bounds__(256, 1)
void hmma_gemm(const __nv_bfloat16* __restrict__ Ahi, const __nv_bfloat16* __restrict__ Alo,
               const __nv_bfloat16* __restrict__ Bhi, const __nv_bfloat16* __restrict__ Blo,
               float* __restrict__ C, int N, int K) {
    extern __shared__ char smem[];
    const uint32_t sb = smem_u32(smem);
    const int tid = threadIdx.x;
    const int wid = tid >> 5;
    const int lane = tid & 31;
    const int wm = wid >> 2;
    const int wn = wid & 3;
    const int m0 = blockIdx.y * BM;
    const int n0 = blockIdx.x * BN;
    const int TOT = K / BK;

    float acc[4][8][4];
    #pragma unroll
    for (int i = 0; i < 4; i++)
        #pragma unroll
        for (int j = 0; j < 8; j++)
            #pragma unroll
            for (int r = 0; r < 4; r++) acc[i][j][r] = 0.0f;

    auto load_chunk = [&](int c, int s) {
        const __nv_bfloat16* aH = Ahi + (size_t)m0 * K + c * BK;
        const __nv_bfloat16* aL = Alo + (size_t)m0 * K + c * BK;
        const __nv_bfloat16* bH = Bhi + (size_t)n0 * K + c * BK;
        const __nv_bfloat16* bL = Blo + (size_t)n0 * K + c * BK;
        uint32_t base = sb + s * STAGE_B;
        #pragma unroll
        for (int t = 0; t < 12; t++) {
            int idx = tid + t * 256;
            const __nv_bfloat16* src;
            uint32_t dst;
            if (idx < 1024) {
                int half = idx >> 9;
                int j = idx & 511;
                int row = j >> 2, ks = j & 3;
                src = (half ? aL : aH) + (size_t)row * K + ks * 8;
                dst = base + half * AT_B + swz_off(row, ks);
            } else {
                int j = idx - 1024;
                int half = j >> 10;
                int jj = j & 1023;
                int row = jj >> 2, ks = jj & 3;
                src = (half ? bL : bH) + (size_t)row * K + ks * 8;
                dst = base + 2 * AT_B + half * BT_B + swz_off(row, ks);
            }
            cp16(dst, src);
        }
    };

    #pragma unroll
    for (int s = 0; s < NST - 1; s++) {
        if (s < TOT) load_chunk(s, s);
        CP_COMMIT();
    }

    const int r15 = lane & 15;
    const int hi = lane >> 4;

    for (int c = 0; c < TOT; c++) {
        const int s = c & (NST - 1);
        cp_wait<NST - 2>();
        __syncthreads();

        {
            int nc = c + NST - 1;
            if (nc < TOT) load_chunk(nc, nc & (NST - 1));
            CP_COMMIT();
        }

        const uint32_t aHb = sb + s * STAGE_B;
        const uint32_t aLb = aHb + AT_B;
        const uint32_t bHb = aHb + 2 * AT_B;
        const uint32_t bLb = bHb + BT_B;

        #pragma unroll
        for (int ks2 = 0; ks2 < 2; ks2++) {
            const int kseg = ks2 * 2 + hi;
            uint32_t aH[4][4], aL[4][4], bH[4][4], bL[4][4];
            #pragma unroll
            for (int i = 0; i < 4; i++) {
                int row = wm * 64 + i * 16 + r15;
                uint32_t so = swz_off(row, kseg);
                LDSM4(aH[i], aHb + so);
                LDSM4(aL[i], aLb + so);
            }
            #pragma unroll
            for (int j = 0; j < 4; j++) {
                int row = wn * 64 + j * 16 + r15;
                uint32_t so = swz_off(row, kseg);
                LDSM4(bH[j], bHb + so);
                LDSM4(bL[j], bLb + so);
            }
            #pragma unroll
            for (int i = 0; i < 4; i++)
                #pragma unroll
                for (int j = 0; j < 4; j++) {
                    MMA16816(acc[i][2 * j],     aH[i], bH[j][0], bH[j][2]);
                    MMA16816(acc[i][2 * j + 1], aH[i], bH[j][1], bH[j][3]);
                }
            #pragma unroll
            for (int i = 0; i < 4; i++)
                #pragma unroll
                for (int j = 0; j < 4; j++) {
                    MMA16816(acc[i][2 * j],     aH[i], bL[j][0], bL[j][2]);
                    MMA16816(acc[i][2 * j + 1], aH[i], bL[j][1], bL[j][3]);
                }
            #pragma unroll
            for (int i = 0; i < 4; i++)
                #pragma unroll
                for (int j = 0; j < 4; j++) {
                    MMA16816(acc[i][2 * j],     aL[i], bH[j][0], bH[j][2]);
                    MMA16816(acc[i][2 * j + 1], aL[i], bH[j][1], bH[j][3]);
                }
        }
    }

    const int quad = lane >> 2;
    const int tq = lane & 3;
    #pragma unroll
    for (int i = 0; i < 4; i++) {
        int row0 = m0 + wm * 64 + i * 16 + quad;
        #pragma unroll
        for (int j = 0; j < 8; j++) {
            int col = n0 + wn * 64 + j * 8 + tq * 2;
            *(float2*)(C + (size_t)row0 * N + col) =
                make_float2(acc[i][j][0], acc[i][j][1]);
            *(float2*)(C + (size_t)(row0 + 8) * N + col) =
                make_float2(acc[i][j][2], acc[i][j][3]);
        }
    }
}

// ----------------------------------------------------------------------------
// HMMA fp16 flash attention (unchanged from R5).
// ----------------------------------------------------------------------------
#define QS_BYTES (128 * 128 * 2)
#define KV_BYTES (64 * 128 * 2)
#define FLASH_SMEM (QS_BYTES + 2 * (2 * KV_BYTES))

__global__ __launch_bounds__(256, 1)
void flash_hmma(const __half* __restrict__ Qg, const __half* __restrict__ Kg,
                const __half* __restrict__ Vg,
                __nv_bfloat16* __restrict__ Zhi, __nv_bfloat16* __restrict__ Zlo) {
    extern __shared__ char smem[];
    const uint32_t sb = smem_u32(smem);
    const int tid = threadIdx.x;
    const int wid = tid >> 5;
    const int lane = tid & 31;
    const int quad = lane >> 2, tq = lane & 3;
    const int r15 = lane & 15, hsel = lane >> 4;
    const int qt = blockIdx.x;
    const int q0 = qt * 128;
    const int bh = blockIdx.y;
    const int b = bh >> 5, h = bh & 31, kvh = h >> 2;
    const __half* qsrc = Qg + ((size_t)bh * SEQ + q0) * DHEAD;
    const __half* ksrc0 = Kg + ((size_t)(b * NKVHEAD + kvh)) * SEQ * DHEAD;
    const __half* vsrc0 = Vg + ((size_t)(b * NKVHEAD + kvh)) * SEQ * DHEAD;
    const int nkt = 2 * (qt + 1);

    #pragma unroll
    for (int t = 0; t < 8; t++) {
        int j = tid + t * 256;
        int row = j >> 4, dc = (j >> 2) & 3, ks = j & 3;
        cp16(sb + dc * 8192 + swz_off(row, ks), qsrc + (size_t)row * DHEAD + dc * 32 + ks * 8);
    }
    CP_COMMIT();

    auto load_kv = [&](int t, int s) {
        uint32_t kb = sb + QS_BYTES + s * (2 * KV_BYTES);
        uint32_t vb = kb + KV_BYTES;
        const __half* ks_ = ksrc0 + (size_t)t * 64 * DHEAD;
        const __half* vs_ = vsrc0 + (size_t)t * 64 * DHEAD;
        #pragma unroll
        for (int u = 0; u < 8; u++) {
            int j = tid + u * 256;
            bool isv = j >= 1024;
            int jj = j & 1023;
            int row = jj >> 4, dc = (jj >> 2) & 3, ks = jj & 3;
            cp16((isv ? vb : kb) + dc * 4096 + swz_off(row, ks),
                 (isv ? vs_ : ks_) + (size_t)row * DHEAD + dc * 32 + ks * 8);
        }
    };

    load_kv(0, 0); CP_COMMIT();
    cp_wait<1>();
    __syncthreads();

    uint32_t qF[8][4];
    #pragma unroll
    for (int kc = 0; kc < 8; kc++) {
        int dc = kc >> 1;
        LDSM4(qF[kc], sb + dc * 8192 + swz_off(wid * 16 + r15, (kc & 1) * 2 + hsel));
    }

    if (nkt > 1) load_kv(1, 1);
    CP_COMMIT();

    float o[16][4];
    #pragma unroll
    for (int i = 0; i < 16; i++)
        #pragma unroll
        for (int r = 0; r < 4; r++) o[i][r] = 0.0f;
    float m0v = -1e30f, m1v = -1e30f, l0v = 0.0f, l1v = 0.0f;

    const int row_g0 = q0 + wid * 16 + quad;

    for (int t = 0; t < nkt; t++) {
        cp_wait<1>();
        __syncthreads();
        const uint32_t kb = sb + QS_BYTES + (t & 1) * (2 * KV_BYTES);
        const uint32_t vb = kb + KV_BYTES;

        float s[8][4];
        #pragma unroll
        for (int j = 0; j < 8; j++)
            #pragma unroll
            for (int r = 0; r < 4; r++) s[j][r] = 0.0f;

        #pragma unroll
        for (int kc = 0; kc < 8; kc++) {
            int dc = kc >> 1;
            #pragma unroll
            for (int j = 0; j < 4; j++) {
                uint32_t kf[4];
                LDSM4(kf, kb + dc * 4096 + swz_off(j * 16 + r15, (kc & 1) * 2 + hsel));
                MMAH(s[2 * j],     qF[kc], kf[0], kf[2]);
                MMAH(s[2 * j + 1], qF[kc], kf[1], kf[3]);
            }
        }

        if (t >= nkt - 2) {
            #pragma unroll
            for (int j = 0; j < 8; j++) {
                int col = t * 64 + j * 8 + tq * 2;
                if (col     > row_g0)     s[j][0] = -1e30f;
                if (col + 1 > row_g0)     s[j][1] = -1e30f;
                if (col     > row_g0 + 8) s[j][2] = -1e30f;
                if (col + 1 > row_g0 + 8) s[j][3] = -1e30f;
            }
        }

        float rm0 = -1e30f, rm1 = -1e30f;
        #pragma unroll
        for (int j = 0; j < 8; j++) {
            rm0 = fmaxf(rm0, fmaxf(s[j][0], s[j][1]));
            rm1 = fmaxf(rm1, fmaxf(s[j][2], s[j][3]));
        }
        rm0 = fmaxf(rm0, __shfl_xor_sync(0xffffffffu, rm0, 1));
        rm0 = fmaxf(rm0, __shfl_xor_sync(0xffffffffu, rm0, 2));
        rm1 = fmaxf(rm1, __shfl_xor_sync(0xffffffffu, rm1, 1));
        rm1 = fmaxf(rm1, __shfl_xor_sync(0xffffffffu, rm1, 2));

        float mn0 = fmaxf(m0v, rm0), mn1 = fmaxf(m1v, rm1);
        float f0 = exp2f(m0v - mn0), f1 = exp2f(m1v - mn1);

        float rs0 = 0.0f, rs1 = 0.0f;
        uint32_t aP[4][4];
        #pragma unroll
        for (int kk = 0; kk < 4; kk++) {
            float p00 = exp2f(s[2 * kk][0] - mn0);
            float p01 = exp2f(s[2 * kk][1] - mn0);
            float p02 = exp2f(s[2 * kk][2] - mn1);
            float p03 = exp2f(s[2 * kk][3] - mn1);
            float p10 = exp2f(s[2 * kk + 1][0] - mn0);
            float p11 = exp2f(s[2 * kk + 1][1] - mn0);
            float p12 = exp2f(s[2 * kk + 1][2] - mn1);
            float p13 = exp2f(s[2 * kk + 1][3] - mn1);
            rs0 += p00 + p01 + p10 + p11;
            rs1 += p02 + p03 + p12 + p13;
            aP[kk][0] = packh2(p00, p01);
            aP[kk][1] = packh2(p02, p03);
            aP[kk][2] = packh2(p10, p11);
            aP[kk][3] = packh2(p12, p13);
        }
        rs0 += __shfl_xor_sync(0xffffffffu, rs0, 1);
        rs0 += __shfl_xor_sync(0xffffffffu, rs0, 2);
        rs1 += __shfl_xor_sync(0xffffffffu, rs1, 1);
        rs1 += __shfl_xor_sync(0xffffffffu, rs1, 2);

        l0v = l0v * f0 + rs0;
        l1v = l1v * f1 + rs1;
        m0v = mn0; m1v = mn1;

        #pragma unroll
        for (int i = 0; i < 16; i++) {
            o[i][0] *= f0; o[i][1] *= f0;
            o[i][2] *= f1; o[i][3] *= f1;
        }

        #pragma unroll
        for (int djp = 0; djp < 8; djp++) {
            int dj = djp * 2 + hsel;
            int dc = dj >> 2, ks = dj & 3;
            #pragma unroll
            for (int kk = 0; kk < 4; kk++) {
                uint32_t vr[4];
                LDSM4T(vr, vb + dc * 4096 + swz_off(kk * 16 + r15, ks));
                MMAH(o[djp * 2],     aP[kk], vr[0], vr[1]);
                MMAH(o[djp * 2 + 1], aP[kk], vr[2], vr[3]);
            }
        }

        __syncthreads();
        if (t + 2 < nkt) load_kv(t + 2, t & 1);
        CP_COMMIT();
    }

    float inv0 = 1.0f / l0v, inv1 = 1.0f / l1v;
    size_t base0 = (size_t)(b * SEQ + row_g0) * DMODEL + h * DHEAD;
    size_t base1 = base0 + (size_t)8 * DMODEL;
    #pragma unroll
    for (int djt = 0; djt < 16; djt++) {
        int col = djt * 8 + tq * 2;
        float v0 = o[djt][0] * inv0, v1 = o[djt][1] * inv0;
        float v2 = o[djt][2] * inv1, v3 = o[djt][3] * inv1;
        __nv_bfloat16 h0 = __float2bfloat16(v0), h1 = __float2bfloat16(v1);
        __nv_bfloat16 h2 = __float2bfloat16(v2), h3 = __float2bfloat16(v3);
        *(__nv_bfloat162*)(Zhi + base0 + col) = __nv_bfloat162(h0, h1);
        *(__nv_bfloat162*)(Zhi + base1 + col) = __nv_bfloat162(h2, h3);
        *(__nv_bfloat162*)(Zlo + base0 + col) = __nv_bfloat162(
            __float2bfloat16(v0 - __bfloat162float(h0)),
            __float2bfloat16(v1 - __bfloat162float(h1)));
        *(__nv_bfloat162*)(Zlo + base1 + col) = __nv_bfloat162(
            __float2bfloat16(v2 - __bfloat162float(h2)),
            __float2bfloat16(v3 - __bfloat162float(h3)));
    }
}

// ----------------------------------------------------------------------------
// Host launcher
// ----------------------------------------------------------------------------
extern "C" void kernel_launch(void* const* d_in, const int* in_sizes, int n_in,
                              void* d_out, int out_size) {
    const float* x    = (const float*)d_in[0];
    const float* fcos = (const float*)d_in[1];
    const float* fsin = (const float*)d_in[2];
    const float* wq   = (const float*)d_in[3];
    const float* wk   = (const float*)d_in[4];
    const float* wv   = (const float*)d_in[5];
    const float* wo   = (const float*)d_in[6];
    float* out = (float*)d_out;

    __half *x16, *wqt16, *wkvt16, *q16, *k16, *v16;
    __nv_bfloat16 *woh, *wol, *zhi, *zlo;
    cudaGetSymbolAddress((void**)&x16, X16);
    cudaGetSymbolAddress((void**)&wqt16, WQT16);
    cudaGetSymbolAddress((void**)&wkvt16, WKVT16);
    cudaGetSymbolAddress((void**)&woh, WOT_HI);
    cudaGetSymbolAddress((void**)&wol, WOT_LO);
    cudaGetSymbolAddress((void**)&zhi, ZHI);
    cudaGetSymbolAddress((void**)&zlo, ZLO);
    cudaGetSymbolAddress((void**)&q16, Q16);
    cudaGetSymbolAddress((void**)&k16, K16);
    cudaGetSymbolAddress((void**)&v16, V16);

    cudaFuncSetAttribute(gemm_f16_fused, cudaFuncAttributeMaxDynamicSharedMemorySize, GEMM_F16_SMEM);
    cudaFuncSetAttribute(hmma_gemm, cudaFuncAttributeMaxDynamicSharedMemorySize, GEMM_SMEM);
    cudaFuncSetAttribute(flash_hmma, cudaFuncAttributeMaxDynamicSharedMemorySize, FLASH_SMEM);

    // Input conversions
    {
        int n = MROWS * DMODEL;
        xconvert<<<(n + 255) / 256, 256>>>(x, x16, n);
    }
    transpose_convert<<<dim3(QCOLS / 32, DMODEL / 32), dim3(32, 8)>>>(wq, wqt16, DMODEL, QCOLS);
    transpose_convert<<<dim3(KVCOLS / 32, DMODEL / 32), dim3(32, 8)>>>(wk, wkvt16, DMODEL, KVCOLS);
    transpose_convert<<<dim3(KVCOLS / 32, DMODEL / 32), dim3(32, 8)>>>(wv, wkvt16 + (size_t)KVCOLS * DMODEL, DMODEL, KVCOLS);
    transpose_split<<<dim3(DMODEL / 32, DMODEL / 32), dim3(32, 8)>>>(wo, woh, wol, DMODEL, DMODEL);

    // QKV projections (single-pass fp16, fused RoPE/convert epilogues)
    const float qs = 0.08838834764831845f * 1.4426950408889634f;   // scale * log2(e)
    gemm_f16_fused<<<dim3(QCOLS / BN, MROWS / BM), 256, GEMM_F16_SMEM>>>(
        x16, wqt16, fcos, fsin, q16, nullptr, QCOLS, DMODEL, 0, qs);
    gemm_f16_fused<<<dim3((2 * KVCOLS) / BN, MROWS / BM), 256, GEMM_F16_SMEM>>>(
        x16, wkvt16, fcos, fsin, k16, v16, 2 * KVCOLS, DMODEL, 1, 1.0f);

    // Flash attention (fp16 HMMA) -> ZHI/ZLO
    flash_hmma<<<dim3(SEQ / 128, BATCH * NHEAD), 256, FLASH_SMEM>>>(q16, k16, v16, zhi, zlo);

    // Output projection (bf16x3, exact path)
    hmma_gemm<<<dim3(DMODEL / BN, MROWS / BM), 256, GEMM_SMEM>>>(zhi, zlo, woh, wol, out, DMODEL, DMODEL);
}

// round 7
// speedup vs baseline: 6.3905x; 1.2036x over previous
#include <cuda_runtime.h>
#include <cuda_bf16.h>
#include <cuda_fp16.h>
#include <cstdint>
#include <math.h>

// Problem constants
#define BATCH 2
#define SEQ 2048
#define DMODEL 4096
#define NHEAD 32
#define NKVHEAD 8
#define DHEAD 128
#define MROWS (BATCH * SEQ)            // 4096
#define QCOLS (NHEAD * DHEAD)          // 4096
#define KVCOLS (NKVHEAD * DHEAD)       // 1024
#define QKVCOLS (QCOLS + 2 * KVCOLS)   // 6144

// ---------------------------------------------------------------------------
// Scratch buffers (__device__ globals; allocation-free rule)
// ---------------------------------------------------------------------------
__device__ __half X16[(size_t)MROWS * DMODEL];
__device__ __half WQKVT16[(size_t)QKVCOLS * DMODEL];  // rows: 0-4095 Q, 4096-5119 K, 5120-6143 V
__device__ __half WOT_H16[(size_t)DMODEL * DMODEL];
__device__ __half WOT_L16[(size_t)DMODEL * DMODEL];
__device__ __half Z16[(size_t)MROWS * DMODEL];
__device__ __half Q16[(size_t)MROWS * QCOLS];
__device__ __half K16[(size_t)MROWS * KVCOLS];
__device__ __half V16[(size_t)MROWS * KVCOLS];

// ---------------------------------------------------------------------------
// Helpers
// ---------------------------------------------------------------------------
__device__ __forceinline__ uint32_t smem_u32(const void* p) {
    uint32_t a;
    asm("{ .reg .u64 t; cvta.to.shared.u64 t, %1; cvt.u32.u64 %0, t; }" : "=r"(a) : "l"(p));
    return a;
}

__device__ __forceinline__ void cp16(uint32_t dst, const void* src) {
    asm volatile("cp.async.cg.shared.global [%0], [%1], 16;" :: "r"(dst), "l"(src));
}
#define CP_COMMIT() asm volatile("cp.async.commit_group;" ::: "memory")
template <int N>
__device__ __forceinline__ void cp_wait() {
    asm volatile("cp.async.wait_group %0;" :: "n"(N) : "memory");
}

#define LDSM4(r, addr)                                                        \
    asm volatile("ldmatrix.sync.aligned.m8n8.x4.shared.b16 {%0,%1,%2,%3}, [%4];" \
        : "=r"((r)[0]), "=r"((r)[1]), "=r"((r)[2]), "=r"((r)[3]) : "r"(addr))

#define LDSM4T(r, addr)                                                       \
    asm volatile("ldmatrix.sync.aligned.m8n8.x4.trans.shared.b16 {%0,%1,%2,%3}, [%4];" \
        : "=r"((r)[0]), "=r"((r)[1]), "=r"((r)[2]), "=r"((r)[3]) : "r"(addr))

#define MMAH(c, a, b0, b1)                                                    \
    asm volatile("mma.sync.aligned.m16n8k16.row.col.f32.f16.f16.f32 "         \
        "{%0,%1,%2,%3}, {%4,%5,%6,%7}, {%8,%9}, {%0,%1,%2,%3};"               \
        : "+f"((c)[0]), "+f"((c)[1]), "+f"((c)[2]), "+f"((c)[3])              \
        : "r"((a)[0]), "r"((a)[1]), "r"((a)[2]), "r"((a)[3]),                 \
          "r"(b0), "r"(b1))

__device__ __forceinline__ uint32_t packh2(float x, float y) {
    __half2 h = __floats2half2_rn(x, y);
    return *(uint32_t*)&h;
}

// swizzled byte offset within a 64B-row tile for (row, kseg[0..3])
__device__ __forceinline__ uint32_t swz_off(int row, int ks) {
    return (uint32_t)(row * 64 + (((ks ^ (row >> 1)) & 3) << 4));
}

// ---------------------------------------------------------------------------
// fp32 -> fp16 convert (elementwise)
// ---------------------------------------------------------------------------
__global__ __launch_bounds__(256) void xconvert(const float* __restrict__ src,
                                                __half* __restrict__ dst, int n) {
    int i = blockIdx.x * blockDim.x + threadIdx.x;
    if (i < n) dst[i] = __float2half(src[i]);
}

// Transpose + fp16 convert: W[K,N] fp32 -> T [N,K] fp16
__global__ __launch_bounds__(256) void transpose_convert(const float* __restrict__ W,
                                                         __half* __restrict__ T,
                                                         int K, int N) {
    __shared__ float t[32][33];
    int n0 = blockIdx.x * 32;
    int k0 = blockIdx.y * 32;
    int tx = threadIdx.x, ty = threadIdx.y;
    #pragma unroll
    for (int r = ty; r < 32; r += 8)
        t[r][tx] = W[(size_t)(k0 + r) * N + n0 + tx];
    __syncthreads();
    #pragma unroll
    for (int r = ty; r < 32; r += 8)
        T[(size_t)(n0 + r) * K + k0 + tx] = __float2half(t[tx][r]);
}

// Transpose + fp16 hi/lo split: W[K,N] fp32 -> T_hi/T_lo [N,K] fp16
__global__ __launch_bounds__(256) void transpose_split_f16(const float* __restrict__ W,
                                                           __half* __restrict__ Thi,
                                                           __half* __restrict__ Tlo,
                                                           int K, int N) {
    __shared__ float t[32][33];
    int n0 = blockIdx.x * 32;
    int k0 = blockIdx.y * 32;
    int tx = threadIdx.x, ty = threadIdx.y;
    #pragma unroll
    for (int r = ty; r < 32; r += 8)
        t[r][tx] = W[(size_t)(k0 + r) * N + n0 + tx];
    __syncthreads();
    #pragma unroll
    for (int r = ty; r < 32; r += 8) {
        float a = t[tx][r];
        __half h = __float2half(a);
        size_t o = (size_t)(n0 + r) * K + k0 + tx;
        Thi[o] = h;
        Tlo[o] = __float2half(a - __half2float(h));
    }
}

// ---------------------------------------------------------------------------
// Merged QKV single-pass fp16 GEMM, fused RoPE/scale/head-major epilogue.
// C[M,6144] = X[M,K] @ Wqkv[6144,K]^T
//   cols [0,4096): Q  (rope, *qs) -> q16 [b,32,t,128]
//   cols [4096,5120): K (rope)    -> k16 [b,8,t,128]
//   cols [5120,6144): V           -> v16 [b,8,t,128]
// CTA 128x256, BK=32, NST=6 stages, 8 warps.
// ---------------------------------------------------------------------------
#define BM 128
#define BN 256
#define BK 32
#define F_AT_B (BM * BK * 2)              // 8192
#define F_BT_B (BN * BK * 2)              // 16384
#define F_STAGE (F_AT_B + F_BT_B)         // 24576
#define F_NST 6
#define GEMM_F16_SMEM (F_NST * F_STAGE)   // 147456

__global__ __launch_bounds__(256, 1)
void gemm_qkv(const __half* __restrict__ A, const __half* __restrict__ B,
              const float* __restrict__ cosb, const float* __restrict__ sinb,
              __half* __restrict__ qo, __half* __restrict__ ko,
              __half* __restrict__ vo, float qs) {
    extern __shared__ char smem[];
    const uint32_t sb = smem_u32(smem);
    const int tid = threadIdx.x;
    const int wid = tid >> 5;
    const int lane = tid & 31;
    const int wm = wid >> 2;
    const int wn = wid & 3;
    const int m0 = blockIdx.y * BM;
    const int n0 = blockIdx.x * BN;
    const int K = DMODEL;
    const int TOT = K / BK;

    float acc[4][8][4];
    #pragma unroll
    for (int i = 0; i < 4; i++)
        #pragma unroll
        for (int j = 0; j < 8; j++)
            #pragma unroll
            for (int r = 0; r < 4; r++) acc[i][j][r] = 0.0f;

    auto load_chunk = [&](int c, int s) {
        const __half* as = A + (size_t)m0 * K + c * BK;
        const __half* bs = B + (size_t)n0 * K + c * BK;
        uint32_t base = sb + s * F_STAGE;
        #pragma unroll
        for (int t = 0; t < 6; t++) {
            int idx = tid + t * 256;
            if (idx < 512) {
                int row = idx >> 2, ks = idx & 3;
                cp16(base + swz_off(row, ks), as + (size_t)row * K + ks * 8);
            } else {
                int j = idx - 512;
                int row = j >> 2, ks = j & 3;
                cp16(base + F_AT_B + swz_off(row, ks), bs + (size_t)row * K + ks * 8);
            }
        }
    };

    #pragma unroll
    for (int s = 0; s < F_NST - 1; s++) {
        if (s < TOT) load_chunk(s, s);
        CP_COMMIT();
    }

    const int r15 = lane & 15;
    const int hsel = lane >> 4;

    for (int c = 0; c < TOT; c++) {
        const int s = c % F_NST;
        cp_wait<F_NST - 2>();
        __syncthreads();

        {
            int nc = c + F_NST - 1;
            if (nc < TOT) load_chunk(nc, nc % F_NST);
            CP_COMMIT();
        }

        const uint32_t ab = sb + s * F_STAGE;
        const uint32_t bb = ab + F_AT_B;

        #pragma unroll
        for (int ks2 = 0; ks2 < 2; ks2++) {
            const int kseg = ks2 * 2 + hsel;
            uint32_t aF[4][4], bF[4][4];
            #pragma unroll
            for (int i = 0; i < 4; i++)
                LDSM4(aF[i], ab + swz_off(wm * 64 + i * 16 + r15, kseg));
            #pragma unroll
            for (int j = 0; j < 4; j++)
                LDSM4(bF[j], bb + swz_off(wn * 64 + j * 16 + r15, kseg));
            #pragma unroll
            for (int i = 0; i < 4; i++)
                #pragma unroll
                for (int j = 0; j < 4; j++) {
                    MMAH(acc[i][2 * j],     aF[i], bF[j][0], bF[j][2]);
                    MMAH(acc[i][2 * j + 1], aF[i], bF[j][1], bF[j][3]);
                }
        }
    }

    // Fused epilogue: route to Q/K/V, RoPE (+scale), head-major fp16 store
    const int quad = lane >> 2;
    const int tq = lane & 3;
    #pragma unroll
    for (int i = 0; i < 4; i++) {
        int r0 = m0 + wm * 64 + i * 16 + quad;
        int b0 = r0 >> 11;
        int t0 = r0 & (SEQ - 1);
        #pragma unroll
        for (int j = 0; j < 8; j++) {
            int c = n0 + wn * 64 + j * 8 + tq * 2;
            __half* dst;
            int H, cc;
            bool dorope;
            float scl;
            if (c < QCOLS)            { dst = qo; H = NHEAD;   cc = c;          dorope = true;  scl = qs; }
            else if (c < QCOLS + 1024){ dst = ko; H = NKVHEAD; cc = c - QCOLS;  dorope = true;  scl = 1.0f; }
            else                      { dst = vo; H = NKVHEAD; cc = c - QCOLS - 1024; dorope = false; scl = 1.0f; }
            int h = cc >> 7, d = cc & 127, d2 = d >> 1;
            float f0 = acc[i][j][0], f1 = acc[i][j][1];
            float f2 = acc[i][j][2], f3 = acc[i][j][3];
            if (dorope) {
                float c0 = cosb[t0 * 64 + d2], s0 = sinb[t0 * 64 + d2];
                float c1 = cosb[(t0 + 8) * 64 + d2], s1 = sinb[(t0 + 8) * 64 + d2];
                float a0 = (f0 * c0 - f1 * s0) * scl, a1 = (f0 * s0 + f1 * c0) * scl;
                float a2 = (f2 * c1 - f3 * s1) * scl, a3 = (f2 * s1 + f3 * c1) * scl;
                f0 = a0; f1 = a1; f2 = a2; f3 = a3;
            }
            size_t o0 = (((size_t)b0 * H + h) * SEQ + t0) * DHEAD + d;
            *(__half2*)(dst + o0) = __floats2half2_rn(f0, f1);
            *(__half2*)(dst + o0 + (size_t)8 * DHEAD) = __floats2half2_rn(f2, f3);
        }
    }
}

// ---------------------------------------------------------------------------
// WO projection: 2-pass fp16 GEMM  out[M,N] = Z @ (Wh + Wl)^T, fp32 out.
// CTA 128x256, BK=32, NST=4 stages (40KB each), 8 warps.
// ---------------------------------------------------------------------------
#define W_STAGE (F_AT_B + 2 * F_BT_B)     // 40960
#define W_NST 4
#define GEMM_WO_SMEM (W_NST * W_STAGE)    // 163840

__global__ __launch_bounds__(256, 1)
void wo_gemm(const __half* __restrict__ A, const __half* __restrict__ Bh,
             const __half* __restrict__ Bl, float* __restrict__ C,
             int N, int K) {
    extern __shared__ char smem[];
    const uint32_t sb = smem_u32(smem);
    const int tid = threadIdx.x;
    const int wid = tid >> 5;
    const int lane = tid & 31;
    const int wm = wid >> 2;
    const int wn = wid & 3;
    const int m0 = blockIdx.y * BM;
    const int n0 = blockIdx.x * BN;
    const int TOT = K / BK;

    float acc[4][8][4];
    #pragma unroll
    for (int i = 0; i < 4; i++)
        #pragma unroll
        for (int j = 0; j < 8; j++)
            #pragma unroll
            for (int r = 0; r < 4; r++) acc[i][j][r] = 0.0f;

    auto load_chunk = [&](int c, int s) {
        const __half* as = A + (size_t)m0 * K + c * BK;
        const __half* bh = Bh + (size_t)n0 * K + c * BK;
        const __half* bl = Bl + (size_t)n0 * K + c * BK;
        uint32_t base = sb + s * W_STAGE;
        #pragma unroll
        for (int t = 0; t < 10; t++) {
            int idx = tid + t * 256;      // 512 A + 1024 Bh + 1024 Bl
            if (idx < 512) {
                int row = idx >> 2, ks = idx & 3;
                cp16(base + swz_off(row, ks), as + (size_t)row * K + ks * 8);
            } else if (idx < 1536) {
                int j = idx - 512;
                int row = j >> 2, ks = j & 3;
                cp16(base + F_AT_B + swz_off(row, ks), bh + (size_t)row * K + ks * 8);
            } else {
                int j = idx - 1536;
                int row = j >> 2, ks = j & 3;
                cp16(base + F_AT_B + F_BT_B + swz_off(row, ks), bl + (size_t)row * K + ks * 8);
            }
        }
    };

    #pragma unroll
    for (int s = 0; s < W_NST - 1; s++) {
        if (s < TOT) load_chunk(s, s);
        CP_COMMIT();
    }

    const int r15 = lane & 15;
    const int hsel = lane >> 4;

    for (int c = 0; c < TOT; c++) {
        const int s = c & (W_NST - 1);
        cp_wait<W_NST - 2>();
        __syncthreads();

        {
            int nc = c + W_NST - 1;
            if (nc < TOT) load_chunk(nc, nc & (W_NST - 1));
            CP_COMMIT();
        }

        const uint32_t ab = sb + s * W_STAGE;
        const uint32_t bhb = ab + F_AT_B;
        const uint32_t blb = bhb + F_BT_B;

        #pragma unroll
        for (int ks2 = 0; ks2 < 2; ks2++) {
            const int kseg = ks2 * 2 + hsel;
            uint32_t aF[4][4], bH[4][4], bL[4][4];
            #pragma unroll
            for (int i = 0; i < 4; i++)
                LDSM4(aF[i], ab + swz_off(wm * 64 + i * 16 + r15, kseg));
            #pragma unroll
            for (int j = 0; j < 4; j++) {
                uint32_t so = swz_off(wn * 64 + j * 16 + r15, kseg);
                LDSM4(bH[j], bhb + so);
                LDSM4(bL[j], blb + so);
            }
            #pragma unroll
            for (int i = 0; i < 4; i++)
                #pragma unroll
                for (int j = 0; j < 4; j++) {
                    MMAH(acc[i][2 * j],     aF[i], bH[j][0], bH[j][2]);
                    MMAH(acc[i][2 * j + 1], aF[i], bH[j][1], bH[j][3]);
                }
            #pragma unroll
            for (int i = 0; i < 4; i++)
                #pragma unroll
                for (int j = 0; j < 4; j++) {
                    MMAH(acc[i][2 * j],     aF[i], bL[j][0], bL[j][2]);
                    MMAH(acc[i][2 * j + 1], aF[i], bL[j][1], bL[j][3]);
                }
        }
    }

    const int quad = lane >> 2;
    const int tq = lane & 3;
    #pragma unroll
    for (int i = 0; i < 4; i++) {
        int row0 = m0 + wm * 64 + i * 16 + quad;
        #pragma unroll
        for (int j = 0; j < 8; j++) {
            int col = n0 + wn * 64 + j * 8 + tq * 2;
            *(float2*)(C + (size_t)row0 * N + col) =
                make_float2(acc[i][j][0], acc[i][j][1]);
            *(float2*)(C + (size_t)(row0 + 8) * N + col) =
                make_float2(acc[i][j][2], acc[i][j][3]);
        }
    }
}

// ----------------------------------------------------------------------------
// HMMA fp16 flash attention; writes Z as single fp16.
// ----------------------------------------------------------------------------
#define QS_BYTES (128 * 128 * 2)
#define KV_BYTES (64 * 128 * 2)
#define FLASH_SMEM (QS_BYTES + 2 * (2 * KV_BYTES))

__global__ __launch_bounds__(256, 1)
void flash_hmma(const __half* __restrict__ Qg, const __half* __restrict__ Kg,
                const __half* __restrict__ Vg, __half* __restrict__ Z) {
    extern __shared__ char smem[];
    const uint32_t sb = smem_u32(smem);
    const int tid = threadIdx.x;
    const int wid = tid >> 5;
    const int lane = tid & 31;
    const int quad = lane >> 2, tq = lane & 3;
    const int r15 = lane & 15, hsel = lane >> 4;
    const int qt = blockIdx.x;
    const int q0 = qt * 128;
    const int bh = blockIdx.y;
    const int b = bh >> 5, h = bh & 31, kvh = h >> 2;
    const __half* qsrc = Qg + ((size_t)bh * SEQ + q0) * DHEAD;
    const __half* ksrc0 = Kg + ((size_t)(b * NKVHEAD + kvh)) * SEQ * DHEAD;
    const __half* vsrc0 = Vg + ((size_t)(b * NKVHEAD + kvh)) * SEQ * DHEAD;
    const int nkt = 2 * (qt + 1);

    #pragma unroll
    for (int t = 0; t < 8; t++) {
        int j = tid + t * 256;
        int row = j >> 4, dc = (j >> 2) & 3, ks = j & 3;
        cp16(sb + dc * 8192 + swz_off(row, ks), qsrc + (size_t)row * DHEAD + dc * 32 + ks * 8);
    }
    CP_COMMIT();

    auto load_kv = [&](int t, int s) {
        uint32_t kb = sb + QS_BYTES + s * (2 * KV_BYTES);
        uint32_t vb = kb + KV_BYTES;
        const __half* ks_ = ksrc0 + (size_t)t * 64 * DHEAD;
        const __half* vs_ = vsrc0 + (size_t)t * 64 * DHEAD;
        #pragma unroll
        for (int u = 0; u < 8; u++) {
            int j = tid + u * 256;
            bool isv = j >= 1024;
            int jj = j & 1023;
            int row = jj >> 4, dc = (jj >> 2) & 3, ks = jj & 3;
            cp16((isv ? vb : kb) + dc * 4096 + swz_off(row, ks),
                 (isv ? vs_ : ks_) + (size_t)row * DHEAD + dc * 32 + ks * 8);
        }
    };

    load_kv(0, 0); CP_COMMIT();
    cp_wait<1>();
    __syncthreads();

    uint32_t qF[8][4];
    #pragma unroll
    for (int kc = 0; kc < 8; kc++) {
        int dc = kc >> 1;
        LDSM4(qF[kc], sb + dc * 8192 + swz_off(wid * 16 + r15, (kc & 1) * 2 + hsel));
    }

    if (nkt > 1) load_kv(1, 1);
    CP_COMMIT();

    float o[16][4];
    #pragma unroll
    for (int i = 0; i < 16; i++)
        #pragma unroll
        for (int r = 0; r < 4; r++) o[i][r] = 0.0f;
    float m0v = -1e30f, m1v = -1e30f, l0v = 0.0f, l1v = 0.0f;

    const int row_g0 = q0 + wid * 16 + quad;

    for (int t = 0; t < nkt; t++) {
        cp_wait<1>();
        __syncthreads();
        const uint32_t kb = sb + QS_BYTES + (t & 1) * (2 * KV_BYTES);
        const uint32_t vb = kb + KV_BYTES;

        float s[8][4];
        #pragma unroll
        for (int j = 0; j < 8; j++)
            #pragma unroll
            for (int r = 0; r < 4; r++) s[j][r] = 0.0f;

        #pragma unroll
        for (int kc = 0; kc < 8; kc++) {
            int dc = kc >> 1;
            #pragma unroll
            for (int j = 0; j < 4; j++) {
                uint32_t kf[4];
                LDSM4(kf, kb + dc * 4096 + swz_off(j * 16 + r15, (kc & 1) * 2 + hsel));
                MMAH(s[2 * j],     qF[kc], kf[0], kf[2]);
                MMAH(s[2 * j + 1], qF[kc], kf[1], kf[3]);
            }
        }

        if (t >= nkt - 2) {
            #pragma unroll
            for (int j = 0; j < 8; j++) {
                int col = t * 64 + j * 8 + tq * 2;
                if (col     > row_g0)     s[j][0] = -1e30f;
                if (col + 1 > row_g0)     s[j][1] = -1e30f;
                if (col     > row_g0 + 8) s[j][2] = -1e30f;
                if (col + 1 > row_g0 + 8) s[j][3] = -1e30f;
            }
        }

        float rm0 = -1e30f, rm1 = -1e30f;
        #pragma unroll
        for (int j = 0; j < 8; j++) {
            rm0 = fmaxf(rm0, fmaxf(s[j][0], s[j][1]));
            rm1 = fmaxf(rm1, fmaxf(s[j][2], s[j][3]));
        }
        rm0 = fmaxf(rm0, __shfl_xor_sync(0xffffffffu, rm0, 1));
        rm0 = fmaxf(rm0, __shfl_xor_sync(0xffffffffu, rm0, 2));
        rm1 = fmaxf(rm1, __shfl_xor_sync(0xffffffffu, rm1, 1));
        rm1 = fmaxf(rm1, __shfl_xor_sync(0xffffffffu, rm1, 2));

        float mn0 = fmaxf(m0v, rm0), mn1 = fmaxf(m1v, rm1);
        float f0 = exp2f(m0v - mn0), f1 = exp2f(m1v - mn1);

        float rs0 = 0.0f, rs1 = 0.0f;
        uint32_t aP[4][4];
        #pragma unroll
        for (int kk = 0; kk < 4; kk++) {
            float p00 = exp2f(s[2 * kk][0] - mn0);
            float p01 = exp2f(s[2 * kk][1] - mn0);
            float p02 = exp2f(s[2 * kk][2] - mn1);
            float p03 = exp2f(s[2 * kk][3] - mn1);
            float p10 = exp2f(s[2 * kk + 1][0] - mn0);
            float p11 = exp2f(s[2 * kk + 1][1] - mn0);
            float p12 = exp2f(s[2 * kk + 1][2] - mn1);
            float p13 = exp2f(s[2 * kk + 1][3] - mn1);
            rs0 += p00 + p01 + p10 + p11;
            rs1 += p02 + p03 + p12 + p13;
            aP[kk][0] = packh2(p00, p01);
            aP[kk][1] = packh2(p02, p03);
            aP[kk][2] = packh2(p10, p11);
            aP[kk][3] = packh2(p12, p13);
        }
        rs0 += __shfl_xor_sync(0xffffffffu, rs0, 1);
        rs0 += __shfl_xor_sync(0xffffffffu, rs0, 2);
        rs1 += __shfl_xor_sync(0xffffffffu, rs1, 1);
        rs1 += __shfl_xor_sync(0xffffffffu, rs1, 2);

        l0v = l0v * f0 + rs0;
        l1v = l1v * f1 + rs1;
        m0v = mn0; m1v = mn1;

        #pragma unroll
        for (int i = 0; i < 16; i++) {
            o[i][0] *= f0; o[i][1] *= f0;
            o[i][2] *= f1; o[i][3] *= f1;
        }

        #pragma unroll
        for (int djp = 0; djp < 8; djp++) {
            int dj = djp * 2 + hsel;
            int dc = dj >> 2, ks = dj & 3;
            #pragma unroll
            for (int kk = 0; kk < 4; kk++) {
                uint32_t vr[4];
                LDSM4T(vr, vb + dc * 4096 + swz_off(kk * 16 + r15, ks));
                MMAH(o[djp * 2],     aP[kk], vr[0], vr[1]);
                MMAH(o[djp * 2 + 1], aP[kk], vr[2], vr[3]);
            }
        }

        __syncthreads();
        if (t + 2 < nkt) load_kv(t + 2, t & 1);
        CP_COMMIT();
    }

    float inv0 = 1.0f / l0v, inv1 = 1.0f / l1v;
    size_t base0 = (size_t)(b * SEQ + row_g0) * DMODEL + h * DHEAD;
    size_t base1 = base0 + (size_t)8 * DMODEL;
    #pragma unroll
    for (int djt = 0; djt < 16; djt++) {
        int col = djt * 8 + tq * 2;
        *(__half2*)(Z + base0 + col) = __floats2half2_rn(o[djt][0] * inv0, o[djt][1] * inv0);
        *(__half2*)(Z + base1 + col) = __floats2half2_rn(o[djt][2] * inv1, o[djt][3] * inv1);
    }
}

// ----------------------------------------------------------------------------
// Host launcher
// ----------------------------------------------------------------------------
extern "C" void kernel_launch(void* const* d_in, const int* in_sizes, int n_in,
                              void* d_out, int out_size) {
    const float* x    = (const float*)d_in[0];
    const float* fcos = (const float*)d_in[1];
    const float* fsin = (const float*)d_in[2];
    const float* wq   = (const float*)d_in[3];
    const float* wk   = (const float*)d_in[4];
    const float* wv   = (const float*)d_in[5];
    const float* wo   = (const float*)d_in[6];
    float* out = (float*)d_out;

    __half *x16, *wqkv, *woh, *wol, *z16, *q16, *k16, *v16;
    cudaGetSymbolAddress((void**)&x16, X16);
    cudaGetSymbolAddress((void**)&wqkv, WQKVT16);
    cudaGetSymbolAddress((void**)&woh, WOT_H16);
    cudaGetSymbolAddress((void**)&wol, WOT_L16);
    cudaGetSymbolAddress((void**)&z16, Z16);
    cudaGetSymbolAddress((void**)&q16, Q16);
    cudaGetSymbolAddress((void**)&k16, K16);
    cudaGetSymbolAddress((void**)&v16, V16);

    cudaFuncSetAttribute(gemm_qkv, cudaFuncAttributeMaxDynamicSharedMemorySize, GEMM_F16_SMEM);
    cudaFuncSetAttribute(wo_gemm, cudaFuncAttributeMaxDynamicSharedMemorySize, GEMM_WO_SMEM);
    cudaFuncSetAttribute(flash_hmma, cudaFuncAttributeMaxDynamicSharedMemorySize, FLASH_SMEM);

    // Input conversions
    {
        int n = MROWS * DMODEL;
        xconvert<<<(n + 255) / 256, 256>>>(x, x16, n);
    }
    transpose_convert<<<dim3(QCOLS / 32, DMODEL / 32), dim3(32, 8)>>>(wq, wqkv, DMODEL, QCOLS);
    transpose_convert<<<dim3(KVCOLS / 32, DMODEL / 32), dim3(32, 8)>>>(wk, wqkv + (size_t)QCOLS * DMODEL, DMODEL, KVCOLS);
    transpose_convert<<<dim3(KVCOLS / 32, DMODEL / 32), dim3(32, 8)>>>(wv, wqkv + (size_t)(QCOLS + KVCOLS) * DMODEL, DMODEL, KVCOLS);
    transpose_split_f16<<<dim3(DMODEL / 32, DMODEL / 32), dim3(32, 8)>>>(wo, woh, wol, DMODEL, DMODEL);

    // Merged QKV projection (single-pass fp16, fused RoPE epilogue)
    const float qs = 0.08838834764831845f * 1.4426950408889634f;   // scale * log2(e)
    gemm_qkv<<<dim3(QKVCOLS / BN, MROWS / BM), 256, GEMM_F16_SMEM>>>(
        x16, wqkv, fcos, fsin, q16, k16, v16, qs);

    // Flash attention (fp16 HMMA) -> Z16 fp16
    flash_hmma<<<dim3(SEQ / 128, BATCH * NHEAD), 256, FLASH_SMEM>>>(q16, k16, v16, z16);

    // Output projection: 2-pass fp16 (Z * (Wh + Wl))
    wo_gemm<<<dim3(DMODEL / BN, MROWS / BM), 256, GEMM_WO_SMEM>>>(z16, woh, wol, out, DMODEL, DMODEL);
}

// round 8
// speedup vs baseline: 7.8102x; 1.2222x over previous
#include <cuda_runtime.h>
#include <cuda_bf16.h>
#include <cuda_fp16.h>
#include <cstdint>
#include <math.h>

// Problem constants
#define BATCH 2
#define SEQ 2048
#define DMODEL 4096
#define NHEAD 32
#define NKVHEAD 8
#define DHEAD 128
#define MROWS (BATCH * SEQ)            // 4096
#define QCOLS (NHEAD * DHEAD)          // 4096
#define KVCOLS (NKVHEAD * DHEAD)       // 1024
#define QKVCOLS (QCOLS + 2 * KVCOLS)   // 6144

// ---------------------------------------------------------------------------
// Scratch buffers (__device__ globals; allocation-free rule)
// ---------------------------------------------------------------------------
__device__ __half X16[(size_t)MROWS * DMODEL];
__device__ __half WQKVT16[(size_t)QKVCOLS * DMODEL];  // rows: 0-4095 Q, 4096-5119 K, 5120-6143 V
__device__ __half WOT16[(size_t)DMODEL * DMODEL];
__device__ __half Z16[(size_t)MROWS * DMODEL];
__device__ __half Q16[(size_t)MROWS * QCOLS];
__device__ __half K16[(size_t)MROWS * KVCOLS];
__device__ __half V16[(size_t)MROWS * KVCOLS];

// ---------------------------------------------------------------------------
// Helpers
// ---------------------------------------------------------------------------
__device__ __forceinline__ uint32_t smem_u32(const void* p) {
    uint32_t a;
    asm("{ .reg .u64 t; cvta.to.shared.u64 t, %1; cvt.u32.u64 %0, t; }" : "=r"(a) : "l"(p));
    return a;
}

__device__ __forceinline__ void cp16(uint32_t dst, const void* src) {
    asm volatile("cp.async.cg.shared.global [%0], [%1], 16;" :: "r"(dst), "l"(src));
}
#define CP_COMMIT() asm volatile("cp.async.commit_group;" ::: "memory")
template <int N>
__device__ __forceinline__ void cp_wait() {
    asm volatile("cp.async.wait_group %0;" :: "n"(N) : "memory");
}

#define LDSM4(r, addr)                                                        \
    asm volatile("ldmatrix.sync.aligned.m8n8.x4.shared.b16 {%0,%1,%2,%3}, [%4];" \
        : "=r"((r)[0]), "=r"((r)[1]), "=r"((r)[2]), "=r"((r)[3]) : "r"(addr))

#define LDSM4T(r, addr)                                                       \
    asm volatile("ldmatrix.sync.aligned.m8n8.x4.trans.shared.b16 {%0,%1,%2,%3}, [%4];" \
        : "=r"((r)[0]), "=r"((r)[1]), "=r"((r)[2]), "=r"((r)[3]) : "r"(addr))

#define MMAH(c, a, b0, b1)                                                    \
    asm volatile("mma.sync.aligned.m16n8k16.row.col.f32.f16.f16.f32 "         \
        "{%0,%1,%2,%3}, {%4,%5,%6,%7}, {%8,%9}, {%0,%1,%2,%3};"               \
        : "+f"((c)[0]), "+f"((c)[1]), "+f"((c)[2]), "+f"((c)[3])              \
        : "r"((a)[0]), "r"((a)[1]), "r"((a)[2]), "r"((a)[3]),                 \
          "r"(b0), "r"(b1))

__device__ __forceinline__ uint32_t packh2(float x, float y) {
    __half2 h = __floats2half2_rn(x, y);
    return *(uint32_t*)&h;
}

// swizzled byte offset within a 64B-row tile for (row, kseg[0..3])
__device__ __forceinline__ uint32_t swz_off(int row, int ks) {
    return (uint32_t)(row * 64 + (((ks ^ (row >> 1)) & 3) << 4));
}

// ---------------------------------------------------------------------------
// fp32 -> fp16 convert (elementwise)
// ---------------------------------------------------------------------------
__global__ __launch_bounds__(256) void xconvert(const float* __restrict__ src,
                                                __half* __restrict__ dst, int n) {
    int i = blockIdx.x * blockDim.x + threadIdx.x;
    if (i < n) dst[i] = __float2half(src[i]);
}

// Transpose + fp16 convert: W[K,N] fp32 -> T [N,K] fp16
__global__ __launch_bounds__(256) void transpose_convert(const float* __restrict__ W,
                                                         __half* __restrict__ T,
                                                         int K, int N) {
    __shared__ float t[32][33];
    int n0 = blockIdx.x * 32;
    int k0 = blockIdx.y * 32;
    int tx = threadIdx.x, ty = threadIdx.y;
    #pragma unroll
    for (int r = ty; r < 32; r += 8)
        t[r][tx] = W[(size_t)(k0 + r) * N + n0 + tx];
    __syncthreads();
    #pragma unroll
    for (int r = ty; r < 32; r += 8)
        T[(size_t)(n0 + r) * K + k0 + tx] = __float2half(t[tx][r]);
}

// ---------------------------------------------------------------------------
// Merged QKV single-pass fp16 GEMM, fused RoPE/scale/head-major epilogue.
// C[M,6144] = X[M,K] @ Wqkv[6144,K]^T
//   cols [0,4096): Q  (rope, *qs) -> q16 [b,32,t,128]
//   cols [4096,5120): K (rope)    -> k16 [b,8,t,128]
//   cols [5120,6144): V           -> v16 [b,8,t,128]
// CTA 128x256, BK=32, NST=6 stages, 8 warps.
// ---------------------------------------------------------------------------
#define BM 128
#define BN 256
#define BK 32
#define F_AT_B (BM * BK * 2)              // 8192
#define F_BT_B (BN * BK * 2)              // 16384
#define F_STAGE (F_AT_B + F_BT_B)         // 24576
#define F_NST 6
#define GEMM_F16_SMEM (F_NST * F_STAGE)   // 147456

__global__ __launch_bounds__(256, 1)
void gemm_qkv(const __half* __restrict__ A, const __half* __restrict__ B,
              const float* __restrict__ cosb, const float* __restrict__ sinb,
              __half* __restrict__ qo, __half* __restrict__ ko,
              __half* __restrict__ vo, float qs) {
    extern __shared__ char smem[];
    const uint32_t sb = smem_u32(smem);
    const int tid = threadIdx.x;
    const int wid = tid >> 5;
    const int lane = tid & 31;
    const int wm = wid >> 2;
    const int wn = wid & 3;
    const int m0 = blockIdx.y * BM;
    const int n0 = blockIdx.x * BN;
    const int K = DMODEL;
    const int TOT = K / BK;

    float acc[4][8][4];
    #pragma unroll
    for (int i = 0; i < 4; i++)
        #pragma unroll
        for (int j = 0; j < 8; j++)
            #pragma unroll
            for (int r = 0; r < 4; r++) acc[i][j][r] = 0.0f;

    auto load_chunk = [&](int c, int s) {
        const __half* as = A + (size_t)m0 * K + c * BK;
        const __half* bs = B + (size_t)n0 * K + c * BK;
        uint32_t base = sb + s * F_STAGE;
        #pragma unroll
        for (int t = 0; t < 6; t++) {
            int idx = tid + t * 256;
            if (idx < 512) {
                int row = idx >> 2, ks = idx & 3;
                cp16(base + swz_off(row, ks), as + (size_t)row * K + ks * 8);
            } else {
                int j = idx - 512;
                int row = j >> 2, ks = j & 3;
                cp16(base + F_AT_B + swz_off(row, ks), bs + (size_t)row * K + ks * 8);
            }
        }
    };

    #pragma unroll
    for (int s = 0; s < F_NST - 1; s++) {
        if (s < TOT) load_chunk(s, s);
        CP_COMMIT();
    }

    const int r15 = lane & 15;
    const int hsel = lane >> 4;

    for (int c = 0; c < TOT; c++) {
        const int s = c % F_NST;
        cp_wait<F_NST - 2>();
        __syncthreads();

        {
            int nc = c + F_NST - 1;
            if (nc < TOT) load_chunk(nc, nc % F_NST);
            CP_COMMIT();
        }

        const uint32_t ab = sb + s * F_STAGE;
        const uint32_t bb = ab + F_AT_B;

        #pragma unroll
        for (int ks2 = 0; ks2 < 2; ks2++) {
            const int kseg = ks2 * 2 + hsel;
            uint32_t aF[4][4], bF[4][4];
            #pragma unroll
            for (int i = 0; i < 4; i++)
                LDSM4(aF[i], ab + swz_off(wm * 64 + i * 16 + r15, kseg));
            #pragma unroll
            for (int j = 0; j < 4; j++)
                LDSM4(bF[j], bb + swz_off(wn * 64 + j * 16 + r15, kseg));
            #pragma unroll
            for (int i = 0; i < 4; i++)
                #pragma unroll
                for (int j = 0; j < 4; j++) {
                    MMAH(acc[i][2 * j],     aF[i], bF[j][0], bF[j][2]);
                    MMAH(acc[i][2 * j + 1], aF[i], bF[j][1], bF[j][3]);
                }
        }
    }

    // Fused epilogue: route to Q/K/V, RoPE (+scale), head-major fp16 store
    const int quad = lane >> 2;
    const int tq = lane & 3;
    #pragma unroll
    for (int i = 0; i < 4; i++) {
        int r0 = m0 + wm * 64 + i * 16 + quad;
        int b0 = r0 >> 11;
        int t0 = r0 & (SEQ - 1);
        #pragma unroll
        for (int j = 0; j < 8; j++) {
            int c = n0 + wn * 64 + j * 8 + tq * 2;
            __half* dst;
            int H, cc;
            bool dorope;
            float scl;
            if (c < QCOLS)            { dst = qo; H = NHEAD;   cc = c;          dorope = true;  scl = qs; }
            else if (c < QCOLS + 1024){ dst = ko; H = NKVHEAD; cc = c - QCOLS;  dorope = true;  scl = 1.0f; }
            else                      { dst = vo; H = NKVHEAD; cc = c - QCOLS - 1024; dorope = false; scl = 1.0f; }
            int h = cc >> 7, d = cc & 127, d2 = d >> 1;
            float f0 = acc[i][j][0], f1 = acc[i][j][1];
            float f2 = acc[i][j][2], f3 = acc[i][j][3];
            if (dorope) {
                float c0 = cosb[t0 * 64 + d2], s0 = sinb[t0 * 64 + d2];
                float c1 = cosb[(t0 + 8) * 64 + d2], s1 = sinb[(t0 + 8) * 64 + d2];
                float a0 = (f0 * c0 - f1 * s0) * scl, a1 = (f0 * s0 + f1 * c0) * scl;
                float a2 = (f2 * c1 - f3 * s1) * scl, a3 = (f2 * s1 + f3 * c1) * scl;
                f0 = a0; f1 = a1; f2 = a2; f3 = a3;
            }
            size_t o0 = (((size_t)b0 * H + h) * SEQ + t0) * DHEAD + d;
            *(__half2*)(dst + o0) = __floats2half2_rn(f0, f1);
            *(__half2*)(dst + o0 + (size_t)8 * DHEAD) = __floats2half2_rn(f2, f3);
        }
    }
}

// ---------------------------------------------------------------------------
// WO projection: single-pass fp16 GEMM  out[M,N] = Z @ W^T, fp32 out.
// CTA 128x256, BK=32, NST=6 stages, 8 warps.
// ---------------------------------------------------------------------------
__global__ __launch_bounds__(256, 1)
void wo_gemm(const __half* __restrict__ A, const __half* __restrict__ B,
             float* __restrict__ C, int N, int K) {
    extern __shared__ char smem[];
    const uint32_t sb = smem_u32(smem);
    const int tid = threadIdx.x;
    const int wid = tid >> 5;
    const int lane = tid & 31;
    const int wm = wid >> 2;
    const int wn = wid & 3;
    const int m0 = blockIdx.y * BM;
    const int n0 = blockIdx.x * BN;
    const int TOT = K / BK;

    float acc[4][8][4];
    #pragma unroll
    for (int i = 0; i < 4; i++)
        #pragma unroll
        for (int j = 0; j < 8; j++)
            #pragma unroll
            for (int r = 0; r < 4; r++) acc[i][j][r] = 0.0f;

    auto load_chunk = [&](int c, int s) {
        const __half* as = A + (size_t)m0 * K + c * BK;
        const __half* bs = B + (size_t)n0 * K + c * BK;
        uint32_t base = sb + s * F_STAGE;
        #pragma unroll
        for (int t = 0; t < 6; t++) {
            int idx = tid + t * 256;
            if (idx < 512) {
                int row = idx >> 2, ks = idx & 3;
                cp16(base + swz_off(row, ks), as + (size_t)row * K + ks * 8);
            } else {
                int j = idx - 512;
                int row = j >> 2, ks = j & 3;
                cp16(base + F_AT_B + swz_off(row, ks), bs + (size_t)row * K + ks * 8);
            }
        }
    };

    #pragma unroll
    for (int s = 0; s < F_NST - 1; s++) {
        if (s < TOT) load_chunk(s, s);
        CP_COMMIT();
    }

    const int r15 = lane & 15;
    const int hsel = lane >> 4;

    for (int c = 0; c < TOT; c++) {
        const int s = c % F_NST;
        cp_wait<F_NST - 2>();
        __syncthreads();

        {
            int nc = c + F_NST - 1;
            if (nc < TOT) load_chunk(nc, nc % F_NST);
            CP_COMMIT();
        }

        const uint32_t ab = sb + s * F_STAGE;
        const uint32_t bb = ab + F_AT_B;

        #pragma unroll
        for (int ks2 = 0; ks2 < 2; ks2++) {
            const int kseg = ks2 * 2 + hsel;
            uint32_t aF[4][4], bF[4][4];
            #pragma unroll
            for (int i = 0; i < 4; i++)
                LDSM4(aF[i], ab + swz_off(wm * 64 + i * 16 + r15, kseg));
            #pragma unroll
            for (int j = 0; j < 4; j++)
                LDSM4(bF[j], bb + swz_off(wn * 64 + j * 16 + r15, kseg));
            #pragma unroll
            for (int i = 0; i < 4; i++)
                #pragma unroll
                for (int j = 0; j < 4; j++) {
                    MMAH(acc[i][2 * j],     aF[i], bF[j][0], bF[j][2]);
                    MMAH(acc[i][2 * j + 1], aF[i], bF[j][1], bF[j][3]);
                }
        }
    }

    const int quad = lane >> 2;
    const int tq = lane & 3;
    #pragma unroll
    for (int i = 0; i < 4; i++) {
        int row0 = m0 + wm * 64 + i * 16 + quad;
        #pragma unroll
        for (int j = 0; j < 8; j++) {
            int col = n0 + wn * 64 + j * 8 + tq * 2;
            *(float2*)(C + (size_t)row0 * N + col) =
                make_float2(acc[i][j][0], acc[i][j][1]);
            *(float2*)(C + (size_t)(row0 + 8) * N + col) =
                make_float2(acc[i][j][2], acc[i][j][3]);
        }
    }
}

// ----------------------------------------------------------------------------
// HMMA fp16 flash attention; writes Z as fp16. Heavy tiles scheduled first.
// ----------------------------------------------------------------------------
#define QS_BYTES (128 * 128 * 2)
#define KV_BYTES (64 * 128 * 2)
#define FLASH_SMEM (QS_BYTES + 2 * (2 * KV_BYTES))

__global__ __launch_bounds__(256, 1)
void flash_hmma(const __half* __restrict__ Qg, const __half* __restrict__ Kg,
                const __half* __restrict__ Vg, __half* __restrict__ Z) {
    extern __shared__ char smem[];
    const uint32_t sb = smem_u32(smem);
    const int tid = threadIdx.x;
    const int wid = tid >> 5;
    const int lane = tid & 31;
    const int quad = lane >> 2, tq = lane & 3;
    const int r15 = lane & 15, hsel = lane >> 4;
    const int qt = (gridDim.x - 1) - blockIdx.x;   // heavy (long-KV) tiles first
    const int q0 = qt * 128;
    const int bh = blockIdx.y;
    const int b = bh >> 5, h = bh & 31, kvh = h >> 2;
    const __half* qsrc = Qg + ((size_t)bh * SEQ + q0) * DHEAD;
    const __half* ksrc0 = Kg + ((size_t)(b * NKVHEAD + kvh)) * SEQ * DHEAD;
    const __half* vsrc0 = Vg + ((size_t)(b * NKVHEAD + kvh)) * SEQ * DHEAD;
    const int nkt = 2 * (qt + 1);

    #pragma unroll
    for (int t = 0; t < 8; t++) {
        int j = tid + t * 256;
        int row = j >> 4, dc = (j >> 2) & 3, ks = j & 3;
        cp16(sb + dc * 8192 + swz_off(row, ks), qsrc + (size_t)row * DHEAD + dc * 32 + ks * 8);
    }
    CP_COMMIT();

    auto load_kv = [&](int t, int s) {
        uint32_t kb = sb + QS_BYTES + s * (2 * KV_BYTES);
        uint32_t vb = kb + KV_BYTES;
        const __half* ks_ = ksrc0 + (size_t)t * 64 * DHEAD;
        const __half* vs_ = vsrc0 + (size_t)t * 64 * DHEAD;
        #pragma unroll
        for (int u = 0; u < 8; u++) {
            int j = tid + u * 256;
            bool isv = j >= 1024;
            int jj = j & 1023;
            int row = jj >> 4, dc = (jj >> 2) & 3, ks = jj & 3;
            cp16((isv ? vb : kb) + dc * 4096 + swz_off(row, ks),
                 (isv ? vs_ : ks_) + (size_t)row * DHEAD + dc * 32 + ks * 8);
        }
    };

    load_kv(0, 0); CP_COMMIT();
    cp_wait<1>();
    __syncthreads();

    uint32_t qF[8][4];
    #pragma unroll
    for (int kc = 0; kc < 8; kc++) {
        int dc = kc >> 1;
        LDSM4(qF[kc], sb + dc * 8192 + swz_off(wid * 16 + r15, (kc & 1) * 2 + hsel));
    }

    if (nkt > 1) load_kv(1, 1);
    CP_COMMIT();

    float o[16][4];
    #pragma unroll
    for (int i = 0; i < 16; i++)
        #pragma unroll
        for (int r = 0; r < 4; r++) o[i][r] = 0.0f;
    float m0v = -1e30f, m1v = -1e30f, l0v = 0.0f, l1v = 0.0f;

    const int row_g0 = q0 + wid * 16 + quad;

    for (int t = 0; t < nkt; t++) {
        cp_wait<1>();
        __syncthreads();
        const uint32_t kb = sb + QS_BYTES + (t & 1) * (2 * KV_BYTES);
        const uint32_t vb = kb + KV_BYTES;

        float s[8][4];
        #pragma unroll
        for (int j = 0; j < 8; j++)
            #pragma unroll
            for (int r = 0; r < 4; r++) s[j][r] = 0.0f;

        #pragma unroll
        for (int kc = 0; kc < 8; kc++) {
            int dc = kc >> 1;
            #pragma unroll
            for (int j = 0; j < 4; j++) {
                uint32_t kf[4];
                LDSM4(kf, kb + dc * 4096 + swz_off(j * 16 + r15, (kc & 1) * 2 + hsel));
                MMAH(s[2 * j],     qF[kc], kf[0], kf[2]);
                MMAH(s[2 * j + 1], qF[kc], kf[1], kf[3]);
            }
        }

        if (t >= nkt - 2) {
            #pragma unroll
            for (int j = 0; j < 8; j++) {
                int col = t * 64 + j * 8 + tq * 2;
                if (col     > row_g0)     s[j][0] = -1e30f;
                if (col + 1 > row_g0)     s[j][1] = -1e30f;
                if (col     > row_g0 + 8) s[j][2] = -1e30f;
                if (col + 1 > row_g0 + 8) s[j][3] = -1e30f;
            }
        }

        float rm0 = -1e30f, rm1 = -1e30f;
        #pragma unroll
        for (int j = 0; j < 8; j++) {
            rm0 = fmaxf(rm0, fmaxf(s[j][0], s[j][1]));
            rm1 = fmaxf(rm1, fmaxf(s[j][2], s[j][3]));
        }
        rm0 = fmaxf(rm0, __shfl_xor_sync(0xffffffffu, rm0, 1));
        rm0 = fmaxf(rm0, __shfl_xor_sync(0xffffffffu, rm0, 2));
        rm1 = fmaxf(rm1, __shfl_xor_sync(0xffffffffu, rm1, 1));
        rm1 = fmaxf(rm1, __shfl_xor_sync(0xffffffffu, rm1, 2));

        float mn0 = fmaxf(m0v, rm0), mn1 = fmaxf(m1v, rm1);
        float f0 = exp2f(m0v - mn0), f1 = exp2f(m1v - mn1);

        float rs0 = 0.0f, rs1 = 0.0f;
        uint32_t aP[4][4];
        #pragma unroll
        for (int kk = 0; kk < 4; kk++) {
            float p00 = exp2f(s[2 * kk][0] - mn0);
            float p01 = exp2f(s[2 * kk][1] - mn0);
            float p02 = exp2f(s[2 * kk][2] - mn1);
            float p03 = exp2f(s[2 * kk][3] - mn1);
            float p10 = exp2f(s[2 * kk + 1][0] - mn0);
            float p11 = exp2f(s[2 * kk + 1][1] - mn0);
            float p12 = exp2f(s[2 * kk + 1][2] - mn1);
            float p13 = exp2f(s[2 * kk + 1][3] - mn1);
            rs0 += p00 + p01 + p10 + p11;
            rs1 += p02 + p03 + p12 + p13;
            aP[kk][0] = packh2(p00, p01);
            aP[kk][1] = packh2(p02, p03);
            aP[kk][2] = packh2(p10, p11);
            aP[kk][3] = packh2(p12, p13);
        }
        rs0 += __shfl_xor_sync(0xffffffffu, rs0, 1);
        rs0 += __shfl_xor_sync(0xffffffffu, rs0, 2);
        rs1 += __shfl_xor_sync(0xffffffffu, rs1, 1);
        rs1 += __shfl_xor_sync(0xffffffffu, rs1, 2);

        l0v = l0v * f0 + rs0;
        l1v = l1v * f1 + rs1;
        m0v = mn0; m1v = mn1;

        #pragma unroll
        for (int i = 0; i < 16; i++) {
            o[i][0] *= f0; o[i][1] *= f0;
            o[i][2] *= f1; o[i][3] *= f1;
        }

        #pragma unroll
        for (int djp = 0; djp < 8; djp++) {
            int dj = djp * 2 + hsel;
            int dc = dj >> 2, ks = dj & 3;
            #pragma unroll
            for (int kk = 0; kk < 4; kk++) {
                uint32_t vr[4];
                LDSM4T(vr, vb + dc * 4096 + swz_off(kk * 16 + r15, ks));
                MMAH(o[djp * 2],     aP[kk], vr[0], vr[1]);
                MMAH(o[djp * 2 + 1], aP[kk], vr[2], vr[3]);
            }
        }

        __syncthreads();
        if (t + 2 < nkt) load_kv(t + 2, t & 1);
        CP_COMMIT();
    }

    float inv0 = 1.0f / l0v, inv1 = 1.0f / l1v;
    size_t base0 = (size_t)(b * SEQ + row_g0) * DMODEL + h * DHEAD;
    size_t base1 = base0 + (size_t)8 * DMODEL;
    #pragma unroll
    for (int djt = 0; djt < 16; djt++) {
        int col = djt * 8 + tq * 2;
        *(__half2*)(Z + base0 + col) = __floats2half2_rn(o[djt][0] * inv0, o[djt][1] * inv0);
        *(__half2*)(Z + base1 + col) = __floats2half2_rn(o[djt][2] * inv1, o[djt][3] * inv1);
    }
}

// ----------------------------------------------------------------------------
// Host launcher
// ----------------------------------------------------------------------------
extern "C" void kernel_launch(void* const* d_in, const int* in_sizes, int n_in,
                              void* d_out, int out_size) {
    const float* x    = (const float*)d_in[0];
    const float* fcos = (const float*)d_in[1];
    const float* fsin = (const float*)d_in[2];
    const float* wq   = (const float*)d_in[3];
    const float* wk   = (const float*)d_in[4];
    const float* wv   = (const float*)d_in[5];
    const float* wo   = (const float*)d_in[6];
    float* out = (float*)d_out;

    __half *x16, *wqkv, *wot, *z16, *q16, *k16, *v16;
    cudaGetSymbolAddress((void**)&x16, X16);
    cudaGetSymbolAddress((void**)&wqkv, WQKVT16);
    cudaGetSymbolAddress((void**)&wot, WOT16);
    cudaGetSymbolAddress((void**)&z16, Z16);
    cudaGetSymbolAddress((void**)&q16, Q16);
    cudaGetSymbolAddress((void**)&k16, K16);
    cudaGetSymbolAddress((void**)&v16, V16);

    cudaFuncSetAttribute(gemm_qkv, cudaFuncAttributeMaxDynamicSharedMemorySize, GEMM_F16_SMEM);
    cudaFuncSetAttribute(wo_gemm, cudaFuncAttributeMaxDynamicSharedMemorySize, GEMM_F16_SMEM);
    cudaFuncSetAttribute(flash_hmma, cudaFuncAttributeMaxDynamicSharedMemorySize, FLASH_SMEM);

    // Input conversions
    {
        int n = MROWS * DMODEL;
        xconvert<<<(n + 255) / 256, 256>>>(x, x16, n);
    }
    transpose_convert<<<dim3(QCOLS / 32, DMODEL / 32), dim3(32, 8)>>>(wq, wqkv, DMODEL, QCOLS);
    transpose_convert<<<dim3(KVCOLS / 32, DMODEL / 32), dim3(32, 8)>>>(wk, wqkv + (size_t)QCOLS * DMODEL, DMODEL, KVCOLS);
    transpose_convert<<<dim3(KVCOLS / 32, DMODEL / 32), dim3(32, 8)>>>(wv, wqkv + (size_t)(QCOLS + KVCOLS) * DMODEL, DMODEL, KVCOLS);
    transpose_convert<<<dim3(DMODEL / 32, DMODEL / 32), dim3(32, 8)>>>(wo, wot, DMODEL, DMODEL);

    // Merged QKV projection (single-pass fp16, fused RoPE epilogue)
    const float qs = 0.08838834764831845f * 1.4426950408889634f;   // scale * log2(e)
    gemm_qkv<<<dim3(QKVCOLS / BN, MROWS / BM), 256, GEMM_F16_SMEM>>>(
        x16, wqkv, fcos, fsin, q16, k16, v16, qs);

    // Flash attention (fp16 HMMA) -> Z16 fp16
    flash_hmma<<<dim3(SEQ / 128, BATCH * NHEAD), 256, FLASH_SMEM>>>(q16, k16, v16, z16);

    // Output projection: single-pass fp16
    wo_gemm<<<dim3(DMODEL / BN, MROWS / BM), 256, GEMM_F16_SMEM>>>(z16, wot, out, DMODEL, DMODEL);
}

// round 9
// speedup vs baseline: 8.7820x; 1.1244x over previous
#include <cuda_runtime.h>
#include <cuda_fp16.h>
#include <cstdint>
#include <math.h>

// Problem constants
#define BATCH 2
#define SEQ 2048
#define DMODEL 4096
#define NHEAD 32
#define NKVHEAD 8
#define DHEAD 128
#define MROWS (BATCH * SEQ)            // 4096
#define QCOLS (NHEAD * DHEAD)          // 4096
#define KVCOLS (NKVHEAD * DHEAD)       // 1024
#define QKVCOLS (QCOLS + 2 * KVCOLS)   // 6144

// ---------------------------------------------------------------------------
// Scratch buffers (__device__ globals; allocation-free rule)
// ---------------------------------------------------------------------------
__device__ __half X16[(size_t)MROWS * DMODEL];
__device__ __half WQKVT16[(size_t)QKVCOLS * DMODEL];  // rows: 0-4095 Q, 4096-5119 K, 5120-6143 V
__device__ __half WOT16[(size_t)DMODEL * DMODEL];
__device__ __half Z16[(size_t)MROWS * DMODEL];
__device__ __half Q16[(size_t)MROWS * QCOLS];
__device__ __half K16[(size_t)MROWS * KVCOLS];
__device__ __half V16[(size_t)MROWS * KVCOLS];

// ---------------------------------------------------------------------------
// Helpers
// ---------------------------------------------------------------------------
__device__ __forceinline__ uint32_t smem_u32(const void* p) {
    uint32_t a;
    asm("{ .reg .u64 t; cvta.to.shared.u64 t, %1; cvt.u32.u64 %0, t; }" : "=r"(a) : "l"(p));
    return a;
}

__device__ __forceinline__ void cp16(uint32_t dst, const void* src) {
    asm volatile("cp.async.cg.shared.global [%0], [%1], 16;" :: "r"(dst), "l"(src));
}
#define CP_COMMIT() asm volatile("cp.async.commit_group;" ::: "memory")
template <int N>
__device__ __forceinline__ void cp_wait() {
    asm volatile("cp.async.wait_group %0;" :: "n"(N) : "memory");
}

#define LDSM4(r, addr)                                                        \
    asm volatile("ldmatrix.sync.aligned.m8n8.x4.shared.b16 {%0,%1,%2,%3}, [%4];" \
        : "=r"((r)[0]), "=r"((r)[1]), "=r"((r)[2]), "=r"((r)[3]) : "r"(addr))

#define LDSM4T(r, addr)                                                       \
    asm volatile("ldmatrix.sync.aligned.m8n8.x4.trans.shared.b16 {%0,%1,%2,%3}, [%4];" \
        : "=r"((r)[0]), "=r"((r)[1]), "=r"((r)[2]), "=r"((r)[3]) : "r"(addr))

#define MMAH(c, a, b0, b1)                                                    \
    asm volatile("mma.sync.aligned.m16n8k16.row.col.f32.f16.f16.f32 "         \
        "{%0,%1,%2,%3}, {%4,%5,%6,%7}, {%8,%9}, {%0,%1,%2,%3};"               \
        : "+f"((c)[0]), "+f"((c)[1]), "+f"((c)[2]), "+f"((c)[3])              \
        : "r"((a)[0]), "r"((a)[1]), "r"((a)[2]), "r"((a)[3]),                 \
          "r"(b0), "r"(b1))

__device__ __forceinline__ uint32_t packh2(float x, float y) {
    __half2 h = __floats2half2_rn(x, y);
    return *(uint32_t*)&h;
}

// swizzled byte offset within a 64B-row tile for (row, kseg[0..3])
__device__ __forceinline__ uint32_t swz_off(int row, int ks) {
    return (uint32_t)(row * 64 + (((ks ^ (row >> 1)) & 3) << 4));
}

// ---------------------------------------------------------------------------
// fp32 -> fp16 convert (elementwise)
// ---------------------------------------------------------------------------
__global__ __launch_bounds__(256) void xconvert(const float* __restrict__ src,
                                                __half* __restrict__ dst, int n) {
    int i = blockIdx.x * blockDim.x + threadIdx.x;
    if (i < n) dst[i] = __float2half(src[i]);
}

// Transpose + fp16 convert: W[K,N] fp32 -> T [N,K] fp16
__global__ __launch_bounds__(256) void transpose_convert(const float* __restrict__ W,
                                                         __half* __restrict__ T,
                                                         int K, int N) {
    __shared__ float t[32][33];
    int n0 = blockIdx.x * 32;
    int k0 = blockIdx.y * 32;
    int tx = threadIdx.x, ty = threadIdx.y;
    #pragma unroll
    for (int r = ty; r < 32; r += 8)
        t[r][tx] = W[(size_t)(k0 + r) * N + n0 + tx];
    __syncthreads();
    #pragma unroll
    for (int r = ty; r < 32; r += 8)
        T[(size_t)(n0 + r) * K + k0 + tx] = __float2half(t[tx][r]);
}

// ---------------------------------------------------------------------------
// Merged QKV single-pass fp16 GEMM, fused RoPE/scale/head-major epilogue.
// BN=192 -> grid (32,32)=1024 CTAs = 6.92 waves (minimal tail).
// ---------------------------------------------------------------------------
#define BM 128
#define BK 32
#define A_SEG_B (BM * BK * 2)               // 8192

#define QKV_BN 192
#define QKV_BT_B (QKV_BN * BK * 2)          // 12288
#define QKV_STAGE (A_SEG_B + QKV_BT_B)      // 20480
#define QKV_NST 6
#define GEMM_QKV_SMEM (QKV_NST * QKV_STAGE) // 122880

__global__ __launch_bounds__(256, 1)
void gemm_qkv(const __half* __restrict__ A, const __half* __restrict__ B,
              const float* __restrict__ cosb, const float* __restrict__ sinb,
              __half* __restrict__ qo, __half* __restrict__ ko,
              __half* __restrict__ vo, float qs) {
    extern __shared__ char smem[];
    const uint32_t sb = smem_u32(smem);
    const int tid = threadIdx.x;
    const int wid = tid >> 5;
    const int lane = tid & 31;
    const int wm = wid >> 2;       // 0..1
    const int wn = wid & 3;        // 0..3 (48 cols each)
    const int m0 = blockIdx.y * BM;
    const int n0 = blockIdx.x * QKV_BN;
    const int K = DMODEL;
    const int TOT = K / BK;

    float acc[4][6][4];
    #pragma unroll
    for (int i = 0; i < 4; i++)
        #pragma unroll
        for (int j = 0; j < 6; j++)
            #pragma unroll
            for (int r = 0; r < 4; r++) acc[i][j][r] = 0.0f;

    auto load_chunk = [&](int c, int s) {
        const __half* as = A + (size_t)m0 * K + c * BK;
        const __half* bs = B + (size_t)n0 * K + c * BK;
        uint32_t base = sb + s * QKV_STAGE;
        #pragma unroll
        for (int t = 0; t < 5; t++) {
            int idx = tid + t * 256;          // 512 A segs + 768 B segs
            if (idx < 512) {
                int row = idx >> 2, ks = idx & 3;
                cp16(base + swz_off(row, ks), as + (size_t)row * K + ks * 8);
            } else {
                int j = idx - 512;
                int row = j >> 2, ks = j & 3;
                cp16(base + A_SEG_B + swz_off(row, ks), bs + (size_t)row * K + ks * 8);
            }
        }
    };

    #pragma unroll
    for (int s = 0; s < QKV_NST - 1; s++) {
        if (s < TOT) load_chunk(s, s);
        CP_COMMIT();
    }

    const int r15 = lane & 15;
    const int hsel = lane >> 4;

    for (int c = 0; c < TOT; c++) {
        const int s = c % QKV_NST;
        cp_wait<QKV_NST - 2>();
        __syncthreads();

        {
            int nc = c + QKV_NST - 1;
            if (nc < TOT) load_chunk(nc, nc % QKV_NST);
            CP_COMMIT();
        }

        const uint32_t ab = sb + s * QKV_STAGE;
        const uint32_t bb = ab + A_SEG_B;

        #pragma unroll
        for (int ks2 = 0; ks2 < 2; ks2++) {
            const int kseg = ks2 * 2 + hsel;
            uint32_t aF[4][4], bF[3][4];
            #pragma unroll
            for (int i = 0; i < 4; i++)
                LDSM4(aF[i], ab + swz_off(wm * 64 + i * 16 + r15, kseg));
            #pragma unroll
            for (int j = 0; j < 3; j++)
                LDSM4(bF[j], bb + swz_off(wn * 48 + j * 16 + r15, kseg));
            #pragma unroll
            for (int i = 0; i < 4; i++)
                #pragma unroll
                for (int j = 0; j < 3; j++) {
                    MMAH(acc[i][2 * j],     aF[i], bF[j][0], bF[j][2]);
                    MMAH(acc[i][2 * j + 1], aF[i], bF[j][1], bF[j][3]);
                }
        }
    }

    // Fused epilogue: route to Q/K/V, RoPE (+scale), head-major fp16 store
    const int quad = lane >> 2;
    const int tq = lane & 3;
    #pragma unroll
    for (int i = 0; i < 4; i++) {
        int r0 = m0 + wm * 64 + i * 16 + quad;
        int b0 = r0 >> 11;
        int t0 = r0 & (SEQ - 1);
        #pragma unroll
        for (int j = 0; j < 6; j++) {
            int c = n0 + wn * 48 + j * 8 + tq * 2;
            __half* dst;
            int H, cc;
            bool dorope;
            float scl;
            if (c < QCOLS)            { dst = qo; H = NHEAD;   cc = c;          dorope = true;  scl = qs; }
            else if (c < QCOLS + 1024){ dst = ko; H = NKVHEAD; cc = c - QCOLS;  dorope = true;  scl = 1.0f; }
            else                      { dst = vo; H = NKVHEAD; cc = c - QCOLS - 1024; dorope = false; scl = 1.0f; }
            int h = cc >> 7, d = cc & 127, d2 = d >> 1;
            float f0 = acc[i][j][0], f1 = acc[i][j][1];
            float f2 = acc[i][j][2], f3 = acc[i][j][3];
            if (dorope) {
                float c0 = cosb[t0 * 64 + d2], s0 = sinb[t0 * 64 + d2];
                float c1 = cosb[(t0 + 8) * 64 + d2], s1 = sinb[(t0 + 8) * 64 + d2];
                float a0 = (f0 * c0 - f1 * s0) * scl, a1 = (f0 * s0 + f1 * c0) * scl;
                float a2 = (f2 * c1 - f3 * s1) * scl, a3 = (f2 * s1 + f3 * c1) * scl;
                f0 = a0; f1 = a1; f2 = a2; f3 = a3;
            }
            size_t o0 = (((size_t)b0 * H + h) * SEQ + t0) * DHEAD + d;
            *(__half2*)(dst + o0) = __floats2half2_rn(f0, f1);
            *(__half2*)(dst + o0 + (size_t)8 * DHEAD) = __floats2half2_rn(f2, f3);
        }
    }
}

// ---------------------------------------------------------------------------
// WO projection: single-pass fp16 GEMM, BN=128 -> 1024 CTAs = 6.92 waves.
// ---------------------------------------------------------------------------
#define WO_BN 128
#define WO_BT_B (WO_BN * BK * 2)            // 8192
#define WO_STAGE (A_SEG_B + WO_BT_B)        // 16384
#define WO_NST 6
#define GEMM_WO_SMEM (WO_NST * WO_STAGE)    // 98304

__global__ __launch_bounds__(256, 1)
void wo_gemm(const __half* __restrict__ A, const __half* __restrict__ B,
             float* __restrict__ C, int N, int K) {
    extern __shared__ char smem[];
    const uint32_t sb = smem_u32(smem);
    const int tid = threadIdx.x;
    const int wid = tid >> 5;
    const int lane = tid & 31;
    const int wm = wid >> 2;       // 0..1
    const int wn = wid & 3;        // 0..3 (32 cols each)
    const int m0 = blockIdx.y * BM;
    const int n0 = blockIdx.x * WO_BN;
    const int TOT = K / BK;

    float acc[4][4][4];
    #pragma unroll
    for (int i = 0; i < 4; i++)
        #pragma unroll
        for (int j = 0; j < 4; j++)
            #pragma unroll
            for (int r = 0; r < 4; r++) acc[i][j][r] = 0.0f;

    auto load_chunk = [&](int c, int s) {
        const __half* as = A + (size_t)m0 * K + c * BK;
        const __half* bs = B + (size_t)n0 * K + c * BK;
        uint32_t base = sb + s * WO_STAGE;
        #pragma unroll
        for (int t = 0; t < 4; t++) {
            int idx = tid + t * 256;          // 512 A + 512 B
            if (idx < 512) {
                int row = idx >> 2, ks = idx & 3;
                cp16(base + swz_off(row, ks), as + (size_t)row * K + ks * 8);
            } else {
                int j = idx - 512;
                int row = j >> 2, ks = j & 3;
                cp16(base + A_SEG_B + swz_off(row, ks), bs + (size_t)row * K + ks * 8);
            }
        }
    };

    #pragma unroll
    for (int s = 0; s < WO_NST - 1; s++) {
        if (s < TOT) load_chunk(s, s);
        CP_COMMIT();
    }

    const int r15 = lane & 15;
    const int hsel = lane >> 4;

    for (int c = 0; c < TOT; c++) {
        const int s = c % WO_NST;
        cp_wait<WO_NST - 2>();
        __syncthreads();

        {
            int nc = c + WO_NST - 1;
            if (nc < TOT) load_chunk(nc, nc % WO_NST);
            CP_COMMIT();
        }

        const uint32_t ab = sb + s * WO_STAGE;
        const uint32_t bb = ab + A_SEG_B;

        #pragma unroll
        for (int ks2 = 0; ks2 < 2; ks2++) {
            const int kseg = ks2 * 2 + hsel;
            uint32_t aF[4][4], bF[2][4];
            #pragma unroll
            for (int i = 0; i < 4; i++)
                LDSM4(aF[i], ab + swz_off(wm * 64 + i * 16 + r15, kseg));
            #pragma unroll
            for (int j = 0; j < 2; j++)
                LDSM4(bF[j], bb + swz_off(wn * 32 + j * 16 + r15, kseg));
            #pragma unroll
            for (int i = 0; i < 4; i++)
                #pragma unroll
                for (int j = 0; j < 2; j++) {
                    MMAH(acc[i][2 * j],     aF[i], bF[j][0], bF[j][2]);
                    MMAH(acc[i][2 * j + 1], aF[i], bF[j][1], bF[j][3]);
                }
        }
    }

    const int quad = lane >> 2;
    const int tq = lane & 3;
    #pragma unroll
    for (int i = 0; i < 4; i++) {
        int row0 = m0 + wm * 64 + i * 16 + quad;
        #pragma unroll
        for (int j = 0; j < 4; j++) {
            int col = n0 + wn * 32 + j * 8 + tq * 2;
            *(float2*)(C + (size_t)row0 * N + col) =
                make_float2(acc[i][j][0], acc[i][j][1]);
            *(float2*)(C + (size_t)(row0 + 8) * N + col) =
                make_float2(acc[i][j][2], acc[i][j][3]);
        }
    }
}

// ----------------------------------------------------------------------------
// HMMA fp16 flash attention. KV tiles 128 wide (half the softmax updates).
// grid (16, 64); heavy (long-KV) q-tiles scheduled first.
// ----------------------------------------------------------------------------
#define QS_BYTES (128 * 128 * 2)      // 32768
#define KV_BYTES (128 * 128 * 2)      // 32768 per K (or V) tile
#define FLASH_SMEM (QS_BYTES + 2 * (2 * KV_BYTES))   // 163840

__global__ __launch_bounds__(256, 1)
void flash_hmma(const __half* __restrict__ Qg, const __half* __restrict__ Kg,
                const __half* __restrict__ Vg, __half* __restrict__ Z) {
    extern __shared__ char smem[];
    const uint32_t sb = smem_u32(smem);
    const int tid = threadIdx.x;
    const int wid = tid >> 5;
    const int lane = tid & 31;
    const int quad = lane >> 2, tq = lane & 3;
    const int r15 = lane & 15, hsel = lane >> 4;
    const int qt = (gridDim.x - 1) - blockIdx.x;   // heavy tiles first
    const int q0 = qt * 128;
    const int bh = blockIdx.y;
    const int b = bh >> 5, h = bh & 31, kvh = h >> 2;
    const __half* qsrc = Qg + ((size_t)bh * SEQ + q0) * DHEAD;
    const __half* ksrc0 = Kg + ((size_t)(b * NKVHEAD + kvh)) * SEQ * DHEAD;
    const __half* vsrc0 = Vg + ((size_t)(b * NKVHEAD + kvh)) * SEQ * DHEAD;
    const int nkt = qt + 1;           // 128-wide KV tiles

    // Q tile: 2048 x 16B segs
    #pragma unroll
    for (int t = 0; t < 8; t++) {
        int j = tid + t * 256;
        int row = j >> 4, dc = (j >> 2) & 3, ks = j & 3;
        cp16(sb + dc * 8192 + swz_off(row, ks), qsrc + (size_t)row * DHEAD + dc * 32 + ks * 8);
    }
    CP_COMMIT();

    // KV tile t (128 rows of K and V each): 4096 segs
    auto load_kv = [&](int t, int s) {
        uint32_t kb = sb + QS_BYTES + s * (2 * KV_BYTES);
        uint32_t vb = kb + KV_BYTES;
        const __half* ks_ = ksrc0 + (size_t)t * 128 * DHEAD;
        const __half* vs_ = vsrc0 + (size_t)t * 128 * DHEAD;
        #pragma unroll
        for (int u = 0; u < 16; u++) {
            int j = tid + u * 256;
            bool isv = j >= 2048;
            int jj = j & 2047;
            int row = jj >> 4, dc = (jj >> 2) & 3, ks = jj & 3;
            cp16((isv ? vb : kb) + dc * 8192 + swz_off(row, ks),
                 (isv ? vs_ : ks_) + (size_t)row * DHEAD + dc * 32 + ks * 8);
        }
    };

    load_kv(0, 0); CP_COMMIT();
    cp_wait<1>();
    __syncthreads();

    uint32_t qF[8][4];
    #pragma unroll
    for (int kc = 0; kc < 8; kc++) {
        int dc = kc >> 1;
        LDSM4(qF[kc], sb + dc * 8192 + swz_off(wid * 16 + r15, (kc & 1) * 2 + hsel));
    }

    if (nkt > 1) load_kv(1, 1);
    CP_COMMIT();

    float o[16][4];
    #pragma unroll
    for (int i = 0; i < 16; i++)
        #pragma unroll
        for (int r = 0; r < 4; r++) o[i][r] = 0.0f;
    float m0v = -1e30f, m1v = -1e30f, l0v = 0.0f, l1v = 0.0f;

    const int row_g0 = q0 + wid * 16 + quad;

    for (int t = 0; t < nkt; t++) {
        cp_wait<1>();
        __syncthreads();
        const uint32_t kb = sb + QS_BYTES + (t & 1) * (2 * KV_BYTES);
        const uint32_t vb = kb + KV_BYTES;

        // S = Q @ K^T over 128 kv cols
        float s[16][4];
        #pragma unroll
        for (int j = 0; j < 16; j++)
            #pragma unroll
            for (int r = 0; r < 4; r++) s[j][r] = 0.0f;

        #pragma unroll
        for (int kc = 0; kc < 8; kc++) {
            int dc = kc >> 1;
            #pragma unroll
            for (int j = 0; j < 8; j++) {
                uint32_t kf[4];
                LDSM4(kf, kb + dc * 8192 + swz_off(j * 16 + r15, (kc & 1) * 2 + hsel));
                MMAH(s[2 * j],     qF[kc], kf[0], kf[2]);
                MMAH(s[2 * j + 1], qF[kc], kf[1], kf[3]);
            }
        }

        // causal mask (diagonal tile only)
        if (t == nkt - 1) {
            #pragma unroll
            for (int j = 0; j < 16; j++) {
                int col = t * 128 + j * 8 + tq * 2;
                if (col     > row_g0)     s[j][0] = -1e30f;
                if (col + 1 > row_g0)     s[j][1] = -1e30f;
                if (col     > row_g0 + 8) s[j][2] = -1e30f;
                if (col + 1 > row_g0 + 8) s[j][3] = -1e30f;
            }
        }

        // row max
        float rm0 = -1e30f, rm1 = -1e30f;
        #pragma unroll
        for (int j = 0; j < 16; j++) {
            rm0 = fmaxf(rm0, fmaxf(s[j][0], s[j][1]));
            rm1 = fmaxf(rm1, fmaxf(s[j][2], s[j][3]));
        }
        rm0 = fmaxf(rm0, __shfl_xor_sync(0xffffffffu, rm0, 1));
        rm0 = fmaxf(rm0, __shfl_xor_sync(0xffffffffu, rm0, 2));
        rm1 = fmaxf(rm1, __shfl_xor_sync(0xffffffffu, rm1, 1));
        rm1 = fmaxf(rm1, __shfl_xor_sync(0xffffffffu, rm1, 2));

        float mn0 = fmaxf(m0v, rm0), mn1 = fmaxf(m1v, rm1);
        float f0 = exp2f(m0v - mn0), f1 = exp2f(m1v - mn1);

        float rs0 = 0.0f, rs1 = 0.0f;
        uint32_t aP[8][4];
        #pragma unroll
        for (int kk = 0; kk < 8; kk++) {
            float p00 = exp2f(s[2 * kk][0] - mn0);
            float p01 = exp2f(s[2 * kk][1] - mn0);
            float p02 = exp2f(s[2 * kk][2] - mn1);
            float p03 = exp2f(s[2 * kk][3] - mn1);
            float p10 = exp2f(s[2 * kk + 1][0] - mn0);
            float p11 = exp2f(s[2 * kk + 1][1] - mn0);
            float p12 = exp2f(s[2 * kk + 1][2] - mn1);
            float p13 = exp2f(s[2 * kk + 1][3] - mn1);
            rs0 += p00 + p01 + p10 + p11;
            rs1 += p02 + p03 + p12 + p13;
            aP[kk][0] = packh2(p00, p01);
            aP[kk][1] = packh2(p02, p03);
            aP[kk][2] = packh2(p10, p11);
            aP[kk][3] = packh2(p12, p13);
        }
        rs0 += __shfl_xor_sync(0xffffffffu, rs0, 1);
        rs0 += __shfl_xor_sync(0xffffffffu, rs0, 2);
        rs1 += __shfl_xor_sync(0xffffffffu, rs1, 1);
        rs1 += __shfl_xor_sync(0xffffffffu, rs1, 2);

        l0v = l0v * f0 + rs0;
        l1v = l1v * f1 + rs1;
        m0v = mn0; m1v = mn1;

        #pragma unroll
        for (int i = 0; i < 16; i++) {
            o[i][0] *= f0; o[i][1] *= f0;
            o[i][2] *= f1; o[i][3] *= f1;
        }

        // O += P @ V over 128 kv rows
        #pragma unroll
        for (int djp = 0; djp < 8; djp++) {
            int dj = djp * 2 + hsel;
            int dc = dj >> 2, ks = dj & 3;
            #pragma unroll
            for (int kk = 0; kk < 8; kk++) {
                uint32_t vr[4];
                LDSM4T(vr, vb + dc * 8192 + swz_off(kk * 16 + r15, ks));
                MMAH(o[djp * 2],     aP[kk], vr[0], vr[1]);
                MMAH(o[djp * 2 + 1], aP[kk], vr[2], vr[3]);
            }
        }

        __syncthreads();
        if (t + 2 < nkt) load_kv(t + 2, t & 1);
        CP_COMMIT();
    }

    float inv0 = 1.0f / l0v, inv1 = 1.0f / l1v;
    size_t base0 = (size_t)(b * SEQ + row_g0) * DMODEL + h * DHEAD;
    size_t base1 = base0 + (size_t)8 * DMODEL;
    #pragma unroll
    for (int djt = 0; djt < 16; djt++) {
        int col = djt * 8 + tq * 2;
        *(__half2*)(Z + base0 + col) = __floats2half2_rn(o[djt][0] * inv0, o[djt][1] * inv0);
        *(__half2*)(Z + base1 + col) = __floats2half2_rn(o[djt][2] * inv1, o[djt][3] * inv1);
    }
}

// ----------------------------------------------------------------------------
// Host launcher
// ----------------------------------------------------------------------------
extern "C" void kernel_launch(void* const* d_in, const int* in_sizes, int n_in,
                              void* d_out, int out_size) {
    const float* x    = (const float*)d_in[0];
    const float* fcos = (const float*)d_in[1];
    const float* fsin = (const float*)d_in[2];
    const float* wq   = (const float*)d_in[3];
    const float* wk   = (const float*)d_in[4];
    const float* wv   = (const float*)d_in[5];
    const float* wo   = (const float*)d_in[6];
    float* out = (float*)d_out;

    __half *x16, *wqkv, *wot, *z16, *q16, *k16, *v16;
    cudaGetSymbolAddress((void**)&x16, X16);
    cudaGetSymbolAddress((void**)&wqkv, WQKVT16);
    cudaGetSymbolAddress((void**)&wot, WOT16);
    cudaGetSymbolAddress((void**)&z16, Z16);
    cudaGetSymbolAddress((void**)&q16, Q16);
    cudaGetSymbolAddress((void**)&k16, K16);
    cudaGetSymbolAddress((void**)&v16, V16);

    cudaFuncSetAttribute(gemm_qkv, cudaFuncAttributeMaxDynamicSharedMemorySize, GEMM_QKV_SMEM);
    cudaFuncSetAttribute(wo_gemm, cudaFuncAttributeMaxDynamicSharedMemorySize, GEMM_WO_SMEM);
    cudaFuncSetAttribute(flash_hmma, cudaFuncAttributeMaxDynamicSharedMemorySize, FLASH_SMEM);

    // Input conversions
    {
        int n = MROWS * DMODEL;
        xconvert<<<(n + 255) / 256, 256>>>(x, x16, n);
    }
    transpose_convert<<<dim3(QCOLS / 32, DMODEL / 32), dim3(32, 8)>>>(wq, wqkv, DMODEL, QCOLS);
    transpose_convert<<<dim3(KVCOLS / 32, DMODEL / 32), dim3(32, 8)>>>(wk, wqkv + (size_t)QCOLS * DMODEL, DMODEL, KVCOLS);
    transpose_convert<<<dim3(KVCOLS / 32, DMODEL / 32), dim3(32, 8)>>>(wv, wqkv + (size_t)(QCOLS + KVCOLS) * DMODEL, DMODEL, KVCOLS);
    transpose_convert<<<dim3(DMODEL / 32, DMODEL / 32), dim3(32, 8)>>>(wo, wot, DMODEL, DMODEL);

    // Merged QKV projection (single-pass fp16, fused RoPE epilogue)
    const float qs = 0.08838834764831845f * 1.4426950408889634f;   // scale * log2(e)
    gemm_qkv<<<dim3(QKVCOLS / QKV_BN, MROWS / BM), 256, GEMM_QKV_SMEM>>>(
        x16, wqkv, fcos, fsin, q16, k16, v16, qs);

    // Flash attention (fp16 HMMA) -> Z16 fp16
    flash_hmma<<<dim3(SEQ / 128, BATCH * NHEAD), 256, FLASH_SMEM>>>(q16, k16, v16, z16);

    // Output projection: single-pass fp16
    wo_gemm<<<dim3(DMODEL / WO_BN, MROWS / BM), 256, GEMM_WO_SMEM>>>(z16, wot, out, DMODEL, DMODEL);
}

// round 10
// speedup vs baseline: 9.2717x; 1.0558x over previous
#include <cuda_runtime.h>
#include <cuda_fp16.h>
#include <cstdint>
#include <math.h>

// Problem constants
#define BATCH 2
#define SEQ 2048
#define DMODEL 4096
#define NHEAD 32
#define NKVHEAD 8
#define DHEAD 128
#define MROWS (BATCH * SEQ)            // 4096
#define QCOLS (NHEAD * DHEAD)          // 4096
#define KVCOLS (NKVHEAD * DHEAD)       // 1024
#define QKVCOLS (QCOLS + 2 * KVCOLS)   // 6144

// ---------------------------------------------------------------------------
// Scratch buffers (__device__ globals; allocation-free rule)
// ---------------------------------------------------------------------------
__device__ __half X16[(size_t)MROWS * DMODEL];
__device__ __half WQKVT16[(size_t)QKVCOLS * DMODEL];  // rows: 0-4095 Q, 4096-5119 K, 5120-6143 V
__device__ __half WOT16[(size_t)DMODEL * DMODEL];
__device__ __half Z16[(size_t)MROWS * DMODEL];
__device__ __half Q16[(size_t)MROWS * QCOLS];
__device__ __half K16[(size_t)MROWS * KVCOLS];
__device__ __half V16[(size_t)MROWS * KVCOLS];

// ---------------------------------------------------------------------------
// Helpers
// ---------------------------------------------------------------------------
__device__ __forceinline__ uint32_t smem_u32(const void* p) {
    uint32_t a;
    asm("{ .reg .u64 t; cvta.to.shared.u64 t, %1; cvt.u32.u64 %0, t; }" : "=r"(a) : "l"(p));
    return a;
}

__device__ __forceinline__ void cp16(uint32_t dst, const void* src) {
    asm volatile("cp.async.cg.shared.global [%0], [%1], 16;" :: "r"(dst), "l"(src));
}
#define CP_COMMIT() asm volatile("cp.async.commit_group;" ::: "memory")
template <int N>
__device__ __forceinline__ void cp_wait() {
    asm volatile("cp.async.wait_group %0;" :: "n"(N) : "memory");
}

#define LDSM4(r, addr)                                                        \
    asm volatile("ldmatrix.sync.aligned.m8n8.x4.shared.b16 {%0,%1,%2,%3}, [%4];" \
        : "=r"((r)[0]), "=r"((r)[1]), "=r"((r)[2]), "=r"((r)[3]) : "r"(addr))

#define LDSM4T(r, addr)                                                       \
    asm volatile("ldmatrix.sync.aligned.m8n8.x4.trans.shared.b16 {%0,%1,%2,%3}, [%4];" \
        : "=r"((r)[0]), "=r"((r)[1]), "=r"((r)[2]), "=r"((r)[3]) : "r"(addr))

#define MMAH(c, a, b0, b1)                                                    \
    asm volatile("mma.sync.aligned.m16n8k16.row.col.f32.f16.f16.f32 "         \
        "{%0,%1,%2,%3}, {%4,%5,%6,%7}, {%8,%9}, {%0,%1,%2,%3};"               \
        : "+f"((c)[0]), "+f"((c)[1]), "+f"((c)[2]), "+f"((c)[3])              \
        : "r"((a)[0]), "r"((a)[1]), "r"((a)[2]), "r"((a)[3]),                 \
          "r"(b0), "r"(b1))

__device__ __forceinline__ uint32_t packh2(float x, float y) {
    __half2 h = __floats2half2_rn(x, y);
    return *(uint32_t*)&h;
}

// swizzled byte offset within a 64B-row tile for (row, kseg[0..3])
__device__ __forceinline__ uint32_t swz_off(int row, int ks) {
    return (uint32_t)(row * 64 + (((ks ^ (row >> 1)) & 3) << 4));
}

// ---------------------------------------------------------------------------
// fp32 -> fp16 convert (elementwise)
// ---------------------------------------------------------------------------
__global__ __launch_bounds__(256) void xconvert(const float* __restrict__ src,
                                                __half* __restrict__ dst, int n) {
    int i = blockIdx.x * blockDim.x + threadIdx.x;
    if (i < n) dst[i] = __float2half(src[i]);
}

// ---------------------------------------------------------------------------
// Merged weight prep: all 4 transposes (wq,wk,wv -> WQKVT16; wo -> WOT16)
// in one launch. Linearized 32x32-tile job table.
// ---------------------------------------------------------------------------
#define TQ (128 * 128)        // wq tiles: (4096/32) x (4096/32) = 16384
#define TK (32 * 128)         // wk tiles: (1024/32) x (4096/32) = 4096
#define TV TK
#define TO (128 * 128)

__global__ __launch_bounds__(256) void prep_weights(const float* __restrict__ wq,
                                                    const float* __restrict__ wk,
                                                    const float* __restrict__ wv,
                                                    const float* __restrict__ wo,
                                                    __half* __restrict__ wqkv,
                                                    __half* __restrict__ wot) {
    __shared__ float t[32][33];
    int id = blockIdx.x;
    const float* W;
    __half* T;
    int N;
    if (id < TQ)                { W = wq; T = wqkv;                                   N = QCOLS;  }
    else if (id < TQ + TK)      { W = wk; T = wqkv + (size_t)QCOLS * DMODEL;          N = KVCOLS; id -= TQ; }
    else if (id < TQ + TK + TV) { W = wv; T = wqkv + (size_t)(QCOLS + KVCOLS) * DMODEL; N = KVCOLS; id -= TQ + TK; }
    else                        { W = wo; T = wot;                                    N = DMODEL; id -= TQ + TK + TV; }
    int ntx = N / 32;
    int n0 = (id % ntx) * 32;
    int k0 = (id / ntx) * 32;
    int tx = threadIdx.x & 31, ty = threadIdx.x >> 5;
    #pragma unroll
    for (int r = ty; r < 32; r += 8)
        t[r][tx] = W[(size_t)(k0 + r) * N + n0 + tx];
    __syncthreads();
    #pragma unroll
    for (int r = ty; r < 32; r += 8)
        T[(size_t)(n0 + r) * DMODEL + k0 + tx] = __float2half(t[tx][r]);
}

// ---------------------------------------------------------------------------
// Merged QKV single-pass fp16 GEMM, fused RoPE/scale/head-major epilogue.
// BN=192; BK=64 per stage (two stacked 32-wide sub-tiles); NST=3.
// grid (32,32)=1024 CTAs = 6.92 waves.
// ---------------------------------------------------------------------------
#define BM 128
#define A32_B (BM * 32 * 2)                 // 8192 per 32-wide A sub-tile

#define QKV_BN 192
#define QKV_B32_B (QKV_BN * 32 * 2)         // 12288 per 32-wide B sub-tile
#define QKV_STAGE (2 * A32_B + 2 * QKV_B32_B)  // 40960
#define QKV_NST 3
#define GEMM_QKV_SMEM (QKV_NST * QKV_STAGE) // 122880

__global__ __launch_bounds__(256, 1)
void gemm_qkv(const __half* __restrict__ A, const __half* __restrict__ B,
              const float* __restrict__ cosb, const float* __restrict__ sinb,
              __half* __restrict__ qo, __half* __restrict__ ko,
              __half* __restrict__ vo, float qs) {
    extern __shared__ char smem[];
    const uint32_t sb = smem_u32(smem);
    const int tid = threadIdx.x;
    const int wid = tid >> 5;
    const int lane = tid & 31;
    const int wm = wid >> 2;       // 0..1
    const int wn = wid & 3;        // 0..3 (48 cols each)
    const int m0 = blockIdx.y * BM;
    const int n0 = blockIdx.x * QKV_BN;
    const int K = DMODEL;
    const int TOT = K / 64;        // 64 chunks of BK=64

    float acc[4][6][4];
    #pragma unroll
    for (int i = 0; i < 4; i++)
        #pragma unroll
        for (int j = 0; j < 6; j++)
            #pragma unroll
            for (int r = 0; r < 4; r++) acc[i][j][r] = 0.0f;

    // chunk c (64 k-cols) -> stage s: [A0|A1|B0|B1] 32-wide sub-tiles
    auto load_chunk = [&](int c, int s) {
        const __half* as = A + (size_t)m0 * K + c * 64;
        const __half* bs = B + (size_t)n0 * K + c * 64;
        uint32_t base = sb + s * QKV_STAGE;
        #pragma unroll
        for (int t = 0; t < 10; t++) {
            int idx = tid + t * 256;      // 1024 A segs + 1536 B segs
            if (idx < 1024) {
                int kh = idx >> 9;        // sub-tile
                int j = idx & 511;
                int row = j >> 2, ks = j & 3;
                cp16(base + kh * A32_B + swz_off(row, ks),
                     as + kh * 32 + (size_t)row * K + ks * 8);
            } else {
                int j = idx - 1024;       // 0..1535
                int kh = j / 768;
                int jj = j - kh * 768;
                int row = jj >> 2, ks = jj & 3;
                cp16(base + 2 * A32_B + kh * QKV_B32_B + swz_off(row, ks),
                     bs + kh * 32 + (size_t)row * K + ks * 8);
            }
        }
    };

    load_chunk(0, 0); CP_COMMIT();
    load_chunk(1, 1); CP_COMMIT();

    const int r15 = lane & 15;
    const int hsel = lane >> 4;

    for (int c = 0; c < TOT; c++) {
        const int s = c % QKV_NST;
        cp_wait<1>();
        __syncthreads();

        {
            int nc = c + 2;
            if (nc < TOT) load_chunk(nc, nc % QKV_NST);
            CP_COMMIT();
        }

        const uint32_t ab0 = sb + s * QKV_STAGE;
        const uint32_t bb0 = ab0 + 2 * A32_B;

        #pragma unroll
        for (int kh = 0; kh < 2; kh++) {
            const uint32_t ab = ab0 + kh * A32_B;
            const uint32_t bb = bb0 + kh * QKV_B32_B;
            #pragma unroll
            for (int ks2 = 0; ks2 < 2; ks2++) {
                const int kseg = ks2 * 2 + hsel;
                uint32_t aF[4][4], bF[3][4];
                #pragma unroll
                for (int i = 0; i < 4; i++)
                    LDSM4(aF[i], ab + swz_off(wm * 64 + i * 16 + r15, kseg));
                #pragma unroll
                for (int j = 0; j < 3; j++)
                    LDSM4(bF[j], bb + swz_off(wn * 48 + j * 16 + r15, kseg));
                #pragma unroll
                for (int i = 0; i < 4; i++)
                    #pragma unroll
                    for (int j = 0; j < 3; j++) {
                        MMAH(acc[i][2 * j],     aF[i], bF[j][0], bF[j][2]);
                        MMAH(acc[i][2 * j + 1], aF[i], bF[j][1], bF[j][3]);
                    }
            }
        }
    }

    // Fused epilogue: route to Q/K/V, RoPE (+scale), head-major fp16 store
    const int quad = lane >> 2;
    const int tq = lane & 3;
    #pragma unroll
    for (int i = 0; i < 4; i++) {
        int r0 = m0 + wm * 64 + i * 16 + quad;
        int b0 = r0 >> 11;
        int t0 = r0 & (SEQ - 1);
        #pragma unroll
        for (int j = 0; j < 6; j++) {
            int c = n0 + wn * 48 + j * 8 + tq * 2;
            __half* dst;
            int H, cc;
            bool dorope;
            float scl;
            if (c < QCOLS)            { dst = qo; H = NHEAD;   cc = c;          dorope = true;  scl = qs; }
            else if (c < QCOLS + 1024){ dst = ko; H = NKVHEAD; cc = c - QCOLS;  dorope = true;  scl = 1.0f; }
            else                      { dst = vo; H = NKVHEAD; cc = c - QCOLS - 1024; dorope = false; scl = 1.0f; }
            int h = cc >> 7, d = cc & 127, d2 = d >> 1;
            float f0 = acc[i][j][0], f1 = acc[i][j][1];
            float f2 = acc[i][j][2], f3 = acc[i][j][3];
            if (dorope) {
                float c0 = cosb[t0 * 64 + d2], s0 = sinb[t0 * 64 + d2];
                float c1 = cosb[(t0 + 8) * 64 + d2], s1 = sinb[(t0 + 8) * 64 + d2];
                float a0 = (f0 * c0 - f1 * s0) * scl, a1 = (f0 * s0 + f1 * c0) * scl;
                float a2 = (f2 * c1 - f3 * s1) * scl, a3 = (f2 * s1 + f3 * c1) * scl;
                f0 = a0; f1 = a1; f2 = a2; f3 = a3;
            }
            size_t o0 = (((size_t)b0 * H + h) * SEQ + t0) * DHEAD + d;
            *(__half2*)(dst + o0) = __floats2half2_rn(f0, f1);
            *(__half2*)(dst + o0 + (size_t)8 * DHEAD) = __floats2half2_rn(f2, f3);
        }
    }
}

// ---------------------------------------------------------------------------
// WO projection: single-pass fp16 GEMM, BN=128, BK=64, NST=3.
// 1024 CTAs = 6.92 waves.
// ---------------------------------------------------------------------------
#define WO_BN 128
#define WO_B32_B (WO_BN * 32 * 2)           // 8192
#define WO_STAGE (2 * A32_B + 2 * WO_B32_B) // 32768
#define WO_NST 3
#define GEMM_WO_SMEM (WO_NST * WO_STAGE)    // 98304

__global__ __launch_bounds__(256, 1)
void wo_gemm(const __half* __restrict__ A, const __half* __restrict__ B,
             float* __restrict__ C, int N, int K) {
    extern __shared__ char smem[];
    const uint32_t sb = smem_u32(smem);
    const int tid = threadIdx.x;
    const int wid = tid >> 5;
    const int lane = tid & 31;
    const int wm = wid >> 2;       // 0..1
    const int wn = wid & 3;        // 0..3 (32 cols each)
    const int m0 = blockIdx.y * BM;
    const int n0 = blockIdx.x * WO_BN;
    const int TOT = K / 64;

    float acc[4][4][4];
    #pragma unroll
    for (int i = 0; i < 4; i++)
        #pragma unroll
        for (int j = 0; j < 4; j++)
            #pragma unroll
            for (int r = 0; r < 4; r++) acc[i][j][r] = 0.0f;

    auto load_chunk = [&](int c, int s) {
        const __half* as = A + (size_t)m0 * K + c * 64;
        const __half* bs = B + (size_t)n0 * K + c * 64;
        uint32_t base = sb + s * WO_STAGE;
        #pragma unroll
        for (int t = 0; t < 8; t++) {
            int idx = tid + t * 256;      // 1024 A + 1024 B
            if (idx < 1024) {
                int kh = idx >> 9;
                int j = idx & 511;
                int row = j >> 2, ks = j & 3;
                cp16(base + kh * A32_B + swz_off(row, ks),
                     as + kh * 32 + (size_t)row * K + ks * 8);
            } else {
                int j = idx - 1024;
                int kh = j >> 9;
                int jj = j & 511;
                int row = jj >> 2, ks = jj & 3;
                cp16(base + 2 * A32_B + kh * WO_B32_B + swz_off(row, ks),
                     bs + kh * 32 + (size_t)row * K + ks * 8);
            }
        }
    };

    load_chunk(0, 0); CP_COMMIT();
    load_chunk(1, 1); CP_COMMIT();

    const int r15 = lane & 15;
    const int hsel = lane >> 4;

    for (int c = 0; c < TOT; c++) {
        const int s = c % WO_NST;
        cp_wait<1>();
        __syncthreads();

        {
            int nc = c + 2;
            if (nc < TOT) load_chunk(nc, nc % WO_NST);
            CP_COMMIT();
        }

        const uint32_t ab0 = sb + s * WO_STAGE;
        const uint32_t bb0 = ab0 + 2 * A32_B;

        #pragma unroll
        for (int kh = 0; kh < 2; kh++) {
            const uint32_t ab = ab0 + kh * A32_B;
            const uint32_t bb = bb0 + kh * WO_B32_B;
            #pragma unroll
            for (int ks2 = 0; ks2 < 2; ks2++) {
                const int kseg = ks2 * 2 + hsel;
                uint32_t aF[4][4], bF[2][4];
                #pragma unroll
                for (int i = 0; i < 4; i++)
                    LDSM4(aF[i], ab + swz_off(wm * 64 + i * 16 + r15, kseg));
                #pragma unroll
                for (int j = 0; j < 2; j++)
                    LDSM4(bF[j], bb + swz_off(wn * 32 + j * 16 + r15, kseg));
                #pragma unroll
                for (int i = 0; i < 4; i++)
                    #pragma unroll
                    for (int j = 0; j < 2; j++) {
                        MMAH(acc[i][2 * j],     aF[i], bF[j][0], bF[j][2]);
                        MMAH(acc[i][2 * j + 1], aF[i], bF[j][1], bF[j][3]);
                    }
            }
        }
    }

    const int quad = lane >> 2;
    const int tq = lane & 3;
    #pragma unroll
    for (int i = 0; i < 4; i++) {
        int row0 = m0 + wm * 64 + i * 16 + quad;
        #pragma unroll
        for (int j = 0; j < 4; j++) {
            int col = n0 + wn * 32 + j * 8 + tq * 2;
            *(float2*)(C + (size_t)row0 * N + col) =
                make_float2(acc[i][j][0], acc[i][j][1]);
            *(float2*)(C + (size_t)(row0 + 8) * N + col) =
                make_float2(acc[i][j][2], acc[i][j][3]);
        }
    }
}

// ----------------------------------------------------------------------------
// HMMA fp16 flash attention. KV tiles 128 wide; heavy q-tiles first.
// ----------------------------------------------------------------------------
#define QS_BYTES (128 * 128 * 2)      // 32768
#define KV_BYTES (128 * 128 * 2)      // 32768 per K (or V) tile
#define FLASH_SMEM (QS_BYTES + 2 * (2 * KV_BYTES))   // 163840

__global__ __launch_bounds__(256, 1)
void flash_hmma(const __half* __restrict__ Qg, const __half* __restrict__ Kg,
                const __half* __restrict__ Vg, __half* __restrict__ Z) {
    extern __shared__ char smem[];
    const uint32_t sb = smem_u32(smem);
    const int tid = threadIdx.x;
    const int wid = tid >> 5;
    const int lane = tid & 31;
    const int quad = lane >> 2, tq = lane & 3;
    const int r15 = lane & 15, hsel = lane >> 4;
    const int qt = (gridDim.x - 1) - blockIdx.x;   // heavy tiles first
    const int q0 = qt * 128;
    const int bh = blockIdx.y;
    const int b = bh >> 5, h = bh & 31, kvh = h >> 2;
    const __half* qsrc = Qg + ((size_t)bh * SEQ + q0) * DHEAD;
    const __half* ksrc0 = Kg + ((size_t)(b * NKVHEAD + kvh)) * SEQ * DHEAD;
    const __half* vsrc0 = Vg + ((size_t)(b * NKVHEAD + kvh)) * SEQ * DHEAD;
    const int nkt = qt + 1;           // 128-wide KV tiles

    #pragma unroll
    for (int t = 0; t < 8; t++) {
        int j = tid + t * 256;
        int row = j >> 4, dc = (j >> 2) & 3, ks = j & 3;
        cp16(sb + dc * 8192 + swz_off(row, ks), qsrc + (size_t)row * DHEAD + dc * 32 + ks * 8);
    }
    CP_COMMIT();

    auto load_kv = [&](int t, int s) {
        uint32_t kb = sb + QS_BYTES + s * (2 * KV_BYTES);
        uint32_t vb = kb + KV_BYTES;
        const __half* ks_ = ksrc0 + (size_t)t * 128 * DHEAD;
        const __half* vs_ = vsrc0 + (size_t)t * 128 * DHEAD;
        #pragma unroll
        for (int u = 0; u < 16; u++) {
            int j = tid + u * 256;
            bool isv = j >= 2048;
            int jj = j & 2047;
            int row = jj >> 4, dc = (jj >> 2) & 3, ks = jj & 3;
            cp16((isv ? vb : kb) + dc * 8192 + swz_off(row, ks),
                 (isv ? vs_ : ks_) + (size_t)row * DHEAD + dc * 32 + ks * 8);
        }
    };

    load_kv(0, 0); CP_COMMIT();
    cp_wait<1>();
    __syncthreads();

    uint32_t qF[8][4];
    #pragma unroll
    for (int kc = 0; kc < 8; kc++) {
        int dc = kc >> 1;
        LDSM4(qF[kc], sb + dc * 8192 + swz_off(wid * 16 + r15, (kc & 1) * 2 + hsel));
    }

    if (nkt > 1) load_kv(1, 1);
    CP_COMMIT();

    float o[16][4];
    #pragma unroll
    for (int i = 0; i < 16; i++)
        #pragma unroll
        for (int r = 0; r < 4; r++) o[i][r] = 0.0f;
    float m0v = -1e30f, m1v = -1e30f, l0v = 0.0f, l1v = 0.0f;

    const int row_g0 = q0 + wid * 16 + quad;

    for (int t = 0; t < nkt; t++) {
        cp_wait<1>();
        __syncthreads();
        const uint32_t kb = sb + QS_BYTES + (t & 1) * (2 * KV_BYTES);
        const uint32_t vb = kb + KV_BYTES;

        float s[16][4];
        #pragma unroll
        for (int j = 0; j < 16; j++)
            #pragma unroll
            for (int r = 0; r < 4; r++) s[j][r] = 0.0f;

        #pragma unroll
        for (int kc = 0; kc < 8; kc++) {
            int dc = kc >> 1;
            #pragma unroll
            for (int j = 0; j < 8; j++) {
                uint32_t kf[4];
                LDSM4(kf, kb + dc * 8192 + swz_off(j * 16 + r15, (kc & 1) * 2 + hsel));
                MMAH(s[2 * j],     qF[kc], kf[0], kf[2]);
                MMAH(s[2 * j + 1], qF[kc], kf[1], kf[3]);
            }
        }

        if (t == nkt - 1) {
            #pragma unroll
            for (int j = 0; j < 16; j++) {
                int col = t * 128 + j * 8 + tq * 2;
                if (col     > row_g0)     s[j][0] = -1e30f;
                if (col + 1 > row_g0)     s[j][1] = -1e30f;
                if (col     > row_g0 + 8) s[j][2] = -1e30f;
                if (col + 1 > row_g0 + 8) s[j][3] = -1e30f;
            }
        }

        float rm0 = -1e30f, rm1 = -1e30f;
        #pragma unroll
        for (int j = 0; j < 16; j++) {
            rm0 = fmaxf(rm0, fmaxf(s[j][0], s[j][1]));
            rm1 = fmaxf(rm1, fmaxf(s[j][2], s[j][3]));
        }
        rm0 = fmaxf(rm0, __shfl_xor_sync(0xffffffffu, rm0, 1));
        rm0 = fmaxf(rm0, __shfl_xor_sync(0xffffffffu, rm0, 2));
        rm1 = fmaxf(rm1, __shfl_xor_sync(0xffffffffu, rm1, 1));
        rm1 = fmaxf(rm1, __shfl_xor_sync(0xffffffffu, rm1, 2));

        float mn0 = fmaxf(m0v, rm0), mn1 = fmaxf(m1v, rm1);
        float f0 = exp2f(m0v - mn0), f1 = exp2f(m1v - mn1);

        float rs0 = 0.0f, rs1 = 0.0f;
        uint32_t aP[8][4];
        #pragma unroll
        for (int kk = 0; kk < 8; kk++) {
            float p00 = exp2f(s[2 * kk][0] - mn0);
            float p01 = exp2f(s[2 * kk][1] - mn0);
            float p02 = exp2f(s[2 * kk][2] - mn1);
            float p03 = exp2f(s[2 * kk][3] - mn1);
            float p10 = exp2f(s[2 * kk + 1][0] - mn0);
            float p11 = exp2f(s[2 * kk + 1][1] - mn0);
            float p12 = exp2f(s[2 * kk + 1][2] - mn1);
            float p13 = exp2f(s[2 * kk + 1][3] - mn1);
            rs0 += p00 + p01 + p10 + p11;
            rs1 += p02 + p03 + p12 + p13;
            aP[kk][0] = packh2(p00, p01);
            aP[kk][1] = packh2(p02, p03);
            aP[kk][2] = packh2(p10, p11);
            aP[kk][3] = packh2(p12, p13);
        }
        rs0 += __shfl_xor_sync(0xffffffffu, rs0, 1);
        rs0 += __shfl_xor_sync(0xffffffffu, rs0, 2);
        rs1 += __shfl_xor_sync(0xffffffffu, rs1, 1);
        rs1 += __shfl_xor_sync(0xffffffffu, rs1, 2);

        l0v = l0v * f0 + rs0;
        l1v = l1v * f1 + rs1;
        m0v = mn0; m1v = mn1;

        #pragma unroll
        for (int i = 0; i < 16; i++) {
            o[i][0] *= f0; o[i][1] *= f0;
            o[i][2] *= f1; o[i][3] *= f1;
        }

        #pragma unroll
        for (int djp = 0; djp < 8; djp++) {
            int dj = djp * 2 + hsel;
            int dc = dj >> 2, ks = dj & 3;
            #pragma unroll
            for (int kk = 0; kk < 8; kk++) {
                uint32_t vr[4];
                LDSM4T(vr, vb + dc * 8192 + swz_off(kk * 16 + r15, ks));
                MMAH(o[djp * 2],     aP[kk], vr[0], vr[1]);
                MMAH(o[djp * 2 + 1], aP[kk], vr[2], vr[3]);
            }
        }

        __syncthreads();
        if (t + 2 < nkt) load_kv(t + 2, t & 1);
        CP_COMMIT();
    }

    float inv0 = 1.0f / l0v, inv1 = 1.0f / l1v;
    size_t base0 = (size_t)(b * SEQ + row_g0) * DMODEL + h * DHEAD;
    size_t base1 = base0 + (size_t)8 * DMODEL;
    #pragma unroll
    for (int djt = 0; djt < 16; djt++) {
        int col = djt * 8 + tq * 2;
        *(__half2*)(Z + base0 + col) = __floats2half2_rn(o[djt][0] * inv0, o[djt][1] * inv0);
        *(__half2*)(Z + base1 + col) = __floats2half2_rn(o[djt][2] * inv1, o[djt][3] * inv1);
    }
}

// ----------------------------------------------------------------------------
// Host launcher
// ----------------------------------------------------------------------------
extern "C" void kernel_launch(void* const* d_in, const int* in_sizes, int n_in,
                              void* d_out, int out_size) {
    const float* x    = (const float*)d_in[0];
    const float* fcos = (const float*)d_in[1];
    const float* fsin = (const float*)d_in[2];
    const float* wq   = (const float*)d_in[3];
    const float* wk   = (const float*)d_in[4];
    const float* wv   = (const float*)d_in[5];
    const float* wo   = (const float*)d_in[6];
    float* out = (float*)d_out;

    __half *x16, *wqkv, *wot, *z16, *q16, *k16, *v16;
    cudaGetSymbolAddress((void**)&x16, X16);
    cudaGetSymbolAddress((void**)&wqkv, WQKVT16);
    cudaGetSymbolAddress((void**)&wot, WOT16);
    cudaGetSymbolAddress((void**)&z16, Z16);
    cudaGetSymbolAddress((void**)&q16, Q16);
    cudaGetSymbolAddress((void**)&k16, K16);
    cudaGetSymbolAddress((void**)&v16, V16);

    cudaFuncSetAttribute(gemm_qkv, cudaFuncAttributeMaxDynamicSharedMemorySize, GEMM_QKV_SMEM);
    cudaFuncSetAttribute(wo_gemm, cudaFuncAttributeMaxDynamicSharedMemorySize, GEMM_WO_SMEM);
    cudaFuncSetAttribute(flash_hmma, cudaFuncAttributeMaxDynamicSharedMemorySize, FLASH_SMEM);

    // Input conversions (2 launches)
    {
        int n = MROWS * DMODEL;
        xconvert<<<(n + 255) / 256, 256>>>(x, x16, n);
    }
    prep_weights<<<TQ + TK + TV + TO, 256>>>(wq, wk, wv, wo, wqkv, wot);

    // Merged QKV projection (single-pass fp16, fused RoPE epilogue)
    const float qs = 0.08838834764831845f * 1.4426950408889634f;   // scale * log2(e)
    gemm_qkv<<<dim3(QKVCOLS / QKV_BN, MROWS / BM), 256, GEMM_QKV_SMEM>>>(
        x16, wqkv, fcos, fsin, q16, k16, v16, qs);

    // Flash attention (fp16 HMMA) -> Z16 fp16
    flash_hmma<<<dim3(SEQ / 128, BATCH * NHEAD), 256, FLASH_SMEM>>>(q16, k16, v16, z16);

    // Output projection: single-pass fp16
    wo_gemm<<<dim3(DMODEL / WO_BN, MROWS / BM), 256, GEMM_WO_SMEM>>>(z16, wot, out, DMODEL, DMODEL);
}